// round 12
// baseline (speedup 1.0000x reference)
#include <cuda_runtime.h>
#include <cuda_bf16.h>
#include <math.h>
#include <cstdint>

#define B_  2
#define S_  2048
#define D_  1024
#define H_  16
#define DH_ 64
#define QKDIM 2048
#define NEGV (-1000000000.0f)
#define LOG2E 1.44269504f
#define NEGV2 (-1.44269504e9f)
#define LAMBDA_INIT 0.8f
#define EPS_ 1e-5f

// ---------------- scratch (device globals) ---------------------------------
__device__ float g_o1[(size_t)B_ * S_ * H_ * DH_];
__device__ float g_o2[(size_t)B_ * S_ * H_ * DH_];
__device__ float g_o [(size_t)B_ * S_ * H_ * DH_];
__device__ float g_lambda;
__device__ double g_sum[B_ * H_], g_sumsq[B_ * H_];

// bf16 split buffers
__device__ __nv_bfloat16 g_xh[(size_t)B_ * S_ * D_], g_xl[(size_t)B_ * S_ * D_];
__device__ __nv_bfloat16 g_wqh[QKDIM * D_], g_wql[QKDIM * D_];
__device__ __nv_bfloat16 g_wkh[QKDIM * D_], g_wkl[QKDIM * D_];
__device__ __nv_bfloat16 g_wvh[(H_ * DH_) * D_], g_wvl[(H_ * DH_) * D_];
__device__ __nv_bfloat16 g_woh[D_ * (H_ * DH_)], g_wol[D_ * (H_ * DH_)];
__device__ __nv_bfloat16 g_nh[(size_t)B_ * S_ * H_ * DH_], g_nl[(size_t)B_ * S_ * H_ * DH_];
__device__ __nv_bfloat16 g_qh[(size_t)B_ * S_ * QKDIM], g_ql[(size_t)B_ * S_ * QKDIM];
__device__ __nv_bfloat16 g_kh[(size_t)B_ * S_ * QKDIM], g_kl[(size_t)B_ * S_ * QKDIM];
__device__ __nv_bfloat16 g_vh[(size_t)B_ * S_ * H_ * DH_], g_vl[(size_t)B_ * S_ * H_ * DH_];

// ---------------- helpers ---------------------------------------------------
__device__ __forceinline__ uint32_t smem_u32(const void* p) {
    uint32_t a;
    asm("{ .reg .u64 t; cvta.to.shared.u64 t, %1; cvt.u32.u64 %0, t; }" : "=r"(a) : "l"(p));
    return a;
}
__device__ __forceinline__ float fast_exp2(float x) {
    float r;
    asm("ex2.approx.ftz.f32 %0, %1;" : "=f"(r) : "f"(x));
    return r;
}
#define CP16(dst, src) \
    asm volatile("cp.async.cg.shared.global [%0], [%1], 16;" :: "r"(dst), "l"(src) : "memory")
#define CP_COMMIT() asm volatile("cp.async.commit_group;" ::: "memory")
#define CP_WAIT1()  asm volatile("cp.async.wait_group 1;" ::: "memory")
#define CP_WAIT0()  asm volatile("cp.async.wait_group 0;" ::: "memory")

__device__ __forceinline__ void ldsm_x4(uint32_t& r0, uint32_t& r1, uint32_t& r2, uint32_t& r3,
                                        uint32_t addr) {
    asm volatile("ldmatrix.sync.aligned.m8n8.x4.shared.b16 {%0,%1,%2,%3}, [%4];"
                 : "=r"(r0), "=r"(r1), "=r"(r2), "=r"(r3) : "r"(addr));
}
__device__ __forceinline__ void ldsm_x4t(uint32_t& r0, uint32_t& r1, uint32_t& r2, uint32_t& r3,
                                         uint32_t addr) {
    asm volatile("ldmatrix.sync.aligned.m8n8.x4.trans.shared.b16 {%0,%1,%2,%3}, [%4];"
                 : "=r"(r0), "=r"(r1), "=r"(r2), "=r"(r3) : "r"(addr));
}
#define MMA16816(d, a, b) \
    asm volatile("mma.sync.aligned.m16n8k16.row.col.f32.bf16.bf16.f32 " \
                 "{%0,%1,%2,%3}, {%4,%5,%6,%7}, {%8,%9}, {%0,%1,%2,%3};" \
                 : "+f"((d)[0]), "+f"((d)[1]), "+f"((d)[2]), "+f"((d)[3]) \
                 : "r"((a)[0]), "r"((a)[1]), "r"((a)[2]), "r"((a)[3]), \
                   "r"((b)[0]), "r"((b)[1]))

__device__ __forceinline__ uint32_t pack_bf2(float lo, float hi) {
    __nv_bfloat162 t = __floats2bfloat162_rn(lo, hi);
    return *(uint32_t*)&t;
}

// ---------------- lambda + zero stats ---------------------------------------
__global__ void lam_kernel(const float* __restrict__ lq1, const float* __restrict__ lq2,
                           const float* __restrict__ lk1, const float* __restrict__ lk2) {
    float d1 = 0.f, d2 = 0.f;
    for (int i = 0; i < DH_; i++) { d1 += lq1[i] * lk1[i]; d2 += lq2[i] * lk2[i]; }
    g_lambda = expf(d1) - expf(d2) + LAMBDA_INIT;
    for (int i = 0; i < B_ * H_; i++) { g_sum[i] = 0.0; g_sumsq[i] = 0.0; }
}

// ---------------- fp32 -> bf16 hi/lo splits ---------------------------------
#define N4_X  (B_ * S_ * D_ / 4)
#define N4_WQ (QKDIM * D_ / 4)
#define N4_WV (H_ * DH_ * D_ / 4)
#define N4_W_TOT (2 * N4_WQ + 2 * N4_WV)

__device__ __forceinline__ void split4(const float* src, __nv_bfloat16* h, __nv_bfloat16* l,
                                       size_t i) {
    float4 v = ((const float4*)src)[i];
    float vv[4] = {v.x, v.y, v.z, v.w};
    __nv_bfloat16 hh[4], ll[4];
#pragma unroll
    for (int j = 0; j < 4; j++) {
        hh[j] = __float2bfloat16(vv[j]);
        ll[j] = __float2bfloat16(vv[j] - __bfloat162float(hh[j]));
    }
    *(uint2*)&h[i * 4] = *(uint2*)hh;
    *(uint2*)&l[i * 4] = *(uint2*)ll;
}

__global__ void __launch_bounds__(256) cvt_x(const float* __restrict__ x) {
    int i = blockIdx.x * 256 + threadIdx.x;
    if (i < N4_X) split4(x, g_xh, g_xl, i);
}

__global__ void __launch_bounds__(256) cvt_w(
    const float* __restrict__ Wq, const float* __restrict__ Wk,
    const float* __restrict__ Wv, const float* __restrict__ Wo) {
    int i = blockIdx.x * 256 + threadIdx.x;
    if (i < N4_WQ) { split4(Wq, g_wqh, g_wql, i); return; }
    i -= N4_WQ;
    if (i < N4_WQ) { split4(Wk, g_wkh, g_wkl, i); return; }
    i -= N4_WQ;
    if (i < N4_WV) { split4(Wv, g_wvh, g_wvl, i); return; }
    i -= N4_WV;
    if (i < N4_WV) { split4(Wo, g_woh, g_wol, i); return; }
}

// ---------------- GEMM stage loader -----------------------------------------
#define GSTAGE 32768
#define G_SMEM (3 * GSTAGE)

__device__ __forceinline__ void g_issue(
    const __nv_bfloat16* __restrict__ Ah, const __nv_bfloat16* __restrict__ Al,
    const __nv_bfloat16* __restrict__ Bh, const __nv_bfloat16* __restrict__ Bl,
    uint32_t sbuf, int tid, int bm, int bn, int K, int c) {
#pragma unroll
    for (int i = 0; i < 2; i++) {
        int ch = tid + i * 256;
        int p = ch >> 3, c16 = ch & 7;
        int r = (p << 1) + (c16 >> 2);
        int kb = (c16 & 3) * 8;
        int off = p * 128 + c16 * 16;
        uint32_t dst = sbuf + (off ^ ((off >> 3) & 0x70));
        size_t ga = (size_t)(bm + r) * K + c * 32 + kb;
        size_t gb = (size_t)(bn + r) * K + c * 32 + kb;
        CP16(dst,         Ah + ga);
        CP16(dst + 8192,  Al + ga);
        CP16(dst + 16384, Bh + gb);
        CP16(dst + 24576, Bl + gb);
    }
    CP_COMMIT();
}

__device__ __forceinline__ void g_chunk(uint32_t sbuf, int wm, int wn, int g, int rl,
                                        float acc[2][8][4]) {
#pragma unroll
    for (int ks = 0; ks < 2; ks++) {
        uint32_t ah[2][4], al[2][4];
#pragma unroll
        for (int mb = 0; mb < 2; mb++) {
            int r = wm + mb * 16 + ((g & 1) << 3) + rl;
            int c16 = ((r & 1) << 2) + ks * 2 + (g >> 1);
            int off = (r >> 1) * 128 + c16 * 16;
            uint32_t sw = (uint32_t)(off ^ ((off >> 3) & 0x70));
            ldsm_x4(ah[mb][0], ah[mb][1], ah[mb][2], ah[mb][3], sbuf + sw);
            ldsm_x4(al[mb][0], al[mb][1], al[mb][2], al[mb][3], sbuf + 8192 + sw);
        }
        uint32_t bh[4][4], bl[4][4];
#pragma unroll
        for (int np = 0; np < 4; np++) {
            int r = wn + np * 16 + ((g >> 1) << 3) + rl;
            int c16 = ((r & 1) << 2) + ks * 2 + (g & 1);
            int off = (r >> 1) * 128 + c16 * 16;
            uint32_t sw = (uint32_t)(off ^ ((off >> 3) & 0x70));
            ldsm_x4(bh[np][0], bh[np][1], bh[np][2], bh[np][3], sbuf + 16384 + sw);
            ldsm_x4(bl[np][0], bl[np][1], bl[np][2], bl[np][3], sbuf + 24576 + sw);
        }
#pragma unroll
        for (int mb = 0; mb < 2; mb++)
#pragma unroll
            for (int j = 0; j < 8; j++) {
                MMA16816(acc[mb][j], ah[mb], &bh[j >> 1][(j & 1) * 2]);
                MMA16816(acc[mb][j], ah[mb], &bl[j >> 1][(j & 1) * 2]);
                MMA16816(acc[mb][j], al[mb], &bh[j >> 1][(j & 1) * 2]);
            }
    }
}

// ---------------- fused QKV projection (persistent grid) --------------------
#define QKV_TILES (40 * 32)

__global__ void __launch_bounds__(256, 2) gemm_qkv() {
    extern __shared__ char smem[];
    const uint32_t sbase = smem_u32(smem);
    const int tid = threadIdx.x, wid = tid >> 5, lane = tid & 31;
    const int wm = (wid & 3) * 32;
    const int wn = (wid >> 2) * 64;
    const int g = lane >> 3, rl = lane & 7;
    const int K = D_;

    for (int t = blockIdx.x; t < QKV_TILES; t += gridDim.x) {
        const int nt = t % 40;
        const int bm = (t / 40) * 128;

        const __nv_bfloat16 *Ah = g_xh, *Al = g_xl, *Bh, *Bl;
        __nv_bfloat16 *Oh, *Ol;
        int N, bn;
        if (nt < 16)      { Bh = g_wqh; Bl = g_wql; Oh = g_qh; Ol = g_ql; N = QKDIM; bn = nt * 128; }
        else if (nt < 32) { Bh = g_wkh; Bl = g_wkl; Oh = g_kh; Ol = g_kl; N = QKDIM; bn = (nt - 16) * 128; }
        else              { Bh = g_wvh; Bl = g_wvl; Oh = g_vh; Ol = g_vl; N = H_ * DH_; bn = (nt - 32) * 128; }

        float acc[2][8][4];
#pragma unroll
        for (int a = 0; a < 2; a++)
#pragma unroll
            for (int b = 0; b < 8; b++)
#pragma unroll
                for (int d = 0; d < 4; d++) acc[a][b][d] = 0.f;

        const int nch = K >> 5;
        g_issue(Ah, Al, Bh, Bl, sbase, tid, bm, bn, K, 0);
        g_issue(Ah, Al, Bh, Bl, sbase + GSTAGE, tid, bm, bn, K, 1);

        for (int c = 0; c < nch; c++) {
            if (c + 1 < nch) { CP_WAIT1(); } else { CP_WAIT0(); }
            __syncthreads();
            if (c + 2 < nch)
                g_issue(Ah, Al, Bh, Bl, sbase + (uint32_t)((c + 2) % 3) * GSTAGE, tid, bm, bn, K, c + 2);
            g_chunk(sbase + (uint32_t)(c % 3) * GSTAGE, wm, wn, g, rl, acc);
        }

#pragma unroll
        for (int mb = 0; mb < 2; mb++) {
            int row0 = bm + wm + mb * 16 + (lane >> 2);
#pragma unroll
            for (int j = 0; j < 8; j++) {
                int col = bn + wn + j * 8 + (lane & 3) * 2;
#pragma unroll
                for (int rr = 0; rr < 2; rr++) {
                    float v0 = acc[mb][j][rr * 2], v1 = acc[mb][j][rr * 2 + 1];
                    __nv_bfloat16 h0 = __float2bfloat16(v0), h1 = __float2bfloat16(v1);
                    __nv_bfloat16 l0 = __float2bfloat16(v0 - __bfloat162float(h0));
                    __nv_bfloat16 l1 = __float2bfloat16(v1 - __bfloat162float(h1));
                    size_t idx = (size_t)(row0 + rr * 8) * N + col;
                    __nv_bfloat162 hp; hp.x = h0; hp.y = h1;
                    __nv_bfloat162 lp; lp.x = l0; lp.y = l1;
                    *(__nv_bfloat162*)&Oh[idx] = hp;
                    *(__nv_bfloat162*)&Ol[idx] = lp;
                }
            }
        }
        __syncthreads();   // all warps done with smem before next tile primes
    }
}

// ---------------- output projection (fp32 out) ------------------------------
__global__ void __launch_bounds__(256, 2) gemm_o(
    const __nv_bfloat16* __restrict__ Ah, const __nv_bfloat16* __restrict__ Al,
    const __nv_bfloat16* __restrict__ Bh, const __nv_bfloat16* __restrict__ Bl,
    float* __restrict__ Cf, int M, int N, int K) {
    extern __shared__ char smem[];
    const uint32_t sbase = smem_u32(smem);
    const int tid = threadIdx.x, wid = tid >> 5, lane = tid & 31;
    const int bm = blockIdx.y * 128, bn = blockIdx.x * 128;
    const int wm = (wid & 3) * 32;
    const int wn = (wid >> 2) * 64;
    const int g = lane >> 3, rl = lane & 7;

    float acc[2][8][4];
#pragma unroll
    for (int a = 0; a < 2; a++)
#pragma unroll
        for (int b = 0; b < 8; b++)
#pragma unroll
            for (int d = 0; d < 4; d++) acc[a][b][d] = 0.f;

    const int nch = K >> 5;
    g_issue(Ah, Al, Bh, Bl, sbase, tid, bm, bn, K, 0);
    g_issue(Ah, Al, Bh, Bl, sbase + GSTAGE, tid, bm, bn, K, 1);

    for (int c = 0; c < nch; c++) {
        if (c + 1 < nch) { CP_WAIT1(); } else { CP_WAIT0(); }
        __syncthreads();
        if (c + 2 < nch)
            g_issue(Ah, Al, Bh, Bl, sbase + (uint32_t)((c + 2) % 3) * GSTAGE, tid, bm, bn, K, c + 2);
        g_chunk(sbase + (uint32_t)(c % 3) * GSTAGE, wm, wn, g, rl, acc);
    }

#pragma unroll
    for (int mb = 0; mb < 2; mb++) {
        int row0 = bm + wm + mb * 16 + (lane >> 2);
#pragma unroll
        for (int j = 0; j < 8; j++) {
            int col = bn + wn + j * 8 + (lane & 3) * 2;
            *(float2*)&Cf[(size_t)row0 * N + col]       = make_float2(acc[mb][j][0], acc[mb][j][1]);
            *(float2*)&Cf[(size_t)(row0 + 8) * N + col] = make_float2(acc[mb][j][2], acc[mb][j][3]);
        }
    }
}

// ---------------- flash attention: 4 warps, 64-q tiles, 2 CTAs/SM -----------
#define FSTG_SZ 33024
#define FK_H 0
#define FK_L 8192
#define FV_H 16384
#define FV_L 24576
#define FAM  32768
#define FQ_H (2 * FSTG_SZ)
#define FQ_L (2 * FSTG_SZ + 8192)
#define FL_SMEM (3 * FSTG_SZ)   // 99072

__device__ __forceinline__ void f_issue_stage(uint32_t stg, int tid, int b, int h, int comp,
                                              int kt, const float* __restrict__ amask) {
    const char* Khg = (const char*)(g_kh + ((size_t)(b * S_) + kt * 64) * QKDIM + h * 128 + comp * 64);
    const char* Klg = (const char*)(g_kl + ((size_t)(b * S_) + kt * 64) * QKDIM + h * 128 + comp * 64);
    const char* Vhg = (const char*)(g_vh + ((size_t)(b * S_) + kt * 64) * (H_ * DH_) + h * 64);
    const char* Vlg = (const char*)(g_vl + ((size_t)(b * S_) + kt * 64) * (H_ * DH_) + h * 64);
#pragma unroll
    for (int i = 0; i < 4; i++) {
        int t = tid + i * 128;
        int row = t >> 3, gr = t & 7;
        int off = row * 128 + gr * 16;
        uint32_t sw = (uint32_t)(off ^ ((off >> 3) & 0x70));
        CP16(stg + FK_H + sw, Khg + (size_t)row * (QKDIM * 2) + gr * 16);
        CP16(stg + FK_L + sw, Klg + (size_t)row * (QKDIM * 2) + gr * 16);
        CP16(stg + FV_H + sw, Vhg + (size_t)row * (H_ * DH_ * 2) + gr * 16);
        CP16(stg + FV_L + sw, Vlg + (size_t)row * (H_ * DH_ * 2) + gr * 16);
    }
    if (tid < 16)
        CP16(stg + FAM + tid * 16, amask + b * S_ + kt * 64 + tid * 4);
    CP_COMMIT();
}

__global__ void __launch_bounds__(128) flashmma_kernel(const float* __restrict__ amask) {
    extern __shared__ char fsm[];
    const uint32_t sb = smem_u32(fsm);
    const int tid = threadIdx.x, wid = tid >> 5, lane = tid & 31;
    const int g = lane >> 3, rl = lane & 7;
    const int qt = (gridDim.x - 1) - blockIdx.x;
    const int z = blockIdx.y;
    const int comp = z & 1;
    const int bh = z >> 1;
    const int b = bh / H_, h = bh % H_;
    const float slope2 = exp2f(-8.0f * (float)(h + 1) / (float)H_) * LOG2E;
    const float scale2 = 0.125f * LOG2E;
    const int nkt = qt + 1;

    {
        const char* Qhg = (const char*)(g_qh + ((size_t)(b * S_) + qt * 64) * QKDIM + h * 128 + comp * 64);
        const char* Qlg = (const char*)(g_ql + ((size_t)(b * S_) + qt * 64) * QKDIM + h * 128 + comp * 64);
#pragma unroll
        for (int i = 0; i < 4; i++) {
            int t = tid + i * 128;
            int row = t >> 3, gr = t & 7;
            int off = row * 128 + gr * 16;
            uint32_t sw = (uint32_t)(off ^ ((off >> 3) & 0x70));
            CP16(sb + FQ_H + sw, Qhg + (size_t)row * (QKDIM * 2) + gr * 16);
            CP16(sb + FQ_L + sw, Qlg + (size_t)row * (QKDIM * 2) + gr * 16);
        }
    }
    f_issue_stage(sb, tid, b, h, comp, qt, amask);
    if (nkt > 1) f_issue_stage(sb + FSTG_SZ, tid, b, h, comp, qt - 1, amask);

    float oa[8][4];
#pragma unroll
    for (int j = 0; j < 8; j++)
#pragma unroll
        for (int d = 0; d < 4; d++) oa[j][d] = 0.f;
    float m0 = -1e30f, m1 = -1e30f, l0 = 0.f, l1 = 0.f;
    uint32_t qAh[4][4], qAl[4][4];

    const int qr0 = qt * 64 + wid * 16 + (lane >> 2);
    const float d8 = -8.0f * slope2;

    float cst0[8], cst1[8];
#pragma unroll
    for (int nb = 0; nb < 8; nb++) {
        cst0[nb] = slope2 * (float)(nb * 8 + (lane & 3) * 2);
        cst1[nb] = cst0[nb] + slope2;
    }
    float base0 = -slope2 * (float)(wid * 16 + (lane >> 2));
    const float base_step = 64.0f * slope2;

    for (int it = 0; it < nkt; it++) {
        const int ktile = qt - it;
        if (it + 1 < nkt) { CP_WAIT1(); } else { CP_WAIT0(); }
        __syncthreads();
        if (it == 0) {
#pragma unroll
            for (int kb = 0; kb < 4; kb++) {
                int row = wid * 16 + ((g & 1) << 3) + rl;
                int gr = kb * 2 + (g >> 1);
                int off = row * 128 + gr * 16;
                uint32_t sw = (uint32_t)(off ^ ((off >> 3) & 0x70));
                ldsm_x4(qAh[kb][0], qAh[kb][1], qAh[kb][2], qAh[kb][3], sb + FQ_H + sw);
                ldsm_x4(qAl[kb][0], qAl[kb][1], qAl[kb][2], qAl[kb][3], sb + FQ_L + sw);
            }
            if (nkt > 2) __syncthreads();
        }
        if (it + 2 < nkt)
            f_issue_stage(sb + (uint32_t)((it + 2) % 3) * FSTG_SZ, tid, b, h, comp, qt - (it + 2), amask);
        uint32_t stg = sb + (uint32_t)(it % 3) * FSTG_SZ;

        float sa[8][4];
#pragma unroll
        for (int j = 0; j < 8; j++)
#pragma unroll
            for (int d = 0; d < 4; d++) sa[j][d] = 0.f;
#pragma unroll
        for (int kb = 0; kb < 4; kb++) {
#pragma unroll
            for (int nb2 = 0; nb2 < 4; nb2++) {
                uint32_t kh4[4], kl4[4];
                int row = nb2 * 16 + ((g >> 1) << 3) + rl;
                int gr = kb * 2 + (g & 1);
                int off = row * 128 + gr * 16;
                uint32_t sw = (uint32_t)(off ^ ((off >> 3) & 0x70));
                ldsm_x4(kh4[0], kh4[1], kh4[2], kh4[3], stg + FK_H + sw);
                ldsm_x4(kl4[0], kl4[1], kl4[2], kl4[3], stg + FK_L + sw);
                MMA16816(sa[nb2 * 2], qAh[kb], &kh4[0]);
                MMA16816(sa[nb2 * 2], qAh[kb], &kl4[0]);
                MMA16816(sa[nb2 * 2], qAl[kb], &kh4[0]);
                MMA16816(sa[nb2 * 2 + 1], qAh[kb], &kh4[2]);
                MMA16816(sa[nb2 * 2 + 1], qAh[kb], &kl4[2]);
                MMA16816(sa[nb2 * 2 + 1], qAl[kb], &kh4[2]);
            }
        }

        const float* ams = (const float*)(fsm + (stg - sb) + FAM);
        float colc[8][2];
#pragma unroll
        for (int nb = 0; nb < 8; nb++) {
            int kc = nb * 8 + (lane & 3) * 2;
            colc[nb][0] = fmaf(1.0f - ams[kc],     NEGV2, base0 + cst0[nb]);
            colc[nb][1] = fmaf(1.0f - ams[kc + 1], NEGV2, base0 + cst1[nb]);
        }
#pragma unroll
        for (int nb = 0; nb < 8; nb++) {
            sa[nb][0] = fmaf(sa[nb][0], scale2, colc[nb][0]);
            sa[nb][1] = fmaf(sa[nb][1], scale2, colc[nb][1]);
            sa[nb][2] = fmaf(sa[nb][2], scale2, colc[nb][0] + d8);
            sa[nb][3] = fmaf(sa[nb][3], scale2, colc[nb][1] + d8);
        }
        if (it == 0) {
            const int kcb = ktile * 64;
#pragma unroll
            for (int nb = 0; nb < 8; nb++) {
                int k0 = kcb + nb * 8 + (lane & 3) * 2;
                if (k0 > qr0)         sa[nb][0] += NEGV2;
                if (k0 + 1 > qr0)     sa[nb][1] += NEGV2;
                if (k0 > qr0 + 8)     sa[nb][2] += NEGV2;
                if (k0 + 1 > qr0 + 8) sa[nb][3] += NEGV2;
            }
        }
        base0 -= base_step;

        float mx0 = -1e30f, mx1 = -1e30f;
#pragma unroll
        for (int nb = 0; nb < 8; nb++) {
            mx0 = fmaxf(mx0, fmaxf(sa[nb][0], sa[nb][1]));
            mx1 = fmaxf(mx1, fmaxf(sa[nb][2], sa[nb][3]));
        }
        mx0 = fmaxf(mx0, __shfl_xor_sync(0xffffffffu, mx0, 1));
        mx0 = fmaxf(mx0, __shfl_xor_sync(0xffffffffu, mx0, 2));
        mx1 = fmaxf(mx1, __shfl_xor_sync(0xffffffffu, mx1, 1));
        mx1 = fmaxf(mx1, __shfl_xor_sync(0xffffffffu, mx1, 2));
        float mn0 = fmaxf(m0, mx0), mn1 = fmaxf(m1, mx1);
        float al0 = fast_exp2(m0 - mn0), al1 = fast_exp2(m1 - mn1);
        m0 = mn0; m1 = mn1;
        float ls0 = 0.f, ls1 = 0.f;
#pragma unroll
        for (int nb = 0; nb < 8; nb++) {
            sa[nb][0] = fast_exp2(sa[nb][0] - mn0);
            sa[nb][1] = fast_exp2(sa[nb][1] - mn0);
            sa[nb][2] = fast_exp2(sa[nb][2] - mn1);
            sa[nb][3] = fast_exp2(sa[nb][3] - mn1);
            ls0 += sa[nb][0] + sa[nb][1];
            ls1 += sa[nb][2] + sa[nb][3];
        }
        l0 = l0 * al0 + ls0;
        l1 = l1 * al1 + ls1;

        bool noresc = __all_sync(0xffffffffu, (al0 == 1.0f) && (al1 == 1.0f));
        if (!noresc) {
#pragma unroll
            for (int j = 0; j < 8; j++) {
                oa[j][0] *= al0; oa[j][1] *= al0;
                oa[j][2] *= al1; oa[j][3] *= al1;
            }
        }

#pragma unroll
        for (int kb2 = 0; kb2 < 4; kb2++) {
            uint32_t pAh[4], pAl[4];
#pragma unroll
            for (int half = 0; half < 2; half++) {
                float v0a = sa[kb2 * 2][half * 2], v1a = sa[kb2 * 2][half * 2 + 1];
                float v0b = sa[kb2 * 2 + 1][half * 2], v1b = sa[kb2 * 2 + 1][half * 2 + 1];
                __nv_bfloat16 h0a = __float2bfloat16(v0a), h1a = __float2bfloat16(v1a);
                __nv_bfloat16 h0b = __float2bfloat16(v0b), h1b = __float2bfloat16(v1b);
                pAh[half]     = pack_bf2(__bfloat162float(h0a), __bfloat162float(h1a));
                pAh[2 + half] = pack_bf2(__bfloat162float(h0b), __bfloat162float(h1b));
                pAl[half]     = pack_bf2(v0a - __bfloat162float(h0a), v1a - __bfloat162float(h1a));
                pAl[2 + half] = pack_bf2(v0b - __bfloat162float(h0b), v1b - __bfloat162float(h1b));
            }
#pragma unroll
            for (int db = 0; db < 4; db++) {
                uint32_t vh4[4], vl4[4];
                int row = kb2 * 16 + ((g & 1) << 3) + rl;
                int gr = db * 2 + (g >> 1);
                int off = row * 128 + gr * 16;
                uint32_t sw = (uint32_t)(off ^ ((off >> 3) & 0x70));
                ldsm_x4t(vh4[0], vh4[1], vh4[2], vh4[3], stg + FV_H + sw);
                ldsm_x4t(vl4[0], vl4[1], vl4[2], vl4[3], stg + FV_L + sw);
                MMA16816(oa[db * 2], pAh, &vh4[0]);
                MMA16816(oa[db * 2], pAh, &vl4[0]);
                MMA16816(oa[db * 2], pAl, &vh4[0]);
                MMA16816(oa[db * 2 + 1], pAh, &vh4[2]);
                MMA16816(oa[db * 2 + 1], pAh, &vl4[2]);
                MMA16816(oa[db * 2 + 1], pAl, &vh4[2]);
            }
        }
    }

    l0 += __shfl_xor_sync(0xffffffffu, l0, 1);
    l0 += __shfl_xor_sync(0xffffffffu, l0, 2);
    l1 += __shfl_xor_sync(0xffffffffu, l1, 1);
    l1 += __shfl_xor_sync(0xffffffffu, l1, 2);
    float inv0 = 1.0f / l0, inv1 = 1.0f / l1;
    float* Og = (comp ? g_o2 : g_o1) + ((size_t)(b * S_) + qr0) * (H_ * DH_) + h * 64;
#pragma unroll
    for (int j = 0; j < 8; j++) {
        int col = j * 8 + (lane & 3) * 2;
        *(float2*)&Og[col] = make_float2(oa[j][0] * inv0, oa[j][1] * inv0);
        *(float2*)&Og[(size_t)8 * (H_ * DH_) + col] = make_float2(oa[j][2] * inv1, oa[j][3] * inv1);
    }
}

// ---------------- combine + groupnorm stats ---------------------------------
__global__ void __launch_bounds__(256) combine_stats_kernel() {
    const int bh = blockIdx.x >> 3;
    const int slice = blockIdx.x & 7;
    const int b = bh / H_, h = bh % H_;
    const float lam = g_lambda;
    double s = 0.0, ss = 0.0;
    const int base_row = b * S_ + slice * 256;
    for (int f = threadIdx.x; f < 256 * (DH_ / 4); f += 256) {
        int row = f >> 4, c = (f & 15) * 4;
        size_t e = (size_t)(base_row + row) * (H_ * DH_) + h * DH_ + c;
        float4 a = *(const float4*)&g_o1[e];
        float4 cc = *(const float4*)&g_o2[e];
        float4 y;
        y.x = a.x - lam * cc.x; y.y = a.y - lam * cc.y;
        y.z = a.z - lam * cc.z; y.w = a.w - lam * cc.w;
        *(float4*)&g_o[e] = y;
        s += (double)y.x + y.y + y.z + y.w;
        ss += (double)y.x * y.x + (double)y.y * y.y + (double)y.z * y.z + (double)y.w * y.w;
    }
    __shared__ double sh_s[256], sh_ss[256];
    sh_s[threadIdx.x] = s; sh_ss[threadIdx.x] = ss;
    __syncthreads();
    for (int st = 128; st > 0; st >>= 1) {
        if (threadIdx.x < st) {
            sh_s[threadIdx.x] += sh_s[threadIdx.x + st];
            sh_ss[threadIdx.x] += sh_ss[threadIdx.x + st];
        }
        __syncthreads();
    }
    if (threadIdx.x == 0) {
        atomicAdd(&g_sum[bh], sh_s[0]);
        atomicAdd(&g_sumsq[bh], sh_ss[0]);
    }
}

// ---------------- normalize + emit bf16 hi/lo -------------------------------
__global__ void __launch_bounds__(256) gn_apply_kernel(const float* __restrict__ gamma,
                                                       const float* __restrict__ beta) {
    int f = blockIdx.x * blockDim.x + threadIdx.x;
    if (f >= (B_ * S_ * H_ * DH_) / 4) return;
    int e = f * 4;
    int c = e % (H_ * DH_);
    int row = e / (H_ * DH_);
    int b = row / S_;
    int h = c / DH_;
    const double n = (double)S_ * DH_;
    double sm = g_sum[b * H_ + h], sq = g_sumsq[b * H_ + h];
    double meand = sm / n;
    float mean = (float)meand;
    float inv = rsqrtf((float)(sq / n - meand * meand) + EPS_);
    float4 x = *(const float4*)&g_o[e];
    float4 gm = *(const float4*)&gamma[c];
    float4 bt = *(const float4*)&beta[c];
    const float post = 1.0f - LAMBDA_INIT;
    float y[4];
    y[0] = ((x.x - mean) * inv * gm.x + bt.x) * post;
    y[1] = ((x.y - mean) * inv * gm.y + bt.y) * post;
    y[2] = ((x.z - mean) * inv * gm.z + bt.z) * post;
    y[3] = ((x.w - mean) * inv * gm.w + bt.w) * post;
    __nv_bfloat16 hh[4], ll[4];
#pragma unroll
    for (int j = 0; j < 4; j++) {
        hh[j] = __float2bfloat16(y[j]);
        ll[j] = __float2bfloat16(y[j] - __bfloat162float(hh[j]));
    }
    *(uint2*)&g_nh[e] = *(uint2*)hh;
    *(uint2*)&g_nl[e] = *(uint2*)ll;
}

// ---------------- launch ----------------------------------------------------
extern "C" void kernel_launch(void* const* d_in, const int* in_sizes, int n_in,
                              void* d_out, int out_size) {
    const float* x     = (const float*)d_in[0];
    const float* amask = (const float*)d_in[1];
    const float* Wq = (const float*)d_in[3];
    const float* Wk = (const float*)d_in[4];
    const float* Wv = (const float*)d_in[5];
    const float* Wo = (const float*)d_in[6];
    const float* lq1 = (const float*)d_in[7];
    const float* lq2 = (const float*)d_in[8];
    const float* lk1 = (const float*)d_in[9];
    const float* lk2 = (const float*)d_in[10];
    const float* gam = (const float*)d_in[11];
    const float* bet = (const float*)d_in[12];
    float* out = (float*)d_out;

    __nv_bfloat16 *woh, *wol, *nh, *nl;
    cudaGetSymbolAddress((void**)&woh, g_woh); cudaGetSymbolAddress((void**)&wol, g_wol);
    cudaGetSymbolAddress((void**)&nh, g_nh);   cudaGetSymbolAddress((void**)&nl, g_nl);

    const int M = B_ * S_;  // 4096

    // 0: lambda + zero stats
    lam_kernel<<<1, 1>>>(lq1, lq2, lk1, lk2);
    // 1: x split
    cvt_x<<<(N4_X + 255) / 256, 256>>>(x);
    // 2: weights split
    cvt_w<<<(N4_W_TOT + 255) / 256, 256>>>(Wq, Wk, Wv, Wo);
    // 3: fused QKV projection, persistent grid (profiled this round)
    cudaFuncSetAttribute(gemm_qkv, cudaFuncAttributeMaxDynamicSharedMemorySize, G_SMEM);
    gemm_qkv<<<296, 256, G_SMEM>>>();
    // 4: flash attention
    cudaFuncSetAttribute(flashmma_kernel, cudaFuncAttributeMaxDynamicSharedMemorySize, FL_SMEM);
    flashmma_kernel<<<dim3(S_ / 64, B_ * H_ * 2), 128, FL_SMEM>>>(amask);
    // 5: combine + stats
    combine_stats_kernel<<<B_ * H_ * 8, 256>>>();
    // 6: normalize + split
    gn_apply_kernel<<<(B_ * S_ * H_ * DH_ / 4 + 255) / 256, 256>>>(gam, bet);
    // 7: output projection
    cudaFuncSetAttribute(gemm_o, cudaFuncAttributeMaxDynamicSharedMemorySize, G_SMEM);
    gemm_o<<<dim3(D_ / 128, M / 128), 256, G_SMEM>>>(nh, nl, woh, wol, out, M, D_, H_ * DH_);
}

// round 13
// speedup vs baseline: 1.1188x; 1.1188x over previous
#include <cuda_runtime.h>
#include <cuda_bf16.h>
#include <cuda_fp16.h>
#include <math.h>
#include <cstdint>

#define B_  2
#define S_  2048
#define D_  1024
#define H_  16
#define DH_ 64
#define QKDIM 2048
#define LOG2E 1.44269504f
#define NEGV2 (-1.44269504e9f)
#define LAMBDA_INIT 0.8f
#define EPS_ 1e-5f

// ---------------- scratch (device globals) ---------------------------------
__device__ float g_o1[(size_t)B_ * S_ * H_ * DH_];
__device__ float g_o2[(size_t)B_ * S_ * H_ * DH_];
__device__ float g_o [(size_t)B_ * S_ * H_ * DH_];
__device__ float g_lambda;
__device__ double g_sum[B_ * H_], g_sumsq[B_ * H_];

// bf16 split buffers (score path: x, Wq, Wk, q, k)
__device__ __nv_bfloat16 g_xh[(size_t)B_ * S_ * D_], g_xl[(size_t)B_ * S_ * D_];
__device__ __nv_bfloat16 g_wqh[QKDIM * D_], g_wql[QKDIM * D_];
__device__ __nv_bfloat16 g_wkh[QKDIM * D_], g_wkl[QKDIM * D_];
__device__ __nv_bfloat16 g_qh[(size_t)B_ * S_ * QKDIM], g_ql[(size_t)B_ * S_ * QKDIM];
__device__ __nv_bfloat16 g_kh[(size_t)B_ * S_ * QKDIM], g_kl[(size_t)B_ * S_ * QKDIM];
// fp16 buffers (linear paths: V projection, PV, output projection)
__device__ __half g_xh2[(size_t)B_ * S_ * D_], g_xl2[(size_t)B_ * S_ * D_];
__device__ __half g_wv2[(H_ * DH_) * D_];
__device__ __half g_wo2[D_ * (H_ * DH_)];
__device__ __half g_v2[(size_t)B_ * S_ * H_ * DH_];
__device__ __half g_nh2[(size_t)B_ * S_ * H_ * DH_], g_nl2[(size_t)B_ * S_ * H_ * DH_];

// ---------------- helpers ---------------------------------------------------
__device__ __forceinline__ uint32_t smem_u32(const void* p) {
    uint32_t a;
    asm("{ .reg .u64 t; cvta.to.shared.u64 t, %1; cvt.u32.u64 %0, t; }" : "=r"(a) : "l"(p));
    return a;
}
__device__ __forceinline__ float fast_exp2(float x) {
    float r;
    asm("ex2.approx.ftz.f32 %0, %1;" : "=f"(r) : "f"(x));
    return r;
}
#define CP16(dst, src) \
    asm volatile("cp.async.cg.shared.global [%0], [%1], 16;" :: "r"(dst), "l"(src) : "memory")
#define CP_COMMIT() asm volatile("cp.async.commit_group;" ::: "memory")
#define CP_WAIT1()  asm volatile("cp.async.wait_group 1;" ::: "memory")
#define CP_WAIT0()  asm volatile("cp.async.wait_group 0;" ::: "memory")

__device__ __forceinline__ void ldsm_x4(uint32_t& r0, uint32_t& r1, uint32_t& r2, uint32_t& r3,
                                        uint32_t addr) {
    asm volatile("ldmatrix.sync.aligned.m8n8.x4.shared.b16 {%0,%1,%2,%3}, [%4];"
                 : "=r"(r0), "=r"(r1), "=r"(r2), "=r"(r3) : "r"(addr));
}
__device__ __forceinline__ void ldsm_x4t(uint32_t& r0, uint32_t& r1, uint32_t& r2, uint32_t& r3,
                                         uint32_t addr) {
    asm volatile("ldmatrix.sync.aligned.m8n8.x4.trans.shared.b16 {%0,%1,%2,%3}, [%4];"
                 : "=r"(r0), "=r"(r1), "=r"(r2), "=r"(r3) : "r"(addr));
}
#define MMA16816(d, a, b) \
    asm volatile("mma.sync.aligned.m16n8k16.row.col.f32.bf16.bf16.f32 " \
                 "{%0,%1,%2,%3}, {%4,%5,%6,%7}, {%8,%9}, {%0,%1,%2,%3};" \
                 : "+f"((d)[0]), "+f"((d)[1]), "+f"((d)[2]), "+f"((d)[3]) \
                 : "r"((a)[0]), "r"((a)[1]), "r"((a)[2]), "r"((a)[3]), \
                   "r"((b)[0]), "r"((b)[1]))
#define MMAF16(d, a, b) \
    asm volatile("mma.sync.aligned.m16n8k16.row.col.f32.f16.f16.f32 " \
                 "{%0,%1,%2,%3}, {%4,%5,%6,%7}, {%8,%9}, {%0,%1,%2,%3};" \
                 : "+f"((d)[0]), "+f"((d)[1]), "+f"((d)[2]), "+f"((d)[3]) \
                 : "r"((a)[0]), "r"((a)[1]), "r"((a)[2]), "r"((a)[3]), \
                   "r"((b)[0]), "r"((b)[1]))

__device__ __forceinline__ uint32_t pack_h2(float lo, float hi) {
    __half2 t = __floats2half2_rn(lo, hi);
    return *(uint32_t*)&t;
}

// ---------------- lambda + zero stats ---------------------------------------
__global__ void lam_kernel(const float* __restrict__ lq1, const float* __restrict__ lq2,
                           const float* __restrict__ lk1, const float* __restrict__ lk2) {
    float d1 = 0.f, d2 = 0.f;
    for (int i = 0; i < DH_; i++) { d1 += lq1[i] * lk1[i]; d2 += lq2[i] * lk2[i]; }
    g_lambda = expf(d1) - expf(d2) + LAMBDA_INIT;
    for (int i = 0; i < B_ * H_; i++) { g_sum[i] = 0.0; g_sumsq[i] = 0.0; }
}

// ---------------- conversions ------------------------------------------------
#define N4_X  (B_ * S_ * D_ / 4)
#define N4_WQ (QKDIM * D_ / 4)
#define N4_WV (H_ * DH_ * D_ / 4)
#define N4_W_TOT (2 * N4_WQ + 2 * N4_WV)

__device__ __forceinline__ void split4(const float* src, __nv_bfloat16* h, __nv_bfloat16* l,
                                       size_t i) {
    float4 v = ((const float4*)src)[i];
    float vv[4] = {v.x, v.y, v.z, v.w};
    __nv_bfloat16 hh[4], ll[4];
#pragma unroll
    for (int j = 0; j < 4; j++) {
        hh[j] = __float2bfloat16(vv[j]);
        ll[j] = __float2bfloat16(vv[j] - __bfloat162float(hh[j]));
    }
    *(uint2*)&h[i * 4] = *(uint2*)hh;
    *(uint2*)&l[i * 4] = *(uint2*)ll;
}
__device__ __forceinline__ void split4h(const float* src, __half* h, __half* l, size_t i) {
    float4 v = ((const float4*)src)[i];
    float vv[4] = {v.x, v.y, v.z, v.w};
    __half hh[4], ll[4];
#pragma unroll
    for (int j = 0; j < 4; j++) {
        hh[j] = __float2half_rn(vv[j]);
        ll[j] = __float2half_rn(vv[j] - __half2float(hh[j]));
    }
    *(uint2*)&h[i * 4] = *(uint2*)hh;
    *(uint2*)&l[i * 4] = *(uint2*)ll;
}
__device__ __forceinline__ void cvt4h(const float* src, __half* h, size_t i) {
    float4 v = ((const float4*)src)[i];
    __half hh[4];
    hh[0] = __float2half_rn(v.x); hh[1] = __float2half_rn(v.y);
    hh[2] = __float2half_rn(v.z); hh[3] = __float2half_rn(v.w);
    *(uint2*)&h[i * 4] = *(uint2*)hh;
}

__global__ void __launch_bounds__(256) cvt_x(const float* __restrict__ x) {
    int i = blockIdx.x * 256 + threadIdx.x;
    if (i < N4_X) {
        split4(x, g_xh, g_xl, i);
        split4h(x, g_xh2, g_xl2, i);
    }
}

__global__ void __launch_bounds__(256) cvt_w(
    const float* __restrict__ Wq, const float* __restrict__ Wk,
    const float* __restrict__ Wv, const float* __restrict__ Wo) {
    int i = blockIdx.x * 256 + threadIdx.x;
    if (i < N4_WQ) { split4(Wq, g_wqh, g_wql, i); return; }
    i -= N4_WQ;
    if (i < N4_WQ) { split4(Wk, g_wkh, g_wkl, i); return; }
    i -= N4_WQ;
    if (i < N4_WV) { cvt4h(Wv, g_wv2, i); return; }
    i -= N4_WV;
    if (i < N4_WV) { cvt4h(Wo, g_wo2, i); return; }
}

// ---------------- GEMM loaders / chunks --------------------------------------
#define GSTAGE 32768
#define G_SMEM (3 * GSTAGE)

// bf16 x3 loader: A hi/lo + B hi/lo (4 x 8KB)
__device__ __forceinline__ void g_issue(
    const __nv_bfloat16* __restrict__ Ah, const __nv_bfloat16* __restrict__ Al,
    const __nv_bfloat16* __restrict__ Bh, const __nv_bfloat16* __restrict__ Bl,
    uint32_t sbuf, int tid, int bm, int bn, int K, int c) {
#pragma unroll
    for (int i = 0; i < 2; i++) {
        int ch = tid + i * 256;
        int p = ch >> 3, c16 = ch & 7;
        int r = (p << 1) + (c16 >> 2);
        int kb = (c16 & 3) * 8;
        int off = p * 128 + c16 * 16;
        uint32_t dst = sbuf + (off ^ ((off >> 3) & 0x70));
        size_t ga = (size_t)(bm + r) * K + c * 32 + kb;
        size_t gb = (size_t)(bn + r) * K + c * 32 + kb;
        CP16(dst,         Ah + ga);
        CP16(dst + 8192,  Al + ga);
        CP16(dst + 16384, Bh + gb);
        CP16(dst + 24576, Bl + gb);
    }
    CP_COMMIT();
}

// fp16 x2 loader: A hi/lo + B single (3 x 8KB)
__device__ __forceinline__ void g_issue_h2(
    const __half* __restrict__ Ah, const __half* __restrict__ Al,
    const __half* __restrict__ B2,
    uint32_t sbuf, int tid, int bm, int bn, int K, int c) {
#pragma unroll
    for (int i = 0; i < 2; i++) {
        int ch = tid + i * 256;
        int p = ch >> 3, c16 = ch & 7;
        int r = (p << 1) + (c16 >> 2);
        int kb = (c16 & 3) * 8;
        int off = p * 128 + c16 * 16;
        uint32_t dst = sbuf + (off ^ ((off >> 3) & 0x70));
        size_t ga = (size_t)(bm + r) * K + c * 32 + kb;
        size_t gb = (size_t)(bn + r) * K + c * 32 + kb;
        CP16(dst,         Ah + ga);
        CP16(dst + 8192,  Al + ga);
        CP16(dst + 16384, B2 + gb);
    }
    CP_COMMIT();
}

__device__ __forceinline__ void g_chunk(uint32_t sbuf, int wm, int wn, int g, int rl,
                                        float acc[2][8][4]) {
#pragma unroll
    for (int ks = 0; ks < 2; ks++) {
        uint32_t ah[2][4], al[2][4];
#pragma unroll
        for (int mb = 0; mb < 2; mb++) {
            int r = wm + mb * 16 + ((g & 1) << 3) + rl;
            int c16 = ((r & 1) << 2) + ks * 2 + (g >> 1);
            int off = (r >> 1) * 128 + c16 * 16;
            uint32_t sw = (uint32_t)(off ^ ((off >> 3) & 0x70));
            ldsm_x4(ah[mb][0], ah[mb][1], ah[mb][2], ah[mb][3], sbuf + sw);
            ldsm_x4(al[mb][0], al[mb][1], al[mb][2], al[mb][3], sbuf + 8192 + sw);
        }
        uint32_t bh[4][4], bl[4][4];
#pragma unroll
        for (int np = 0; np < 4; np++) {
            int r = wn + np * 16 + ((g >> 1) << 3) + rl;
            int c16 = ((r & 1) << 2) + ks * 2 + (g & 1);
            int off = (r >> 1) * 128 + c16 * 16;
            uint32_t sw = (uint32_t)(off ^ ((off >> 3) & 0x70));
            ldsm_x4(bh[np][0], bh[np][1], bh[np][2], bh[np][3], sbuf + 16384 + sw);
            ldsm_x4(bl[np][0], bl[np][1], bl[np][2], bl[np][3], sbuf + 24576 + sw);
        }
#pragma unroll
        for (int mb = 0; mb < 2; mb++)
#pragma unroll
            for (int j = 0; j < 8; j++) {
                MMA16816(acc[mb][j], ah[mb], &bh[j >> 1][(j & 1) * 2]);
                MMA16816(acc[mb][j], ah[mb], &bl[j >> 1][(j & 1) * 2]);
                MMA16816(acc[mb][j], al[mb], &bh[j >> 1][(j & 1) * 2]);
            }
    }
}

__device__ __forceinline__ void g_chunk_h2(uint32_t sbuf, int wm, int wn, int g, int rl,
                                           float acc[2][8][4]) {
#pragma unroll
    for (int ks = 0; ks < 2; ks++) {
        uint32_t ah[2][4], al[2][4];
#pragma unroll
        for (int mb = 0; mb < 2; mb++) {
            int r = wm + mb * 16 + ((g & 1) << 3) + rl;
            int c16 = ((r & 1) << 2) + ks * 2 + (g >> 1);
            int off = (r >> 1) * 128 + c16 * 16;
            uint32_t sw = (uint32_t)(off ^ ((off >> 3) & 0x70));
            ldsm_x4(ah[mb][0], ah[mb][1], ah[mb][2], ah[mb][3], sbuf + sw);
            ldsm_x4(al[mb][0], al[mb][1], al[mb][2], al[mb][3], sbuf + 8192 + sw);
        }
        uint32_t bh[4][4];
#pragma unroll
        for (int np = 0; np < 4; np++) {
            int r = wn + np * 16 + ((g >> 1) << 3) + rl;
            int c16 = ((r & 1) << 2) + ks * 2 + (g & 1);
            int off = (r >> 1) * 128 + c16 * 16;
            uint32_t sw = (uint32_t)(off ^ ((off >> 3) & 0x70));
            ldsm_x4(bh[np][0], bh[np][1], bh[np][2], bh[np][3], sbuf + 16384 + sw);
        }
#pragma unroll
        for (int mb = 0; mb < 2; mb++)
#pragma unroll
            for (int j = 0; j < 8; j++) {
                MMAF16(acc[mb][j], ah[mb], &bh[j >> 1][(j & 1) * 2]);
                MMAF16(acc[mb][j], al[mb], &bh[j >> 1][(j & 1) * 2]);
            }
    }
}

// ---------------- fused QKV projection ---------------------------------------
// grid (40, 32). nt<16: Q (bf16 x3), nt<32: K (bf16 x3), else V (fp16 x2).
__global__ void __launch_bounds__(256, 2) gemm_qkv() {
    extern __shared__ char smem[];
    const uint32_t sbase = smem_u32(smem);
    const int tid = threadIdx.x, wid = tid >> 5, lane = tid & 31;
    const int nt = blockIdx.x;
    const int bm = blockIdx.y * 128;
    const int wm = (wid & 3) * 32;
    const int wn = (wid >> 2) * 64;
    const int g = lane >> 3, rl = lane & 7;
    const int K = D_;
    const int nch = K >> 5;

    float acc[2][8][4];
#pragma unroll
    for (int a = 0; a < 2; a++)
#pragma unroll
        for (int b = 0; b < 8; b++)
#pragma unroll
            for (int d = 0; d < 4; d++) acc[a][b][d] = 0.f;

    if (nt < 32) {
        const __nv_bfloat16 *Bh, *Bl;
        __nv_bfloat16 *Oh, *Ol;
        int bn;
        if (nt < 16) { Bh = g_wqh; Bl = g_wql; Oh = g_qh; Ol = g_ql; bn = nt * 128; }
        else         { Bh = g_wkh; Bl = g_wkl; Oh = g_kh; Ol = g_kl; bn = (nt - 16) * 128; }

        g_issue(g_xh, g_xl, Bh, Bl, sbase, tid, bm, bn, K, 0);
        g_issue(g_xh, g_xl, Bh, Bl, sbase + GSTAGE, tid, bm, bn, K, 1);
        for (int c = 0; c < nch; c++) {
            if (c + 1 < nch) { CP_WAIT1(); } else { CP_WAIT0(); }
            __syncthreads();
            if (c + 2 < nch)
                g_issue(g_xh, g_xl, Bh, Bl, sbase + (uint32_t)((c + 2) % 3) * GSTAGE, tid, bm, bn, K, c + 2);
            g_chunk(sbase + (uint32_t)(c % 3) * GSTAGE, wm, wn, g, rl, acc);
        }

#pragma unroll
        for (int mb = 0; mb < 2; mb++) {
            int row0 = bm + wm + mb * 16 + (lane >> 2);
#pragma unroll
            for (int j = 0; j < 8; j++) {
                int col = bn + wn + j * 8 + (lane & 3) * 2;
#pragma unroll
                for (int rr = 0; rr < 2; rr++) {
                    float v0 = acc[mb][j][rr * 2], v1 = acc[mb][j][rr * 2 + 1];
                    __nv_bfloat16 h0 = __float2bfloat16(v0), h1 = __float2bfloat16(v1);
                    __nv_bfloat16 l0 = __float2bfloat16(v0 - __bfloat162float(h0));
                    __nv_bfloat16 l1 = __float2bfloat16(v1 - __bfloat162float(h1));
                    size_t idx = (size_t)(row0 + rr * 8) * QKDIM + col;
                    __nv_bfloat162 hp; hp.x = h0; hp.y = h1;
                    __nv_bfloat162 lp; lp.x = l0; lp.y = l1;
                    *(__nv_bfloat162*)&Oh[idx] = hp;
                    *(__nv_bfloat162*)&Ol[idx] = lp;
                }
            }
        }
    } else {
        const int bn = (nt - 32) * 128;
        g_issue_h2(g_xh2, g_xl2, g_wv2, sbase, tid, bm, bn, K, 0);
        g_issue_h2(g_xh2, g_xl2, g_wv2, sbase + GSTAGE, tid, bm, bn, K, 1);
        for (int c = 0; c < nch; c++) {
            if (c + 1 < nch) { CP_WAIT1(); } else { CP_WAIT0(); }
            __syncthreads();
            if (c + 2 < nch)
                g_issue_h2(g_xh2, g_xl2, g_wv2, sbase + (uint32_t)((c + 2) % 3) * GSTAGE, tid, bm, bn, K, c + 2);
            g_chunk_h2(sbase + (uint32_t)(c % 3) * GSTAGE, wm, wn, g, rl, acc);
        }

#pragma unroll
        for (int mb = 0; mb < 2; mb++) {
            int row0 = bm + wm + mb * 16 + (lane >> 2);
#pragma unroll
            for (int j = 0; j < 8; j++) {
                int col = bn + wn + j * 8 + (lane & 3) * 2;
#pragma unroll
                for (int rr = 0; rr < 2; rr++) {
                    __half2 p = __floats2half2_rn(acc[mb][j][rr * 2], acc[mb][j][rr * 2 + 1]);
                    *(__half2*)&g_v2[(size_t)(row0 + rr * 8) * (H_ * DH_) + col] = p;
                }
            }
        }
    }
}

// ---------------- output projection (fp16 x2, fp32 out) ----------------------
__global__ void __launch_bounds__(256, 2) gemm_o2(float* __restrict__ Cf) {
    extern __shared__ char smem[];
    const uint32_t sbase = smem_u32(smem);
    const int tid = threadIdx.x, wid = tid >> 5, lane = tid & 31;
    const int bm = blockIdx.y * 128, bn = blockIdx.x * 128;
    const int wm = (wid & 3) * 32;
    const int wn = (wid >> 2) * 64;
    const int g = lane >> 3, rl = lane & 7;
    const int K = H_ * DH_, N = D_;
    const int nch = K >> 5;

    float acc[2][8][4];
#pragma unroll
    for (int a = 0; a < 2; a++)
#pragma unroll
        for (int b = 0; b < 8; b++)
#pragma unroll
            for (int d = 0; d < 4; d++) acc[a][b][d] = 0.f;

    g_issue_h2(g_nh2, g_nl2, g_wo2, sbase, tid, bm, bn, K, 0);
    g_issue_h2(g_nh2, g_nl2, g_wo2, sbase + GSTAGE, tid, bm, bn, K, 1);
    for (int c = 0; c < nch; c++) {
        if (c + 1 < nch) { CP_WAIT1(); } else { CP_WAIT0(); }
        __syncthreads();
        if (c + 2 < nch)
            g_issue_h2(g_nh2, g_nl2, g_wo2, sbase + (uint32_t)((c + 2) % 3) * GSTAGE, tid, bm, bn, K, c + 2);
        g_chunk_h2(sbase + (uint32_t)(c % 3) * GSTAGE, wm, wn, g, rl, acc);
    }

#pragma unroll
    for (int mb = 0; mb < 2; mb++) {
        int row0 = bm + wm + mb * 16 + (lane >> 2);
#pragma unroll
        for (int j = 0; j < 8; j++) {
            int col = bn + wn + j * 8 + (lane & 3) * 2;
            *(float2*)&Cf[(size_t)row0 * N + col]       = make_float2(acc[mb][j][0], acc[mb][j][1]);
            *(float2*)&Cf[(size_t)(row0 + 8) * N + col] = make_float2(acc[mb][j][2], acc[mb][j][3]);
        }
    }
}

// ---------------- flash attention --------------------------------------------
// 4 warps, 64-q tiles, 2 CTAs/SM. QK bf16 x3, PV fp16 x2 (V single fp16).
#define FK_H 0
#define FK_L 8192
#define FV2  16384
#define FAM  24576
#define FSTG_SZ 24832
#define FQ_H (2 * FSTG_SZ)
#define FQ_L (2 * FSTG_SZ + 8192)
#define FL_SMEM (3 * FSTG_SZ)   // 74496

__device__ __forceinline__ void f_issue_stage(uint32_t stg, int tid, int b, int h, int comp,
                                              int kt, const float* __restrict__ amask) {
    const char* Khg = (const char*)(g_kh + ((size_t)(b * S_) + kt * 64) * QKDIM + h * 128 + comp * 64);
    const char* Klg = (const char*)(g_kl + ((size_t)(b * S_) + kt * 64) * QKDIM + h * 128 + comp * 64);
    const char* Vg  = (const char*)(g_v2 + ((size_t)(b * S_) + kt * 64) * (H_ * DH_) + h * 64);
#pragma unroll
    for (int i = 0; i < 4; i++) {
        int t = tid + i * 128;
        int row = t >> 3, gr = t & 7;
        int off = row * 128 + gr * 16;
        uint32_t sw = (uint32_t)(off ^ ((off >> 3) & 0x70));
        CP16(stg + FK_H + sw, Khg + (size_t)row * (QKDIM * 2) + gr * 16);
        CP16(stg + FK_L + sw, Klg + (size_t)row * (QKDIM * 2) + gr * 16);
        CP16(stg + FV2 + sw,  Vg  + (size_t)row * (H_ * DH_ * 2) + gr * 16);
    }
    if (tid < 16)
        CP16(stg + FAM + tid * 16, amask + b * S_ + kt * 64 + tid * 4);
    CP_COMMIT();
}

__global__ void __launch_bounds__(128) flashmma_kernel(const float* __restrict__ amask) {
    extern __shared__ char fsm[];
    const uint32_t sb = smem_u32(fsm);
    const int tid = threadIdx.x, wid = tid >> 5, lane = tid & 31;
    const int g = lane >> 3, rl = lane & 7;
    const int qt = (gridDim.x - 1) - blockIdx.x;
    const int z = blockIdx.y;
    const int comp = z & 1;
    const int bh = z >> 1;
    const int b = bh / H_, h = bh % H_;
    const float slope2 = exp2f(-8.0f * (float)(h + 1) / (float)H_) * LOG2E;
    const float scale2 = 0.125f * LOG2E;
    const int nkt = qt + 1;

    {
        const char* Qhg = (const char*)(g_qh + ((size_t)(b * S_) + qt * 64) * QKDIM + h * 128 + comp * 64);
        const char* Qlg = (const char*)(g_ql + ((size_t)(b * S_) + qt * 64) * QKDIM + h * 128 + comp * 64);
#pragma unroll
        for (int i = 0; i < 4; i++) {
            int t = tid + i * 128;
            int row = t >> 3, gr = t & 7;
            int off = row * 128 + gr * 16;
            uint32_t sw = (uint32_t)(off ^ ((off >> 3) & 0x70));
            CP16(sb + FQ_H + sw, Qhg + (size_t)row * (QKDIM * 2) + gr * 16);
            CP16(sb + FQ_L + sw, Qlg + (size_t)row * (QKDIM * 2) + gr * 16);
        }
    }
    f_issue_stage(sb, tid, b, h, comp, qt, amask);
    if (nkt > 1) f_issue_stage(sb + FSTG_SZ, tid, b, h, comp, qt - 1, amask);

    float oa[8][4];
#pragma unroll
    for (int j = 0; j < 8; j++)
#pragma unroll
        for (int d = 0; d < 4; d++) oa[j][d] = 0.f;
    float m0 = -1e30f, m1 = -1e30f, l0 = 0.f, l1 = 0.f;
    uint32_t qAh[4][4], qAl[4][4];

    const int qr0 = qt * 64 + wid * 16 + (lane >> 2);
    const float d8 = -8.0f * slope2;

    float cst0[8], cst1[8];
#pragma unroll
    for (int nb = 0; nb < 8; nb++) {
        cst0[nb] = slope2 * (float)(nb * 8 + (lane & 3) * 2);
        cst1[nb] = cst0[nb] + slope2;
    }
    float base0 = -slope2 * (float)(wid * 16 + (lane >> 2));
    const float base_step = 64.0f * slope2;

    for (int it = 0; it < nkt; it++) {
        const int ktile = qt - it;
        if (it + 1 < nkt) { CP_WAIT1(); } else { CP_WAIT0(); }
        __syncthreads();
        if (it == 0) {
#pragma unroll
            for (int kb = 0; kb < 4; kb++) {
                int row = wid * 16 + ((g & 1) << 3) + rl;
                int gr = kb * 2 + (g >> 1);
                int off = row * 128 + gr * 16;
                uint32_t sw = (uint32_t)(off ^ ((off >> 3) & 0x70));
                ldsm_x4(qAh[kb][0], qAh[kb][1], qAh[kb][2], qAh[kb][3], sb + FQ_H + sw);
                ldsm_x4(qAl[kb][0], qAl[kb][1], qAl[kb][2], qAl[kb][3], sb + FQ_L + sw);
            }
            if (nkt > 2) __syncthreads();
        }
        if (it + 2 < nkt)
            f_issue_stage(sb + (uint32_t)((it + 2) % 3) * FSTG_SZ, tid, b, h, comp, qt - (it + 2), amask);
        uint32_t stg = sb + (uint32_t)(it % 3) * FSTG_SZ;

        // ---- S = Q K^T (bf16 x3) ----
        float sa[8][4];
#pragma unroll
        for (int j = 0; j < 8; j++)
#pragma unroll
            for (int d = 0; d < 4; d++) sa[j][d] = 0.f;
#pragma unroll
        for (int kb = 0; kb < 4; kb++) {
#pragma unroll
            for (int nb2 = 0; nb2 < 4; nb2++) {
                uint32_t kh4[4], kl4[4];
                int row = nb2 * 16 + ((g >> 1) << 3) + rl;
                int gr = kb * 2 + (g & 1);
                int off = row * 128 + gr * 16;
                uint32_t sw = (uint32_t)(off ^ ((off >> 3) & 0x70));
                ldsm_x4(kh4[0], kh4[1], kh4[2], kh4[3], stg + FK_H + sw);
                ldsm_x4(kl4[0], kl4[1], kl4[2], kl4[3], stg + FK_L + sw);
                MMA16816(sa[nb2 * 2], qAh[kb], &kh4[0]);
                MMA16816(sa[nb2 * 2], qAh[kb], &kl4[0]);
                MMA16816(sa[nb2 * 2], qAl[kb], &kh4[0]);
                MMA16816(sa[nb2 * 2 + 1], qAh[kb], &kh4[2]);
                MMA16816(sa[nb2 * 2 + 1], qAh[kb], &kl4[2]);
                MMA16816(sa[nb2 * 2 + 1], qAl[kb], &kh4[2]);
            }
        }

        // ---- bias + masks (base-2 domain) ----
        const float* ams = (const float*)(fsm + (stg - sb) + FAM);
        float colc[8][2];
#pragma unroll
        for (int nb = 0; nb < 8; nb++) {
            int kc = nb * 8 + (lane & 3) * 2;
            colc[nb][0] = fmaf(1.0f - ams[kc],     NEGV2, base0 + cst0[nb]);
            colc[nb][1] = fmaf(1.0f - ams[kc + 1], NEGV2, base0 + cst1[nb]);
        }
#pragma unroll
        for (int nb = 0; nb < 8; nb++) {
            sa[nb][0] = fmaf(sa[nb][0], scale2, colc[nb][0]);
            sa[nb][1] = fmaf(sa[nb][1], scale2, colc[nb][1]);
            sa[nb][2] = fmaf(sa[nb][2], scale2, colc[nb][0] + d8);
            sa[nb][3] = fmaf(sa[nb][3], scale2, colc[nb][1] + d8);
        }
        if (it == 0) {
            const int kcb = ktile * 64;
#pragma unroll
            for (int nb = 0; nb < 8; nb++) {
                int k0 = kcb + nb * 8 + (lane & 3) * 2;
                if (k0 > qr0)         sa[nb][0] += NEGV2;
                if (k0 + 1 > qr0)     sa[nb][1] += NEGV2;
                if (k0 > qr0 + 8)     sa[nb][2] += NEGV2;
                if (k0 + 1 > qr0 + 8) sa[nb][3] += NEGV2;
            }
        }
        base0 -= base_step;

        // ---- online softmax (base 2; l lane-local) ----
        float mx0 = -1e30f, mx1 = -1e30f;
#pragma unroll
        for (int nb = 0; nb < 8; nb++) {
            mx0 = fmaxf(mx0, fmaxf(sa[nb][0], sa[nb][1]));
            mx1 = fmaxf(mx1, fmaxf(sa[nb][2], sa[nb][3]));
        }
        mx0 = fmaxf(mx0, __shfl_xor_sync(0xffffffffu, mx0, 1));
        mx0 = fmaxf(mx0, __shfl_xor_sync(0xffffffffu, mx0, 2));
        mx1 = fmaxf(mx1, __shfl_xor_sync(0xffffffffu, mx1, 1));
        mx1 = fmaxf(mx1, __shfl_xor_sync(0xffffffffu, mx1, 2));
        float mn0 = fmaxf(m0, mx0), mn1 = fmaxf(m1, mx1);
        float al0 = fast_exp2(m0 - mn0), al1 = fast_exp2(m1 - mn1);
        m0 = mn0; m1 = mn1;
        float ls0 = 0.f, ls1 = 0.f;
#pragma unroll
        for (int nb = 0; nb < 8; nb++) {
            sa[nb][0] = fast_exp2(sa[nb][0] - mn0);
            sa[nb][1] = fast_exp2(sa[nb][1] - mn0);
            sa[nb][2] = fast_exp2(sa[nb][2] - mn1);
            sa[nb][3] = fast_exp2(sa[nb][3] - mn1);
            ls0 += sa[nb][0] + sa[nb][1];
            ls1 += sa[nb][2] + sa[nb][3];
        }
        l0 = l0 * al0 + ls0;
        l1 = l1 * al1 + ls1;

        bool noresc = __all_sync(0xffffffffu, (al0 == 1.0f) && (al1 == 1.0f));
        if (!noresc) {
#pragma unroll
            for (int j = 0; j < 8; j++) {
                oa[j][0] *= al0; oa[j][1] *= al0;
                oa[j][2] *= al1; oa[j][3] *= al1;
            }
        }

        // ---- O += P V (fp16 x2: P hi/lo, V single) ----
#pragma unroll
        for (int kb2 = 0; kb2 < 4; kb2++) {
            uint32_t pAh[4], pAl[4];
#pragma unroll
            for (int half = 0; half < 2; half++) {
                float v0a = sa[kb2 * 2][half * 2], v1a = sa[kb2 * 2][half * 2 + 1];
                float v0b = sa[kb2 * 2 + 1][half * 2], v1b = sa[kb2 * 2 + 1][half * 2 + 1];
                __half h0a = __float2half_rn(v0a), h1a = __float2half_rn(v1a);
                __half h0b = __float2half_rn(v0b), h1b = __float2half_rn(v1b);
                pAh[half]     = pack_h2(__half2float(h0a), __half2float(h1a));
                pAh[2 + half] = pack_h2(__half2float(h0b), __half2float(h1b));
                pAl[half]     = pack_h2(v0a - __half2float(h0a), v1a - __half2float(h1a));
                pAl[2 + half] = pack_h2(v0b - __half2float(h0b), v1b - __half2float(h1b));
            }
#pragma unroll
            for (int db = 0; db < 4; db++) {
                uint32_t vh4[4];
                int row = kb2 * 16 + ((g & 1) << 3) + rl;
                int gr = db * 2 + (g >> 1);
                int off = row * 128 + gr * 16;
                uint32_t sw = (uint32_t)(off ^ ((off >> 3) & 0x70));
                ldsm_x4t(vh4[0], vh4[1], vh4[2], vh4[3], stg + FV2 + sw);
                MMAF16(oa[db * 2], pAh, &vh4[0]);
                MMAF16(oa[db * 2], pAl, &vh4[0]);
                MMAF16(oa[db * 2 + 1], pAh, &vh4[2]);
                MMAF16(oa[db * 2 + 1], pAl, &vh4[2]);
            }
        }
    }

    l0 += __shfl_xor_sync(0xffffffffu, l0, 1);
    l0 += __shfl_xor_sync(0xffffffffu, l0, 2);
    l1 += __shfl_xor_sync(0xffffffffu, l1, 1);
    l1 += __shfl_xor_sync(0xffffffffu, l1, 2);
    float inv0 = 1.0f / l0, inv1 = 1.0f / l1;
    float* Og = (comp ? g_o2 : g_o1) + ((size_t)(b * S_) + qr0) * (H_ * DH_) + h * 64;
#pragma unroll
    for (int j = 0; j < 8; j++) {
        int col = j * 8 + (lane & 3) * 2;
        *(float2*)&Og[col] = make_float2(oa[j][0] * inv0, oa[j][1] * inv0);
        *(float2*)&Og[(size_t)8 * (H_ * DH_) + col] = make_float2(oa[j][2] * inv1, oa[j][3] * inv1);
    }
}

// ---------------- combine + groupnorm stats ---------------------------------
__global__ void __launch_bounds__(256) combine_stats_kernel() {
    const int bh = blockIdx.x >> 3;
    const int slice = blockIdx.x & 7;
    const int b = bh / H_, h = bh % H_;
    const float lam = g_lambda;
    double s = 0.0, ss = 0.0;
    const int base_row = b * S_ + slice * 256;
    for (int f = threadIdx.x; f < 256 * (DH_ / 4); f += 256) {
        int row = f >> 4, c = (f & 15) * 4;
        size_t e = (size_t)(base_row + row) * (H_ * DH_) + h * DH_ + c;
        float4 a = *(const float4*)&g_o1[e];
        float4 cc = *(const float4*)&g_o2[e];
        float4 y;
        y.x = a.x - lam * cc.x; y.y = a.y - lam * cc.y;
        y.z = a.z - lam * cc.z; y.w = a.w - lam * cc.w;
        *(float4*)&g_o[e] = y;
        s += (double)y.x + y.y + y.z + y.w;
        ss += (double)y.x * y.x + (double)y.y * y.y + (double)y.z * y.z + (double)y.w * y.w;
    }
    __shared__ double sh_s[256], sh_ss[256];
    sh_s[threadIdx.x] = s; sh_ss[threadIdx.x] = ss;
    __syncthreads();
    for (int st = 128; st > 0; st >>= 1) {
        if (threadIdx.x < st) {
            sh_s[threadIdx.x] += sh_s[threadIdx.x + st];
            sh_ss[threadIdx.x] += sh_ss[threadIdx.x + st];
        }
        __syncthreads();
    }
    if (threadIdx.x == 0) {
        atomicAdd(&g_sum[bh], sh_s[0]);
        atomicAdd(&g_sumsq[bh], sh_ss[0]);
    }
}

// ---------------- normalize + emit fp16 hi/lo --------------------------------
__global__ void __launch_bounds__(256) gn_apply_kernel(const float* __restrict__ gamma,
                                                       const float* __restrict__ beta) {
    int f = blockIdx.x * blockDim.x + threadIdx.x;
    if (f >= (B_ * S_ * H_ * DH_) / 4) return;
    int e = f * 4;
    int c = e % (H_ * DH_);
    int row = e / (H_ * DH_);
    int b = row / S_;
    int h = c / DH_;
    const double n = (double)S_ * DH_;
    double sm = g_sum[b * H_ + h], sq = g_sumsq[b * H_ + h];
    double meand = sm / n;
    float mean = (float)meand;
    float inv = rsqrtf((float)(sq / n - meand * meand) + EPS_);
    float4 x = *(const float4*)&g_o[e];
    float4 gm = *(const float4*)&gamma[c];
    float4 bt = *(const float4*)&beta[c];
    const float post = 1.0f - LAMBDA_INIT;
    float y[4];
    y[0] = ((x.x - mean) * inv * gm.x + bt.x) * post;
    y[1] = ((x.y - mean) * inv * gm.y + bt.y) * post;
    y[2] = ((x.z - mean) * inv * gm.z + bt.z) * post;
    y[3] = ((x.w - mean) * inv * gm.w + bt.w) * post;
    __half hh[4], ll[4];
#pragma unroll
    for (int j = 0; j < 4; j++) {
        hh[j] = __float2half_rn(y[j]);
        ll[j] = __float2half_rn(y[j] - __half2float(hh[j]));
    }
    *(uint2*)&g_nh2[e] = *(uint2*)hh;
    *(uint2*)&g_nl2[e] = *(uint2*)ll;
}

// ---------------- launch ----------------------------------------------------
extern "C" void kernel_launch(void* const* d_in, const int* in_sizes, int n_in,
                              void* d_out, int out_size) {
    const float* x     = (const float*)d_in[0];
    const float* amask = (const float*)d_in[1];
    const float* Wq = (const float*)d_in[3];
    const float* Wk = (const float*)d_in[4];
    const float* Wv = (const float*)d_in[5];
    const float* Wo = (const float*)d_in[6];
    const float* lq1 = (const float*)d_in[7];
    const float* lq2 = (const float*)d_in[8];
    const float* lk1 = (const float*)d_in[9];
    const float* lk2 = (const float*)d_in[10];
    const float* gam = (const float*)d_in[11];
    const float* bet = (const float*)d_in[12];
    float* out = (float*)d_out;

    const int M = B_ * S_;  // 4096

    // 0: lambda + zero stats
    lam_kernel<<<1, 1>>>(lq1, lq2, lk1, lk2);
    // 1: x splits (bf16 + fp16)
    cvt_x<<<(N4_X + 255) / 256, 256>>>(x);
    // 2: weight conversions
    cvt_w<<<(N4_W_TOT + 255) / 256, 256>>>(Wq, Wk, Wv, Wo);
    // 3: fused QKV projection (profiled)
    cudaFuncSetAttribute(gemm_qkv, cudaFuncAttributeMaxDynamicSharedMemorySize, G_SMEM);
    gemm_qkv<<<dim3(40, M / 128), 256, G_SMEM>>>();
    // 4: flash attention
    cudaFuncSetAttribute(flashmma_kernel, cudaFuncAttributeMaxDynamicSharedMemorySize, FL_SMEM);
    flashmma_kernel<<<dim3(S_ / 64, B_ * H_ * 2), 128, FL_SMEM>>>(amask);
    // 5: combine + stats
    combine_stats_kernel<<<B_ * H_ * 8, 256>>>();
    // 6: normalize + fp16 split
    gn_apply_kernel<<<(B_ * S_ * H_ * DH_ / 4 + 255) / 256, 256>>>(gam, bet);
    // 7: output projection (fp16 x2)
    cudaFuncSetAttribute(gemm_o2, cudaFuncAttributeMaxDynamicSharedMemorySize, G_SMEM);
    gemm_o2<<<dim3(D_ / 128, M / 128), 256, G_SMEM>>>(out);
}

// round 14
// speedup vs baseline: 1.3901x; 1.2424x over previous
#include <cuda_runtime.h>
#include <cuda_fp16.h>
#include <math.h>
#include <cstdint>

#define B_  2
#define S_  2048
#define D_  1024
#define H_  16
#define DH_ 64
#define QKDIM 2048
#define LOG2E 1.44269504f
#define NEGV2 (-1.44269504e9f)
#define LAMBDA_INIT 0.8f
#define EPS_ 1e-5f

// ---------------- scratch (device globals) ---------------------------------
__device__ float g_o1[(size_t)B_ * S_ * H_ * DH_];
__device__ float g_o2[(size_t)B_ * S_ * H_ * DH_];
__device__ float g_o [(size_t)B_ * S_ * H_ * DH_];
__device__ float g_lambda;
__device__ double g_sum[B_ * H_], g_sumsq[B_ * H_];

// fp16 buffers
__device__ __half g_xh2[(size_t)B_ * S_ * D_], g_xl2[(size_t)B_ * S_ * D_];
__device__ __half g_wq2[QKDIM * D_];
__device__ __half g_wk2[QKDIM * D_];
__device__ __half g_wv2[(H_ * DH_) * D_];
__device__ __half g_wo2[D_ * (H_ * DH_)];
__device__ __half g_qh2[(size_t)B_ * S_ * QKDIM], g_ql2[(size_t)B_ * S_ * QKDIM];
__device__ __half g_k2[(size_t)B_ * S_ * QKDIM];
__device__ __half g_v2[(size_t)B_ * S_ * H_ * DH_];
__device__ __half g_nh2[(size_t)B_ * S_ * H_ * DH_], g_nl2[(size_t)B_ * S_ * H_ * DH_];

// ---------------- helpers ---------------------------------------------------
__device__ __forceinline__ uint32_t smem_u32(const void* p) {
    uint32_t a;
    asm("{ .reg .u64 t; cvta.to.shared.u64 t, %1; cvt.u32.u64 %0, t; }" : "=r"(a) : "l"(p));
    return a;
}
__device__ __forceinline__ float fast_exp2(float x) {
    float r;
    asm("ex2.approx.ftz.f32 %0, %1;" : "=f"(r) : "f"(x));
    return r;
}
#define CP16(dst, src) \
    asm volatile("cp.async.cg.shared.global [%0], [%1], 16;" :: "r"(dst), "l"(src) : "memory")
#define CP_COMMIT() asm volatile("cp.async.commit_group;" ::: "memory")
#define CP_WAIT1()  asm volatile("cp.async.wait_group 1;" ::: "memory")
#define CP_WAIT0()  asm volatile("cp.async.wait_group 0;" ::: "memory")

__device__ __forceinline__ void ldsm_x4(uint32_t& r0, uint32_t& r1, uint32_t& r2, uint32_t& r3,
                                        uint32_t addr) {
    asm volatile("ldmatrix.sync.aligned.m8n8.x4.shared.b16 {%0,%1,%2,%3}, [%4];"
                 : "=r"(r0), "=r"(r1), "=r"(r2), "=r"(r3) : "r"(addr));
}
__device__ __forceinline__ void ldsm_x4t(uint32_t& r0, uint32_t& r1, uint32_t& r2, uint32_t& r3,
                                         uint32_t addr) {
    asm volatile("ldmatrix.sync.aligned.m8n8.x4.trans.shared.b16 {%0,%1,%2,%3}, [%4];"
                 : "=r"(r0), "=r"(r1), "=r"(r2), "=r"(r3) : "r"(addr));
}
#define MMAF16(d, a, b) \
    asm volatile("mma.sync.aligned.m16n8k16.row.col.f32.f16.f16.f32 " \
                 "{%0,%1,%2,%3}, {%4,%5,%6,%7}, {%8,%9}, {%0,%1,%2,%3};" \
                 : "+f"((d)[0]), "+f"((d)[1]), "+f"((d)[2]), "+f"((d)[3]) \
                 : "r"((a)[0]), "r"((a)[1]), "r"((a)[2]), "r"((a)[3]), \
                   "r"((b)[0]), "r"((b)[1]))

__device__ __forceinline__ uint32_t pack_h2(float lo, float hi) {
    __half2 t = __floats2half2_rn(lo, hi);
    return *(uint32_t*)&t;
}

// ---------------- lambda + zero stats ---------------------------------------
__global__ void lam_kernel(const float* __restrict__ lq1, const float* __restrict__ lq2,
                           const float* __restrict__ lk1, const float* __restrict__ lk2) {
    float d1 = 0.f, d2 = 0.f;
    for (int i = 0; i < DH_; i++) { d1 += lq1[i] * lk1[i]; d2 += lq2[i] * lk2[i]; }
    g_lambda = expf(d1) - expf(d2) + LAMBDA_INIT;
    for (int i = 0; i < B_ * H_; i++) { g_sum[i] = 0.0; g_sumsq[i] = 0.0; }
}

// ---------------- conversions ------------------------------------------------
#define N4_X  (B_ * S_ * D_ / 4)
#define N4_WQ (QKDIM * D_ / 4)
#define N4_WV (H_ * DH_ * D_ / 4)
#define N4_W_TOT (2 * N4_WQ + 2 * N4_WV)

__device__ __forceinline__ void split4h(const float* src, __half* h, __half* l, size_t i) {
    float4 v = ((const float4*)src)[i];
    float vv[4] = {v.x, v.y, v.z, v.w};
    __half hh[4], ll[4];
#pragma unroll
    for (int j = 0; j < 4; j++) {
        hh[j] = __float2half_rn(vv[j]);
        ll[j] = __float2half_rn(vv[j] - __half2float(hh[j]));
    }
    *(uint2*)&h[i * 4] = *(uint2*)hh;
    *(uint2*)&l[i * 4] = *(uint2*)ll;
}
__device__ __forceinline__ void cvt4h(const float* src, __half* h, size_t i) {
    float4 v = ((const float4*)src)[i];
    __half hh[4];
    hh[0] = __float2half_rn(v.x); hh[1] = __float2half_rn(v.y);
    hh[2] = __float2half_rn(v.z); hh[3] = __float2half_rn(v.w);
    *(uint2*)&h[i * 4] = *(uint2*)hh;
}

__global__ void __launch_bounds__(256) cvt_x(const float* __restrict__ x) {
    int i = blockIdx.x * 256 + threadIdx.x;
    if (i < N4_X) split4h(x, g_xh2, g_xl2, i);
}

__global__ void __launch_bounds__(256) cvt_w(
    const float* __restrict__ Wq, const float* __restrict__ Wk,
    const float* __restrict__ Wv, const float* __restrict__ Wo) {
    int i = blockIdx.x * 256 + threadIdx.x;
    if (i < N4_WQ) { cvt4h(Wq, g_wq2, i); return; }
    i -= N4_WQ;
    if (i < N4_WQ) { cvt4h(Wk, g_wk2, i); return; }
    i -= N4_WQ;
    if (i < N4_WV) { cvt4h(Wv, g_wv2, i); return; }
    i -= N4_WV;
    if (i < N4_WV) { cvt4h(Wo, g_wo2, i); return; }
}

// ---------------- GEMM loader / chunk (fp16 x2) ------------------------------
#define GSTAGE 32768
#define G_SMEM (3 * GSTAGE)

__device__ __forceinline__ void g_issue_h2(
    const __half* __restrict__ Ah, const __half* __restrict__ Al,
    const __half* __restrict__ B2,
    uint32_t sbuf, int tid, int bm, int bn, int K, int c) {
#pragma unroll
    for (int i = 0; i < 2; i++) {
        int ch = tid + i * 256;
        int p = ch >> 3, c16 = ch & 7;
        int r = (p << 1) + (c16 >> 2);
        int kb = (c16 & 3) * 8;
        int off = p * 128 + c16 * 16;
        uint32_t dst = sbuf + (off ^ ((off >> 3) & 0x70));
        size_t ga = (size_t)(bm + r) * K + c * 32 + kb;
        size_t gb = (size_t)(bn + r) * K + c * 32 + kb;
        CP16(dst,         Ah + ga);
        CP16(dst + 8192,  Al + ga);
        CP16(dst + 16384, B2 + gb);
    }
    CP_COMMIT();
}

__device__ __forceinline__ void g_chunk_h2(uint32_t sbuf, int wm, int wn, int g, int rl,
                                           float acc[2][8][4]) {
#pragma unroll
    for (int ks = 0; ks < 2; ks++) {
        uint32_t ah[2][4], al[2][4];
#pragma unroll
        for (int mb = 0; mb < 2; mb++) {
            int r = wm + mb * 16 + ((g & 1) << 3) + rl;
            int c16 = ((r & 1) << 2) + ks * 2 + (g >> 1);
            int off = (r >> 1) * 128 + c16 * 16;
            uint32_t sw = (uint32_t)(off ^ ((off >> 3) & 0x70));
            ldsm_x4(ah[mb][0], ah[mb][1], ah[mb][2], ah[mb][3], sbuf + sw);
            ldsm_x4(al[mb][0], al[mb][1], al[mb][2], al[mb][3], sbuf + 8192 + sw);
        }
        uint32_t bh[4][4];
#pragma unroll
        for (int np = 0; np < 4; np++) {
            int r = wn + np * 16 + ((g >> 1) << 3) + rl;
            int c16 = ((r & 1) << 2) + ks * 2 + (g & 1);
            int off = (r >> 1) * 128 + c16 * 16;
            uint32_t sw = (uint32_t)(off ^ ((off >> 3) & 0x70));
            ldsm_x4(bh[np][0], bh[np][1], bh[np][2], bh[np][3], sbuf + 16384 + sw);
        }
#pragma unroll
        for (int mb = 0; mb < 2; mb++)
#pragma unroll
            for (int j = 0; j < 8; j++) {
                MMAF16(acc[mb][j], ah[mb], &bh[j >> 1][(j & 1) * 2]);
                MMAF16(acc[mb][j], al[mb], &bh[j >> 1][(j & 1) * 2]);
            }
    }
}

// ---------------- fused QKV projection (fp16 x2 everywhere) ------------------
// grid (40, 32). nt<16: Q (out fp16 hi/lo), nt<32: K (out single), else V (single).
__global__ void __launch_bounds__(256, 2) gemm_qkv() {
    extern __shared__ char smem[];
    const uint32_t sbase = smem_u32(smem);
    const int tid = threadIdx.x, wid = tid >> 5, lane = tid & 31;
    const int nt = blockIdx.x;
    const int bm = blockIdx.y * 128;
    const int wm = (wid & 3) * 32;
    const int wn = (wid >> 2) * 64;
    const int g = lane >> 3, rl = lane & 7;
    const int K = D_;
    const int nch = K >> 5;

    const __half* B2;
    int N, bn, mode;   // mode 0: Q hi/lo, 1: K single, 2: V single
    if (nt < 16)      { B2 = g_wq2; N = QKDIM;    bn = nt * 128;        mode = 0; }
    else if (nt < 32) { B2 = g_wk2; N = QKDIM;    bn = (nt - 16) * 128; mode = 1; }
    else              { B2 = g_wv2; N = H_ * DH_; bn = (nt - 32) * 128; mode = 2; }

    float acc[2][8][4];
#pragma unroll
    for (int a = 0; a < 2; a++)
#pragma unroll
        for (int b = 0; b < 8; b++)
#pragma unroll
            for (int d = 0; d < 4; d++) acc[a][b][d] = 0.f;

    g_issue_h2(g_xh2, g_xl2, B2, sbase, tid, bm, bn, K, 0);
    g_issue_h2(g_xh2, g_xl2, B2, sbase + GSTAGE, tid, bm, bn, K, 1);
    for (int c = 0; c < nch; c++) {
        if (c + 1 < nch) { CP_WAIT1(); } else { CP_WAIT0(); }
        __syncthreads();
        if (c + 2 < nch)
            g_issue_h2(g_xh2, g_xl2, B2, sbase + (uint32_t)((c + 2) % 3) * GSTAGE, tid, bm, bn, K, c + 2);
        g_chunk_h2(sbase + (uint32_t)(c % 3) * GSTAGE, wm, wn, g, rl, acc);
    }

#pragma unroll
    for (int mb = 0; mb < 2; mb++) {
        int row0 = bm + wm + mb * 16 + (lane >> 2);
#pragma unroll
        for (int j = 0; j < 8; j++) {
            int col = bn + wn + j * 8 + (lane & 3) * 2;
#pragma unroll
            for (int rr = 0; rr < 2; rr++) {
                float v0 = acc[mb][j][rr * 2], v1 = acc[mb][j][rr * 2 + 1];
                size_t idx = (size_t)(row0 + rr * 8) * N + col;
                if (mode == 0) {
                    __half h0 = __float2half_rn(v0), h1 = __float2half_rn(v1);
                    __half2 hp; hp.x = h0; hp.y = h1;
                    __half2 lp;
                    lp.x = __float2half_rn(v0 - __half2float(h0));
                    lp.y = __float2half_rn(v1 - __half2float(h1));
                    *(__half2*)&g_qh2[idx] = hp;
                    *(__half2*)&g_ql2[idx] = lp;
                } else {
                    __half2 p = __floats2half2_rn(v0, v1);
                    if (mode == 1) *(__half2*)&g_k2[idx] = p;
                    else           *(__half2*)&g_v2[idx] = p;
                }
            }
        }
    }
}

// ---------------- output projection (fp16 x2, fp32 out) ----------------------
__global__ void __launch_bounds__(256, 2) gemm_o2(float* __restrict__ Cf) {
    extern __shared__ char smem[];
    const uint32_t sbase = smem_u32(smem);
    const int tid = threadIdx.x, wid = tid >> 5, lane = tid & 31;
    const int bm = blockIdx.y * 128, bn = blockIdx.x * 128;
    const int wm = (wid & 3) * 32;
    const int wn = (wid >> 2) * 64;
    const int g = lane >> 3, rl = lane & 7;
    const int K = H_ * DH_, N = D_;
    const int nch = K >> 5;

    float acc[2][8][4];
#pragma unroll
    for (int a = 0; a < 2; a++)
#pragma unroll
        for (int b = 0; b < 8; b++)
#pragma unroll
            for (int d = 0; d < 4; d++) acc[a][b][d] = 0.f;

    g_issue_h2(g_nh2, g_nl2, g_wo2, sbase, tid, bm, bn, K, 0);
    g_issue_h2(g_nh2, g_nl2, g_wo2, sbase + GSTAGE, tid, bm, bn, K, 1);
    for (int c = 0; c < nch; c++) {
        if (c + 1 < nch) { CP_WAIT1(); } else { CP_WAIT0(); }
        __syncthreads();
        if (c + 2 < nch)
            g_issue_h2(g_nh2, g_nl2, g_wo2, sbase + (uint32_t)((c + 2) % 3) * GSTAGE, tid, bm, bn, K, c + 2);
        g_chunk_h2(sbase + (uint32_t)(c % 3) * GSTAGE, wm, wn, g, rl, acc);
    }

#pragma unroll
    for (int mb = 0; mb < 2; mb++) {
        int row0 = bm + wm + mb * 16 + (lane >> 2);
#pragma unroll
        for (int j = 0; j < 8; j++) {
            int col = bn + wn + j * 8 + (lane & 3) * 2;
            *(float2*)&Cf[(size_t)row0 * N + col]       = make_float2(acc[mb][j][0], acc[mb][j][1]);
            *(float2*)&Cf[(size_t)(row0 + 8) * N + col] = make_float2(acc[mb][j][2], acc[mb][j][3]);
        }
    }
}

// ---------------- flash attention --------------------------------------------
// 4 warps, 64-q tiles. QK fp16 x2 (Q hi/lo, K single), PV fp16 x2 (P hi/lo, V single).
#define FK2  0
#define FV2  8192
#define FAM  16384
#define FSTG_SZ 16640
#define FQ_H (2 * FSTG_SZ)
#define FQ_L (2 * FSTG_SZ + 8192)
#define FL_SMEM (3 * FSTG_SZ)   // 49920 (Q 16KB overlays stage 2's 16.6KB)

__device__ __forceinline__ void f_issue_stage(uint32_t stg, int tid, int b, int h, int comp,
                                              int kt, const float* __restrict__ amask) {
    const char* Kg = (const char*)(g_k2 + ((size_t)(b * S_) + kt * 64) * QKDIM + h * 128 + comp * 64);
    const char* Vg = (const char*)(g_v2 + ((size_t)(b * S_) + kt * 64) * (H_ * DH_) + h * 64);
#pragma unroll
    for (int i = 0; i < 4; i++) {
        int t = tid + i * 128;
        int row = t >> 3, gr = t & 7;
        int off = row * 128 + gr * 16;
        uint32_t sw = (uint32_t)(off ^ ((off >> 3) & 0x70));
        CP16(stg + FK2 + sw, Kg + (size_t)row * (QKDIM * 2) + gr * 16);
        CP16(stg + FV2 + sw, Vg + (size_t)row * (H_ * DH_ * 2) + gr * 16);
    }
    if (tid < 16)
        CP16(stg + FAM + tid * 16, amask + b * S_ + kt * 64 + tid * 4);
    CP_COMMIT();
}

__global__ void __launch_bounds__(128) flashmma_kernel(const float* __restrict__ amask) {
    extern __shared__ char fsm[];
    const uint32_t sb = smem_u32(fsm);
    const int tid = threadIdx.x, wid = tid >> 5, lane = tid & 31;
    const int g = lane >> 3, rl = lane & 7;
    const int qt = (gridDim.x - 1) - blockIdx.x;
    const int z = blockIdx.y;
    const int comp = z & 1;
    const int bh = z >> 1;
    const int b = bh / H_, h = bh % H_;
    const float slope2 = exp2f(-8.0f * (float)(h + 1) / (float)H_) * LOG2E;
    const float scale2 = 0.125f * LOG2E;
    const int nkt = qt + 1;

    {
        const char* Qhg = (const char*)(g_qh2 + ((size_t)(b * S_) + qt * 64) * QKDIM + h * 128 + comp * 64);
        const char* Qlg = (const char*)(g_ql2 + ((size_t)(b * S_) + qt * 64) * QKDIM + h * 128 + comp * 64);
#pragma unroll
        for (int i = 0; i < 4; i++) {
            int t = tid + i * 128;
            int row = t >> 3, gr = t & 7;
            int off = row * 128 + gr * 16;
            uint32_t sw = (uint32_t)(off ^ ((off >> 3) & 0x70));
            CP16(sb + FQ_H + sw, Qhg + (size_t)row * (QKDIM * 2) + gr * 16);
            CP16(sb + FQ_L + sw, Qlg + (size_t)row * (QKDIM * 2) + gr * 16);
        }
    }
    f_issue_stage(sb, tid, b, h, comp, qt, amask);
    if (nkt > 1) f_issue_stage(sb + FSTG_SZ, tid, b, h, comp, qt - 1, amask);

    float oa[8][4];
#pragma unroll
    for (int j = 0; j < 8; j++)
#pragma unroll
        for (int d = 0; d < 4; d++) oa[j][d] = 0.f;
    float m0 = -1e30f, m1 = -1e30f, l0 = 0.f, l1 = 0.f;
    uint32_t qAh[4][4], qAl[4][4];

    const int qr0 = qt * 64 + wid * 16 + (lane >> 2);
    const float d8 = -8.0f * slope2;

    float cst0[8], cst1[8];
#pragma unroll
    for (int nb = 0; nb < 8; nb++) {
        cst0[nb] = slope2 * (float)(nb * 8 + (lane & 3) * 2);
        cst1[nb] = cst0[nb] + slope2;
    }
    float base0 = -slope2 * (float)(wid * 16 + (lane >> 2));
    const float base_step = 64.0f * slope2;

    for (int it = 0; it < nkt; it++) {
        const int ktile = qt - it;
        if (it + 1 < nkt) { CP_WAIT1(); } else { CP_WAIT0(); }
        __syncthreads();
        if (it == 0) {
#pragma unroll
            for (int kb = 0; kb < 4; kb++) {
                int row = wid * 16 + ((g & 1) << 3) + rl;
                int gr = kb * 2 + (g >> 1);
                int off = row * 128 + gr * 16;
                uint32_t sw = (uint32_t)(off ^ ((off >> 3) & 0x70));
                ldsm_x4(qAh[kb][0], qAh[kb][1], qAh[kb][2], qAh[kb][3], sb + FQ_H + sw);
                ldsm_x4(qAl[kb][0], qAl[kb][1], qAl[kb][2], qAl[kb][3], sb + FQ_L + sw);
            }
            if (nkt > 2) __syncthreads();
        }
        if (it + 2 < nkt)
            f_issue_stage(sb + (uint32_t)((it + 2) % 3) * FSTG_SZ, tid, b, h, comp, qt - (it + 2), amask);
        uint32_t stg = sb + (uint32_t)(it % 3) * FSTG_SZ;

        // ---- S = Q K^T (fp16 x2: Q hi/lo x K single) ----
        float sa[8][4];
#pragma unroll
        for (int j = 0; j < 8; j++)
#pragma unroll
            for (int d = 0; d < 4; d++) sa[j][d] = 0.f;
#pragma unroll
        for (int kb = 0; kb < 4; kb++) {
#pragma unroll
            for (int nb2 = 0; nb2 < 4; nb2++) {
                uint32_t kh4[4];
                int row = nb2 * 16 + ((g >> 1) << 3) + rl;
                int gr = kb * 2 + (g & 1);
                int off = row * 128 + gr * 16;
                uint32_t sw = (uint32_t)(off ^ ((off >> 3) & 0x70));
                ldsm_x4(kh4[0], kh4[1], kh4[2], kh4[3], stg + FK2 + sw);
                MMAF16(sa[nb2 * 2], qAh[kb], &kh4[0]);
                MMAF16(sa[nb2 * 2], qAl[kb], &kh4[0]);
                MMAF16(sa[nb2 * 2 + 1], qAh[kb], &kh4[2]);
                MMAF16(sa[nb2 * 2 + 1], qAl[kb], &kh4[2]);
            }
        }

        // ---- bias + masks (base-2 domain) ----
        const float* ams = (const float*)(fsm + (stg - sb) + FAM);
        float colc[8][2];
#pragma unroll
        for (int nb = 0; nb < 8; nb++) {
            int kc = nb * 8 + (lane & 3) * 2;
            colc[nb][0] = fmaf(1.0f - ams[kc],     NEGV2, base0 + cst0[nb]);
            colc[nb][1] = fmaf(1.0f - ams[kc + 1], NEGV2, base0 + cst1[nb]);
        }
#pragma unroll
        for (int nb = 0; nb < 8; nb++) {
            sa[nb][0] = fmaf(sa[nb][0], scale2, colc[nb][0]);
            sa[nb][1] = fmaf(sa[nb][1], scale2, colc[nb][1]);
            sa[nb][2] = fmaf(sa[nb][2], scale2, colc[nb][0] + d8);
            sa[nb][3] = fmaf(sa[nb][3], scale2, colc[nb][1] + d8);
        }
        if (it == 0) {
            const int kcb = ktile * 64;
#pragma unroll
            for (int nb = 0; nb < 8; nb++) {
                int k0 = kcb + nb * 8 + (lane & 3) * 2;
                if (k0 > qr0)         sa[nb][0] += NEGV2;
                if (k0 + 1 > qr0)     sa[nb][1] += NEGV2;
                if (k0 > qr0 + 8)     sa[nb][2] += NEGV2;
                if (k0 + 1 > qr0 + 8) sa[nb][3] += NEGV2;
            }
        }
        base0 -= base_step;

        // ---- online softmax (base 2; l lane-local) ----
        float mx0 = -1e30f, mx1 = -1e30f;
#pragma unroll
        for (int nb = 0; nb < 8; nb++) {
            mx0 = fmaxf(mx0, fmaxf(sa[nb][0], sa[nb][1]));
            mx1 = fmaxf(mx1, fmaxf(sa[nb][2], sa[nb][3]));
        }
        mx0 = fmaxf(mx0, __shfl_xor_sync(0xffffffffu, mx0, 1));
        mx0 = fmaxf(mx0, __shfl_xor_sync(0xffffffffu, mx0, 2));
        mx1 = fmaxf(mx1, __shfl_xor_sync(0xffffffffu, mx1, 1));
        mx1 = fmaxf(mx1, __shfl_xor_sync(0xffffffffu, mx1, 2));
        float mn0 = fmaxf(m0, mx0), mn1 = fmaxf(m1, mx1);
        float al0 = fast_exp2(m0 - mn0), al1 = fast_exp2(m1 - mn1);
        m0 = mn0; m1 = mn1;
        float ls0 = 0.f, ls1 = 0.f;
#pragma unroll
        for (int nb = 0; nb < 8; nb++) {
            sa[nb][0] = fast_exp2(sa[nb][0] - mn0);
            sa[nb][1] = fast_exp2(sa[nb][1] - mn0);
            sa[nb][2] = fast_exp2(sa[nb][2] - mn1);
            sa[nb][3] = fast_exp2(sa[nb][3] - mn1);
            ls0 += sa[nb][0] + sa[nb][1];
            ls1 += sa[nb][2] + sa[nb][3];
        }
        l0 = l0 * al0 + ls0;
        l1 = l1 * al1 + ls1;

        bool noresc = __all_sync(0xffffffffu, (al0 == 1.0f) && (al1 == 1.0f));
        if (!noresc) {
#pragma unroll
            for (int j = 0; j < 8; j++) {
                oa[j][0] *= al0; oa[j][1] *= al0;
                oa[j][2] *= al1; oa[j][3] *= al1;
            }
        }

        // ---- O += P V (fp16 x2: P hi/lo, V single) ----
#pragma unroll
        for (int kb2 = 0; kb2 < 4; kb2++) {
            uint32_t pAh[4], pAl[4];
#pragma unroll
            for (int half = 0; half < 2; half++) {
                float v0a = sa[kb2 * 2][half * 2], v1a = sa[kb2 * 2][half * 2 + 1];
                float v0b = sa[kb2 * 2 + 1][half * 2], v1b = sa[kb2 * 2 + 1][half * 2 + 1];
                __half h0a = __float2half_rn(v0a), h1a = __float2half_rn(v1a);
                __half h0b = __float2half_rn(v0b), h1b = __float2half_rn(v1b);
                pAh[half]     = pack_h2(__half2float(h0a), __half2float(h1a));
                pAh[2 + half] = pack_h2(__half2float(h0b), __half2float(h1b));
                pAl[half]     = pack_h2(v0a - __half2float(h0a), v1a - __half2float(h1a));
                pAl[2 + half] = pack_h2(v0b - __half2float(h0b), v1b - __half2float(h1b));
            }
#pragma unroll
            for (int db = 0; db < 4; db++) {
                uint32_t vh4[4];
                int row = kb2 * 16 + ((g & 1) << 3) + rl;
                int gr = db * 2 + (g >> 1);
                int off = row * 128 + gr * 16;
                uint32_t sw = (uint32_t)(off ^ ((off >> 3) & 0x70));
                ldsm_x4t(vh4[0], vh4[1], vh4[2], vh4[3], stg + FV2 + sw);
                MMAF16(oa[db * 2], pAh, &vh4[0]);
                MMAF16(oa[db * 2], pAl, &vh4[0]);
                MMAF16(oa[db * 2 + 1], pAh, &vh4[2]);
                MMAF16(oa[db * 2 + 1], pAl, &vh4[2]);
            }
        }
    }

    l0 += __shfl_xor_sync(0xffffffffu, l0, 1);
    l0 += __shfl_xor_sync(0xffffffffu, l0, 2);
    l1 += __shfl_xor_sync(0xffffffffu, l1, 1);
    l1 += __shfl_xor_sync(0xffffffffu, l1, 2);
    float inv0 = 1.0f / l0, inv1 = 1.0f / l1;
    float* Og = (comp ? g_o2 : g_o1) + ((size_t)(b * S_) + qr0) * (H_ * DH_) + h * 64;
#pragma unroll
    for (int j = 0; j < 8; j++) {
        int col = j * 8 + (lane & 3) * 2;
        *(float2*)&Og[col] = make_float2(oa[j][0] * inv0, oa[j][1] * inv0);
        *(float2*)&Og[(size_t)8 * (H_ * DH_) + col] = make_float2(oa[j][2] * inv1, oa[j][3] * inv1);
    }
}

// ---------------- combine + groupnorm stats ---------------------------------
__global__ void __launch_bounds__(256) combine_stats_kernel() {
    const int bh = blockIdx.x >> 3;
    const int slice = blockIdx.x & 7;
    const int b = bh / H_, h = bh % H_;
    const float lam = g_lambda;
    double s = 0.0, ss = 0.0;
    const int base_row = b * S_ + slice * 256;
    for (int f = threadIdx.x; f < 256 * (DH_ / 4); f += 256) {
        int row = f >> 4, c = (f & 15) * 4;
        size_t e = (size_t)(base_row + row) * (H_ * DH_) + h * DH_ + c;
        float4 a = *(const float4*)&g_o1[e];
        float4 cc = *(const float4*)&g_o2[e];
        float4 y;
        y.x = a.x - lam * cc.x; y.y = a.y - lam * cc.y;
        y.z = a.z - lam * cc.z; y.w = a.w - lam * cc.w;
        *(float4*)&g_o[e] = y;
        s += (double)y.x + y.y + y.z + y.w;
        ss += (double)y.x * y.x + (double)y.y * y.y + (double)y.z * y.z + (double)y.w * y.w;
    }
    __shared__ double sh_s[256], sh_ss[256];
    sh_s[threadIdx.x] = s; sh_ss[threadIdx.x] = ss;
    __syncthreads();
    for (int st = 128; st > 0; st >>= 1) {
        if (threadIdx.x < st) {
            sh_s[threadIdx.x] += sh_s[threadIdx.x + st];
            sh_ss[threadIdx.x] += sh_ss[threadIdx.x + st];
        }
        __syncthreads();
    }
    if (threadIdx.x == 0) {
        atomicAdd(&g_sum[bh], sh_s[0]);
        atomicAdd(&g_sumsq[bh], sh_ss[0]);
    }
}

// ---------------- normalize + emit fp16 hi/lo --------------------------------
__global__ void __launch_bounds__(256) gn_apply_kernel(const float* __restrict__ gamma,
                                                       const float* __restrict__ beta) {
    int f = blockIdx.x * blockDim.x + threadIdx.x;
    if (f >= (B_ * S_ * H_ * DH_) / 4) return;
    int e = f * 4;
    int c = e % (H_ * DH_);
    int row = e / (H_ * DH_);
    int b = row / S_;
    int h = c / DH_;
    const double n = (double)S_ * DH_;
    double sm = g_sum[b * H_ + h], sq = g_sumsq[b * H_ + h];
    double meand = sm / n;
    float mean = (float)meand;
    float inv = rsqrtf((float)(sq / n - meand * meand) + EPS_);
    float4 x = *(const float4*)&g_o[e];
    float4 gm = *(const float4*)&gamma[c];
    float4 bt = *(const float4*)&beta[c];
    const float post = 1.0f - LAMBDA_INIT;
    float y[4];
    y[0] = ((x.x - mean) * inv * gm.x + bt.x) * post;
    y[1] = ((x.y - mean) * inv * gm.y + bt.y) * post;
    y[2] = ((x.z - mean) * inv * gm.z + bt.z) * post;
    y[3] = ((x.w - mean) * inv * gm.w + bt.w) * post;
    __half hh[4], ll[4];
#pragma unroll
    for (int j = 0; j < 4; j++) {
        hh[j] = __float2half_rn(y[j]);
        ll[j] = __float2half_rn(y[j] - __half2float(hh[j]));
    }
    *(uint2*)&g_nh2[e] = *(uint2*)hh;
    *(uint2*)&g_nl2[e] = *(uint2*)ll;
}

// ---------------- launch ----------------------------------------------------
extern "C" void kernel_launch(void* const* d_in, const int* in_sizes, int n_in,
                              void* d_out, int out_size) {
    const float* x     = (const float*)d_in[0];
    const float* amask = (const float*)d_in[1];
    const float* Wq = (const float*)d_in[3];
    const float* Wk = (const float*)d_in[4];
    const float* Wv = (const float*)d_in[5];
    const float* Wo = (const float*)d_in[6];
    const float* lq1 = (const float*)d_in[7];
    const float* lq2 = (const float*)d_in[8];
    const float* lk1 = (const float*)d_in[9];
    const float* lk2 = (const float*)d_in[10];
    const float* gam = (const float*)d_in[11];
    const float* bet = (const float*)d_in[12];
    float* out = (float*)d_out;

    const int M = B_ * S_;  // 4096

    // 0: lambda + zero stats
    lam_kernel<<<1, 1>>>(lq1, lq2, lk1, lk2);
    // 1: x fp16 hi/lo split
    cvt_x<<<(N4_X + 255) / 256, 256>>>(x);
    // 2: weight fp16 conversions
    cvt_w<<<(N4_W_TOT + 255) / 256, 256>>>(Wq, Wk, Wv, Wo);
    // 3: fused QKV projection (profiled)
    cudaFuncSetAttribute(gemm_qkv, cudaFuncAttributeMaxDynamicSharedMemorySize, G_SMEM);
    gemm_qkv<<<dim3(40, M / 128), 256, G_SMEM>>>();
    // 4: flash attention
    cudaFuncSetAttribute(flashmma_kernel, cudaFuncAttributeMaxDynamicSharedMemorySize, FL_SMEM);
    flashmma_kernel<<<dim3(S_ / 64, B_ * H_ * 2), 128, FL_SMEM>>>(amask);
    // 5: combine + stats
    combine_stats_kernel<<<B_ * H_ * 8, 256>>>();
    // 6: normalize + fp16 split
    gn_apply_kernel<<<(B_ * S_ * H_ * DH_ / 4 + 255) / 256, 256>>>(gam, bet);
    // 7: output projection
    cudaFuncSetAttribute(gemm_o2, cudaFuncAttributeMaxDynamicSharedMemorySize, G_SMEM);
    gemm_o2<<<dim3(D_ / 128, M / 128), 256, G_SMEM>>>(out);
}

// round 15
// speedup vs baseline: 1.5000x; 1.0791x over previous
#include <cuda_runtime.h>
#include <cuda_fp16.h>
#include <math.h>
#include <cstdint>

#define B_  2
#define S_  2048
#define D_  1024
#define H_  16
#define DH_ 64
#define QKDIM 2048
#define LOG2E 1.44269504f
#define NEGV2 (-1.44269504e9f)
#define LAMBDA_INIT 0.8f
#define EPS_ 1e-5f

// ---------------- scratch (device globals) ---------------------------------
__device__ float g_o1[(size_t)B_ * S_ * H_ * DH_];
__device__ float g_o2[(size_t)B_ * S_ * H_ * DH_];
__device__ float g_o [(size_t)B_ * S_ * H_ * DH_];
__device__ float g_lambda;
__device__ double g_sum[B_ * H_], g_sumsq[B_ * H_];

// fp16 buffers
__device__ __half g_xh2[(size_t)B_ * S_ * D_], g_xl2[(size_t)B_ * S_ * D_];
__device__ __half g_wq2[QKDIM * D_];
__device__ __half g_wk2[QKDIM * D_];
__device__ __half g_wv2[(H_ * DH_) * D_];
__device__ __half g_wo2[D_ * (H_ * DH_)];
__device__ __half g_q2[(size_t)B_ * S_ * QKDIM];
__device__ __half g_k2[(size_t)B_ * S_ * QKDIM];
__device__ __half g_v2[(size_t)B_ * S_ * H_ * DH_];
__device__ __half g_nh2[(size_t)B_ * S_ * H_ * DH_], g_nl2[(size_t)B_ * S_ * H_ * DH_];

// ---------------- helpers ---------------------------------------------------
__device__ __forceinline__ uint32_t smem_u32(const void* p) {
    uint32_t a;
    asm("{ .reg .u64 t; cvta.to.shared.u64 t, %1; cvt.u32.u64 %0, t; }" : "=r"(a) : "l"(p));
    return a;
}
__device__ __forceinline__ float fast_exp2(float x) {
    float r;
    asm("ex2.approx.ftz.f32 %0, %1;" : "=f"(r) : "f"(x));
    return r;
}
#define CP16(dst, src) \
    asm volatile("cp.async.cg.shared.global [%0], [%1], 16;" :: "r"(dst), "l"(src) : "memory")
#define CP_COMMIT() asm volatile("cp.async.commit_group;" ::: "memory")
#define CP_WAIT1()  asm volatile("cp.async.wait_group 1;" ::: "memory")
#define CP_WAIT0()  asm volatile("cp.async.wait_group 0;" ::: "memory")

__device__ __forceinline__ void ldsm_x4(uint32_t& r0, uint32_t& r1, uint32_t& r2, uint32_t& r3,
                                        uint32_t addr) {
    asm volatile("ldmatrix.sync.aligned.m8n8.x4.shared.b16 {%0,%1,%2,%3}, [%4];"
                 : "=r"(r0), "=r"(r1), "=r"(r2), "=r"(r3) : "r"(addr));
}
__device__ __forceinline__ void ldsm_x4t(uint32_t& r0, uint32_t& r1, uint32_t& r2, uint32_t& r3,
                                         uint32_t addr) {
    asm volatile("ldmatrix.sync.aligned.m8n8.x4.trans.shared.b16 {%0,%1,%2,%3}, [%4];"
                 : "=r"(r0), "=r"(r1), "=r"(r2), "=r"(r3) : "r"(addr));
}
#define MMAF16(d, a, b) \
    asm volatile("mma.sync.aligned.m16n8k16.row.col.f32.f16.f16.f32 " \
                 "{%0,%1,%2,%3}, {%4,%5,%6,%7}, {%8,%9}, {%0,%1,%2,%3};" \
                 : "+f"((d)[0]), "+f"((d)[1]), "+f"((d)[2]), "+f"((d)[3]) \
                 : "r"((a)[0]), "r"((a)[1]), "r"((a)[2]), "r"((a)[3]), \
                   "r"((b)[0]), "r"((b)[1]))

__device__ __forceinline__ uint32_t pack_h2(float lo, float hi) {
    __half2 t = __floats2half2_rn(lo, hi);
    return *(uint32_t*)&t;
}

// ---------------- lambda + zero stats ---------------------------------------
__global__ void lam_kernel(const float* __restrict__ lq1, const float* __restrict__ lq2,
                           const float* __restrict__ lk1, const float* __restrict__ lk2) {
    float d1 = 0.f, d2 = 0.f;
    for (int i = 0; i < DH_; i++) { d1 += lq1[i] * lk1[i]; d2 += lq2[i] * lk2[i]; }
    g_lambda = expf(d1) - expf(d2) + LAMBDA_INIT;
    for (int i = 0; i < B_ * H_; i++) { g_sum[i] = 0.0; g_sumsq[i] = 0.0; }
}

// ---------------- conversions ------------------------------------------------
#define N4_X  (B_ * S_ * D_ / 4)
#define N4_WQ (QKDIM * D_ / 4)
#define N4_WV (H_ * DH_ * D_ / 4)
#define N4_TOT (N4_X + 2 * N4_WQ + 2 * N4_WV)

__device__ __forceinline__ void split4h(const float* src, __half* h, __half* l, size_t i) {
    float4 v = ((const float4*)src)[i];
    float vv[4] = {v.x, v.y, v.z, v.w};
    __half hh[4], ll[4];
#pragma unroll
    for (int j = 0; j < 4; j++) {
        hh[j] = __float2half_rn(vv[j]);
        ll[j] = __float2half_rn(vv[j] - __half2float(hh[j]));
    }
    *(uint2*)&h[i * 4] = *(uint2*)hh;
    *(uint2*)&l[i * 4] = *(uint2*)ll;
}
__device__ __forceinline__ void cvt4h(const float* src, __half* h, size_t i) {
    float4 v = ((const float4*)src)[i];
    __half hh[4];
    hh[0] = __float2half_rn(v.x); hh[1] = __float2half_rn(v.y);
    hh[2] = __float2half_rn(v.z); hh[3] = __float2half_rn(v.w);
    *(uint2*)&h[i * 4] = *(uint2*)hh;
}

__global__ void __launch_bounds__(256) cvt_all(
    const float* __restrict__ x,  const float* __restrict__ Wq,
    const float* __restrict__ Wk, const float* __restrict__ Wv,
    const float* __restrict__ Wo) {
    int i = blockIdx.x * 256 + threadIdx.x;
    if (i < N4_X) { split4h(x, g_xh2, g_xl2, i); return; }
    i -= N4_X;
    if (i < N4_WQ) { cvt4h(Wq, g_wq2, i); return; }
    i -= N4_WQ;
    if (i < N4_WQ) { cvt4h(Wk, g_wk2, i); return; }
    i -= N4_WQ;
    if (i < N4_WV) { cvt4h(Wv, g_wv2, i); return; }
    i -= N4_WV;
    if (i < N4_WV) { cvt4h(Wo, g_wo2, i); return; }
}

// ---------------- GEMM loader / chunk (fp16 x2) ------------------------------
#define GSTAGE 32768
#define G_SMEM (3 * GSTAGE)

__device__ __forceinline__ void g_issue_h2(
    const __half* __restrict__ Ah, const __half* __restrict__ Al,
    const __half* __restrict__ B2,
    uint32_t sbuf, int tid, int bm, int bn, int K, int c) {
#pragma unroll
    for (int i = 0; i < 2; i++) {
        int ch = tid + i * 256;
        int p = ch >> 3, c16 = ch & 7;
        int r = (p << 1) + (c16 >> 2);
        int kb = (c16 & 3) * 8;
        int off = p * 128 + c16 * 16;
        uint32_t dst = sbuf + (off ^ ((off >> 3) & 0x70));
        size_t ga = (size_t)(bm + r) * K + c * 32 + kb;
        size_t gb = (size_t)(bn + r) * K + c * 32 + kb;
        CP16(dst,         Ah + ga);
        CP16(dst + 8192,  Al + ga);
        CP16(dst + 16384, B2 + gb);
    }
    CP_COMMIT();
}

__device__ __forceinline__ void g_chunk_h2(uint32_t sbuf, int wm, int wn, int g, int rl,
                                           float acc[2][8][4]) {
#pragma unroll
    for (int ks = 0; ks < 2; ks++) {
        uint32_t ah[2][4], al[2][4];
#pragma unroll
        for (int mb = 0; mb < 2; mb++) {
            int r = wm + mb * 16 + ((g & 1) << 3) + rl;
            int c16 = ((r & 1) << 2) + ks * 2 + (g >> 1);
            int off = (r >> 1) * 128 + c16 * 16;
            uint32_t sw = (uint32_t)(off ^ ((off >> 3) & 0x70));
            ldsm_x4(ah[mb][0], ah[mb][1], ah[mb][2], ah[mb][3], sbuf + sw);
            ldsm_x4(al[mb][0], al[mb][1], al[mb][2], al[mb][3], sbuf + 8192 + sw);
        }
        uint32_t bh[4][4];
#pragma unroll
        for (int np = 0; np < 4; np++) {
            int r = wn + np * 16 + ((g >> 1) << 3) + rl;
            int c16 = ((r & 1) << 2) + ks * 2 + (g & 1);
            int off = (r >> 1) * 128 + c16 * 16;
            uint32_t sw = (uint32_t)(off ^ ((off >> 3) & 0x70));
            ldsm_x4(bh[np][0], bh[np][1], bh[np][2], bh[np][3], sbuf + 16384 + sw);
        }
#pragma unroll
        for (int mb = 0; mb < 2; mb++)
#pragma unroll
            for (int j = 0; j < 8; j++) {
                MMAF16(acc[mb][j], ah[mb], &bh[j >> 1][(j & 1) * 2]);
                MMAF16(acc[mb][j], al[mb], &bh[j >> 1][(j & 1) * 2]);
            }
    }
}

// ---------------- fused QKV projection (fp16 x2; all outputs single fp16) ----
__global__ void __launch_bounds__(256, 2) gemm_qkv() {
    extern __shared__ char smem[];
    const uint32_t sbase = smem_u32(smem);
    const int tid = threadIdx.x, wid = tid >> 5, lane = tid & 31;
    const int nt = blockIdx.x;
    const int bm = blockIdx.y * 128;
    const int wm = (wid & 3) * 32;
    const int wn = (wid >> 2) * 64;
    const int g = lane >> 3, rl = lane & 7;
    const int K = D_;
    const int nch = K >> 5;

    const __half* B2;
    __half* O2;
    int N, bn;
    if (nt < 16)      { B2 = g_wq2; O2 = g_q2; N = QKDIM;    bn = nt * 128; }
    else if (nt < 32) { B2 = g_wk2; O2 = g_k2; N = QKDIM;    bn = (nt - 16) * 128; }
    else              { B2 = g_wv2; O2 = g_v2; N = H_ * DH_; bn = (nt - 32) * 128; }

    float acc[2][8][4];
#pragma unroll
    for (int a = 0; a < 2; a++)
#pragma unroll
        for (int b = 0; b < 8; b++)
#pragma unroll
            for (int d = 0; d < 4; d++) acc[a][b][d] = 0.f;

    g_issue_h2(g_xh2, g_xl2, B2, sbase, tid, bm, bn, K, 0);
    g_issue_h2(g_xh2, g_xl2, B2, sbase + GSTAGE, tid, bm, bn, K, 1);
    for (int c = 0; c < nch; c++) {
        if (c + 1 < nch) { CP_WAIT1(); } else { CP_WAIT0(); }
        __syncthreads();
        if (c + 2 < nch)
            g_issue_h2(g_xh2, g_xl2, B2, sbase + (uint32_t)((c + 2) % 3) * GSTAGE, tid, bm, bn, K, c + 2);
        g_chunk_h2(sbase + (uint32_t)(c % 3) * GSTAGE, wm, wn, g, rl, acc);
    }

#pragma unroll
    for (int mb = 0; mb < 2; mb++) {
        int row0 = bm + wm + mb * 16 + (lane >> 2);
#pragma unroll
        for (int j = 0; j < 8; j++) {
            int col = bn + wn + j * 8 + (lane & 3) * 2;
#pragma unroll
            for (int rr = 0; rr < 2; rr++) {
                __half2 p = __floats2half2_rn(acc[mb][j][rr * 2], acc[mb][j][rr * 2 + 1]);
                *(__half2*)&O2[(size_t)(row0 + rr * 8) * N + col] = p;
            }
        }
    }
}

// ---------------- output projection (fp16 x2, fp32 out) ----------------------
__global__ void __launch_bounds__(256, 2) gemm_o2(float* __restrict__ Cf) {
    extern __shared__ char smem[];
    const uint32_t sbase = smem_u32(smem);
    const int tid = threadIdx.x, wid = tid >> 5, lane = tid & 31;
    const int bm = blockIdx.y * 128, bn = blockIdx.x * 128;
    const int wm = (wid & 3) * 32;
    const int wn = (wid >> 2) * 64;
    const int g = lane >> 3, rl = lane & 7;
    const int K = H_ * DH_, N = D_;
    const int nch = K >> 5;

    float acc[2][8][4];
#pragma unroll
    for (int a = 0; a < 2; a++)
#pragma unroll
        for (int b = 0; b < 8; b++)
#pragma unroll
            for (int d = 0; d < 4; d++) acc[a][b][d] = 0.f;

    g_issue_h2(g_nh2, g_nl2, g_wo2, sbase, tid, bm, bn, K, 0);
    g_issue_h2(g_nh2, g_nl2, g_wo2, sbase + GSTAGE, tid, bm, bn, K, 1);
    for (int c = 0; c < nch; c++) {
        if (c + 1 < nch) { CP_WAIT1(); } else { CP_WAIT0(); }
        __syncthreads();
        if (c + 2 < nch)
            g_issue_h2(g_nh2, g_nl2, g_wo2, sbase + (uint32_t)((c + 2) % 3) * GSTAGE, tid, bm, bn, K, c + 2);
        g_chunk_h2(sbase + (uint32_t)(c % 3) * GSTAGE, wm, wn, g, rl, acc);
    }

#pragma unroll
    for (int mb = 0; mb < 2; mb++) {
        int row0 = bm + wm + mb * 16 + (lane >> 2);
#pragma unroll
        for (int j = 0; j < 8; j++) {
            int col = bn + wn + j * 8 + (lane & 3) * 2;
            *(float2*)&Cf[(size_t)row0 * N + col]       = make_float2(acc[mb][j][0], acc[mb][j][1]);
            *(float2*)&Cf[(size_t)(row0 + 8) * N + col] = make_float2(acc[mb][j][2], acc[mb][j][3]);
        }
    }
}

// ---------------- flash attention --------------------------------------------
// 4 warps, 64-q tiles. QK single x single fp16; PV fp16 x2 (P hi/lo, V single).
#define FK2  0
#define FV2  8192
#define FAM  16384
#define FSTG_SZ 16640
#define FQ2 (2 * FSTG_SZ)
#define FL_SMEM (3 * FSTG_SZ)   // 49920 (Q 8KB overlays stage 2)

__device__ __forceinline__ void f_issue_stage(uint32_t stg, int tid, int b, int h, int comp,
                                              int kt, const float* __restrict__ amask) {
    const char* Kg = (const char*)(g_k2 + ((size_t)(b * S_) + kt * 64) * QKDIM + h * 128 + comp * 64);
    const char* Vg = (const char*)(g_v2 + ((size_t)(b * S_) + kt * 64) * (H_ * DH_) + h * 64);
#pragma unroll
    for (int i = 0; i < 4; i++) {
        int t = tid + i * 128;
        int row = t >> 3, gr = t & 7;
        int off = row * 128 + gr * 16;
        uint32_t sw = (uint32_t)(off ^ ((off >> 3) & 0x70));
        CP16(stg + FK2 + sw, Kg + (size_t)row * (QKDIM * 2) + gr * 16);
        CP16(stg + FV2 + sw, Vg + (size_t)row * (H_ * DH_ * 2) + gr * 16);
    }
    if (tid < 16)
        CP16(stg + FAM + tid * 16, amask + b * S_ + kt * 64 + tid * 4);
    CP_COMMIT();
}

__global__ void __launch_bounds__(128) flashmma_kernel(const float* __restrict__ amask) {
    extern __shared__ char fsm[];
    const uint32_t sb = smem_u32(fsm);
    const int tid = threadIdx.x, wid = tid >> 5, lane = tid & 31;
    const int g = lane >> 3, rl = lane & 7;
    const int qt = (gridDim.x - 1) - blockIdx.x;
    const int z = blockIdx.y;
    const int comp = z & 1;
    const int bh = z >> 1;
    const int b = bh / H_, h = bh % H_;
    const float slope2 = exp2f(-8.0f * (float)(h + 1) / (float)H_) * LOG2E;
    const float scale2 = 0.125f * LOG2E;
    const int nkt = qt + 1;

    {
        const char* Qg = (const char*)(g_q2 + ((size_t)(b * S_) + qt * 64) * QKDIM + h * 128 + comp * 64);
#pragma unroll
        for (int i = 0; i < 4; i++) {
            int t = tid + i * 128;
            int row = t >> 3, gr = t & 7;
            int off = row * 128 + gr * 16;
            uint32_t sw = (uint32_t)(off ^ ((off >> 3) & 0x70));
            CP16(sb + FQ2 + sw, Qg + (size_t)row * (QKDIM * 2) + gr * 16);
        }
    }
    f_issue_stage(sb, tid, b, h, comp, qt, amask);
    if (nkt > 1) f_issue_stage(sb + FSTG_SZ, tid, b, h, comp, qt - 1, amask);

    float oa[8][4];
#pragma unroll
    for (int j = 0; j < 8; j++)
#pragma unroll
        for (int d = 0; d < 4; d++) oa[j][d] = 0.f;
    float m0 = -1e30f, m1 = -1e30f, l0 = 0.f, l1 = 0.f;
    uint32_t qA[4][4];

    const int qr0 = qt * 64 + wid * 16 + (lane >> 2);
    const float d8 = -8.0f * slope2;

    float cst0[8], cst1[8];
#pragma unroll
    for (int nb = 0; nb < 8; nb++) {
        cst0[nb] = slope2 * (float)(nb * 8 + (lane & 3) * 2);
        cst1[nb] = cst0[nb] + slope2;
    }
    float base0 = -slope2 * (float)(wid * 16 + (lane >> 2));
    const float base_step = 64.0f * slope2;

    for (int it = 0; it < nkt; it++) {
        const int ktile = qt - it;
        if (it + 1 < nkt) { CP_WAIT1(); } else { CP_WAIT0(); }
        __syncthreads();
        if (it == 0) {
#pragma unroll
            for (int kb = 0; kb < 4; kb++) {
                int row = wid * 16 + ((g & 1) << 3) + rl;
                int gr = kb * 2 + (g >> 1);
                int off = row * 128 + gr * 16;
                uint32_t sw = (uint32_t)(off ^ ((off >> 3) & 0x70));
                ldsm_x4(qA[kb][0], qA[kb][1], qA[kb][2], qA[kb][3], sb + FQ2 + sw);
            }
            if (nkt > 2) __syncthreads();
        }
        if (it + 2 < nkt)
            f_issue_stage(sb + (uint32_t)((it + 2) % 3) * FSTG_SZ, tid, b, h, comp, qt - (it + 2), amask);
        uint32_t stg = sb + (uint32_t)(it % 3) * FSTG_SZ;

        // ---- S = Q K^T (single x single) ----
        float sa[8][4];
#pragma unroll
        for (int j = 0; j < 8; j++)
#pragma unroll
            for (int d = 0; d < 4; d++) sa[j][d] = 0.f;
#pragma unroll
        for (int kb = 0; kb < 4; kb++) {
#pragma unroll
            for (int nb2 = 0; nb2 < 4; nb2++) {
                uint32_t kh4[4];
                int row = nb2 * 16 + ((g >> 1) << 3) + rl;
                int gr = kb * 2 + (g & 1);
                int off = row * 128 + gr * 16;
                uint32_t sw = (uint32_t)(off ^ ((off >> 3) & 0x70));
                ldsm_x4(kh4[0], kh4[1], kh4[2], kh4[3], stg + FK2 + sw);
                MMAF16(sa[nb2 * 2], qA[kb], &kh4[0]);
                MMAF16(sa[nb2 * 2 + 1], qA[kb], &kh4[2]);
            }
        }

        // ---- bias + masks (base-2 domain) ----
        const float* ams = (const float*)(fsm + (stg - sb) + FAM);
        float colc[8][2];
#pragma unroll
        for (int nb = 0; nb < 8; nb++) {
            int kc = nb * 8 + (lane & 3) * 2;
            colc[nb][0] = fmaf(1.0f - ams[kc],     NEGV2, base0 + cst0[nb]);
            colc[nb][1] = fmaf(1.0f - ams[kc + 1], NEGV2, base0 + cst1[nb]);
        }
#pragma unroll
        for (int nb = 0; nb < 8; nb++) {
            sa[nb][0] = fmaf(sa[nb][0], scale2, colc[nb][0]);
            sa[nb][1] = fmaf(sa[nb][1], scale2, colc[nb][1]);
            sa[nb][2] = fmaf(sa[nb][2], scale2, colc[nb][0] + d8);
            sa[nb][3] = fmaf(sa[nb][3], scale2, colc[nb][1] + d8);
        }
        if (it == 0) {
            const int kcb = ktile * 64;
#pragma unroll
            for (int nb = 0; nb < 8; nb++) {
                int k0 = kcb + nb * 8 + (lane & 3) * 2;
                if (k0 > qr0)         sa[nb][0] += NEGV2;
                if (k0 + 1 > qr0)     sa[nb][1] += NEGV2;
                if (k0 > qr0 + 8)     sa[nb][2] += NEGV2;
                if (k0 + 1 > qr0 + 8) sa[nb][3] += NEGV2;
            }
        }
        base0 -= base_step;

        // ---- online softmax (base 2; l lane-local) ----
        float mx0 = -1e30f, mx1 = -1e30f;
#pragma unroll
        for (int nb = 0; nb < 8; nb++) {
            mx0 = fmaxf(mx0, fmaxf(sa[nb][0], sa[nb][1]));
            mx1 = fmaxf(mx1, fmaxf(sa[nb][2], sa[nb][3]));
        }
        mx0 = fmaxf(mx0, __shfl_xor_sync(0xffffffffu, mx0, 1));
        mx0 = fmaxf(mx0, __shfl_xor_sync(0xffffffffu, mx0, 2));
        mx1 = fmaxf(mx1, __shfl_xor_sync(0xffffffffu, mx1, 1));
        mx1 = fmaxf(mx1, __shfl_xor_sync(0xffffffffu, mx1, 2));
        float mn0 = fmaxf(m0, mx0), mn1 = fmaxf(m1, mx1);
        float al0 = fast_exp2(m0 - mn0), al1 = fast_exp2(m1 - mn1);
        m0 = mn0; m1 = mn1;
        float ls0 = 0.f, ls1 = 0.f;
#pragma unroll
        for (int nb = 0; nb < 8; nb++) {
            sa[nb][0] = fast_exp2(sa[nb][0] - mn0);
            sa[nb][1] = fast_exp2(sa[nb][1] - mn0);
            sa[nb][2] = fast_exp2(sa[nb][2] - mn1);
            sa[nb][3] = fast_exp2(sa[nb][3] - mn1);
            ls0 += sa[nb][0] + sa[nb][1];
            ls1 += sa[nb][2] + sa[nb][3];
        }
        l0 = l0 * al0 + ls0;
        l1 = l1 * al1 + ls1;

        bool noresc = __all_sync(0xffffffffu, (al0 == 1.0f) && (al1 == 1.0f));
        if (!noresc) {
#pragma unroll
            for (int j = 0; j < 8; j++) {
                oa[j][0] *= al0; oa[j][1] *= al0;
                oa[j][2] *= al1; oa[j][3] *= al1;
            }
        }

        // ---- O += P V (fp16 x2: P hi/lo, V single) ----
#pragma unroll
        for (int kb2 = 0; kb2 < 4; kb2++) {
            uint32_t pAh[4], pAl[4];
#pragma unroll
            for (int half = 0; half < 2; half++) {
                float v0a = sa[kb2 * 2][half * 2], v1a = sa[kb2 * 2][half * 2 + 1];
                float v0b = sa[kb2 * 2 + 1][half * 2], v1b = sa[kb2 * 2 + 1][half * 2 + 1];
                __half h0a = __float2half_rn(v0a), h1a = __float2half_rn(v1a);
                __half h0b = __float2half_rn(v0b), h1b = __float2half_rn(v1b);
                pAh[half]     = pack_h2(__half2float(h0a), __half2float(h1a));
                pAh[2 + half] = pack_h2(__half2float(h0b), __half2float(h1b));
                pAl[half]     = pack_h2(v0a - __half2float(h0a), v1a - __half2float(h1a));
                pAl[2 + half] = pack_h2(v0b - __half2float(h0b), v1b - __half2float(h1b));
            }
#pragma unroll
            for (int db = 0; db < 4; db++) {
                uint32_t vh4[4];
                int row = kb2 * 16 + ((g & 1) << 3) + rl;
                int gr = db * 2 + (g >> 1);
                int off = row * 128 + gr * 16;
                uint32_t sw = (uint32_t)(off ^ ((off >> 3) & 0x70));
                ldsm_x4t(vh4[0], vh4[1], vh4[2], vh4[3], stg + FV2 + sw);
                MMAF16(oa[db * 2], pAh, &vh4[0]);
                MMAF16(oa[db * 2], pAl, &vh4[0]);
                MMAF16(oa[db * 2 + 1], pAh, &vh4[2]);
                MMAF16(oa[db * 2 + 1], pAl, &vh4[2]);
            }
        }
    }

    l0 += __shfl_xor_sync(0xffffffffu, l0, 1);
    l0 += __shfl_xor_sync(0xffffffffu, l0, 2);
    l1 += __shfl_xor_sync(0xffffffffu, l1, 1);
    l1 += __shfl_xor_sync(0xffffffffu, l1, 2);
    float inv0 = 1.0f / l0, inv1 = 1.0f / l1;
    float* Og = (comp ? g_o2 : g_o1) + ((size_t)(b * S_) + qr0) * (H_ * DH_) + h * 64;
#pragma unroll
    for (int j = 0; j < 8; j++) {
        int col = j * 8 + (lane & 3) * 2;
        *(float2*)&Og[col] = make_float2(oa[j][0] * inv0, oa[j][1] * inv0);
        *(float2*)&Og[(size_t)8 * (H_ * DH_) + col] = make_float2(oa[j][2] * inv1, oa[j][3] * inv1);
    }
}

// ---------------- combine + groupnorm stats ---------------------------------
__global__ void __launch_bounds__(256) combine_stats_kernel() {
    const int bh = blockIdx.x >> 3;
    const int slice = blockIdx.x & 7;
    const int b = bh / H_, h = bh % H_;
    const float lam = g_lambda;
    double s = 0.0, ss = 0.0;
    const int base_row = b * S_ + slice * 256;
    for (int f = threadIdx.x; f < 256 * (DH_ / 4); f += 256) {
        int row = f >> 4, c = (f & 15) * 4;
        size_t e = (size_t)(base_row + row) * (H_ * DH_) + h * DH_ + c;
        float4 a = *(const float4*)&g_o1[e];
        float4 cc = *(const float4*)&g_o2[e];
        float4 y;
        y.x = a.x - lam * cc.x; y.y = a.y - lam * cc.y;
        y.z = a.z - lam * cc.z; y.w = a.w - lam * cc.w;
        *(float4*)&g_o[e] = y;
        s += (double)y.x + y.y + y.z + y.w;
        ss += (double)y.x * y.x + (double)y.y * y.y + (double)y.z * y.z + (double)y.w * y.w;
    }
    __shared__ double sh_s[256], sh_ss[256];
    sh_s[threadIdx.x] = s; sh_ss[threadIdx.x] = ss;
    __syncthreads();
    for (int st = 128; st > 0; st >>= 1) {
        if (threadIdx.x < st) {
            sh_s[threadIdx.x] += sh_s[threadIdx.x + st];
            sh_ss[threadIdx.x] += sh_ss[threadIdx.x + st];
        }
        __syncthreads();
    }
    if (threadIdx.x == 0) {
        atomicAdd(&g_sum[bh], sh_s[0]);
        atomicAdd(&g_sumsq[bh], sh_ss[0]);
    }
}

// ---------------- normalize + emit fp16 hi/lo --------------------------------
__global__ void __launch_bounds__(256) gn_apply_kernel(const float* __restrict__ gamma,
                                                       const float* __restrict__ beta) {
    int f = blockIdx.x * blockDim.x + threadIdx.x;
    if (f >= (B_ * S_ * H_ * DH_) / 4) return;
    int e = f * 4;
    int c = e % (H_ * DH_);
    int row = e / (H_ * DH_);
    int b = row / S_;
    int h = c / DH_;
    const double n = (double)S_ * DH_;
    double sm = g_sum[b * H_ + h], sq = g_sumsq[b * H_ + h];
    double meand = sm / n;
    float mean = (float)meand;
    float inv = rsqrtf((float)(sq / n - meand * meand) + EPS_);
    float4 x = *(const float4*)&g_o[e];
    float4 gm = *(const float4*)&gamma[c];
    float4 bt = *(const float4*)&beta[c];
    const float post = 1.0f - LAMBDA_INIT;
    float y[4];
    y[0] = ((x.x - mean) * inv * gm.x + bt.x) * post;
    y[1] = ((x.y - mean) * inv * gm.y + bt.y) * post;
    y[2] = ((x.z - mean) * inv * gm.z + bt.z) * post;
    y[3] = ((x.w - mean) * inv * gm.w + bt.w) * post;
    __half hh[4], ll[4];
#pragma unroll
    for (int j = 0; j < 4; j++) {
        hh[j] = __float2half_rn(y[j]);
        ll[j] = __float2half_rn(y[j] - __half2float(hh[j]));
    }
    *(uint2*)&g_nh2[e] = *(uint2*)hh;
    *(uint2*)&g_nl2[e] = *(uint2*)ll;
}

// ---------------- launch ----------------------------------------------------
extern "C" void kernel_launch(void* const* d_in, const int* in_sizes, int n_in,
                              void* d_out, int out_size) {
    const float* x     = (const float*)d_in[0];
    const float* amask = (const float*)d_in[1];
    const float* Wq = (const float*)d_in[3];
    const float* Wk = (const float*)d_in[4];
    const float* Wv = (const float*)d_in[5];
    const float* Wo = (const float*)d_in[6];
    const float* lq1 = (const float*)d_in[7];
    const float* lq2 = (const float*)d_in[8];
    const float* lk1 = (const float*)d_in[9];
    const float* lk2 = (const float*)d_in[10];
    const float* gam = (const float*)d_in[11];
    const float* bet = (const float*)d_in[12];
    float* out = (float*)d_out;

    const int M = B_ * S_;  // 4096

    // 0: lambda + zero stats
    lam_kernel<<<1, 1>>>(lq1, lq2, lk1, lk2);
    // 1: all conversions
    cvt_all<<<(N4_TOT + 255) / 256, 256>>>(x, Wq, Wk, Wv, Wo);
    // 2: fused QKV projection
    cudaFuncSetAttribute(gemm_qkv, cudaFuncAttributeMaxDynamicSharedMemorySize, G_SMEM);
    gemm_qkv<<<dim3(40, M / 128), 256, G_SMEM>>>();
    // 3: flash attention (profiled)
    cudaFuncSetAttribute(flashmma_kernel, cudaFuncAttributeMaxDynamicSharedMemorySize, FL_SMEM);
    flashmma_kernel<<<dim3(S_ / 64, B_ * H_ * 2), 128, FL_SMEM>>>(amask);
    // 4: combine + stats
    combine_stats_kernel<<<B_ * H_ * 8, 256>>>();
    // 5: normalize + fp16 split
    gn_apply_kernel<<<(B_ * S_ * H_ * DH_ / 4 + 255) / 256, 256>>>(gam, bet);
    // 6: output projection
    cudaFuncSetAttribute(gemm_o2, cudaFuncAttributeMaxDynamicSharedMemorySize, G_SMEM);
    gemm_o2<<<dim3(D_ / 128, M / 128), 256, G_SMEM>>>(out);
}

// round 16
// speedup vs baseline: 1.6485x; 1.0990x over previous
#include <cuda_runtime.h>
#include <cuda_fp16.h>
#include <math.h>
#include <cstdint>

#define B_  2
#define S_  2048
#define D_  1024
#define H_  16
#define DH_ 64
#define QKDIM 2048
#define LOG2E 1.44269504f
#define NEGV2 (-1.44269504e9f)
#define LAMBDA_INIT 0.8f
#define EPS_ 1e-5f

// ---------------- scratch (device globals) ---------------------------------
__device__ float g_o1[(size_t)B_ * S_ * H_ * DH_];
__device__ float g_o2[(size_t)B_ * S_ * H_ * DH_];
__device__ float g_o [(size_t)B_ * S_ * H_ * DH_];
__device__ float g_lambda;
__device__ double g_sum[B_ * H_], g_sumsq[B_ * H_];

// fp16 buffers
__device__ __half g_xh2[(size_t)B_ * S_ * D_], g_xl2[(size_t)B_ * S_ * D_];
__device__ __half g_wq2[QKDIM * D_];
__device__ __half g_wk2[QKDIM * D_];
__device__ __half g_wv2[(H_ * DH_) * D_];
__device__ __half g_wo2[D_ * (H_ * DH_)];
__device__ __half g_q2[(size_t)B_ * S_ * QKDIM];
__device__ __half g_k2[(size_t)B_ * S_ * QKDIM];
__device__ __half g_v2[(size_t)B_ * S_ * H_ * DH_];
__device__ __half g_nh2[(size_t)B_ * S_ * H_ * DH_], g_nl2[(size_t)B_ * S_ * H_ * DH_];

// ---------------- helpers ---------------------------------------------------
__device__ __forceinline__ uint32_t smem_u32(const void* p) {
    uint32_t a;
    asm("{ .reg .u64 t; cvta.to.shared.u64 t, %1; cvt.u32.u64 %0, t; }" : "=r"(a) : "l"(p));
    return a;
}
__device__ __forceinline__ float fast_exp2(float x) {
    float r;
    asm("ex2.approx.ftz.f32 %0, %1;" : "=f"(r) : "f"(x));
    return r;
}
#define CP16(dst, src) \
    asm volatile("cp.async.cg.shared.global [%0], [%1], 16;" :: "r"(dst), "l"(src) : "memory")
#define CP_COMMIT() asm volatile("cp.async.commit_group;" ::: "memory")
#define CP_WAIT1()  asm volatile("cp.async.wait_group 1;" ::: "memory")
#define CP_WAIT0()  asm volatile("cp.async.wait_group 0;" ::: "memory")

__device__ __forceinline__ void ldsm_x4(uint32_t& r0, uint32_t& r1, uint32_t& r2, uint32_t& r3,
                                        uint32_t addr) {
    asm volatile("ldmatrix.sync.aligned.m8n8.x4.shared.b16 {%0,%1,%2,%3}, [%4];"
                 : "=r"(r0), "=r"(r1), "=r"(r2), "=r"(r3) : "r"(addr));
}
__device__ __forceinline__ void ldsm_x4t(uint32_t& r0, uint32_t& r1, uint32_t& r2, uint32_t& r3,
                                         uint32_t addr) {
    asm volatile("ldmatrix.sync.aligned.m8n8.x4.trans.shared.b16 {%0,%1,%2,%3}, [%4];"
                 : "=r"(r0), "=r"(r1), "=r"(r2), "=r"(r3) : "r"(addr));
}
#define MMAF16(d, a, b) \
    asm volatile("mma.sync.aligned.m16n8k16.row.col.f32.f16.f16.f32 " \
                 "{%0,%1,%2,%3}, {%4,%5,%6,%7}, {%8,%9}, {%0,%1,%2,%3};" \
                 : "+f"((d)[0]), "+f"((d)[1]), "+f"((d)[2]), "+f"((d)[3]) \
                 : "r"((a)[0]), "r"((a)[1]), "r"((a)[2]), "r"((a)[3]), \
                   "r"((b)[0]), "r"((b)[1]))

__device__ __forceinline__ uint32_t pack_h2(float lo, float hi) {
    __half2 t = __floats2half2_rn(lo, hi);
    return *(uint32_t*)&t;
}

// ---------------- lambda + zero stats ---------------------------------------
__global__ void lam_kernel(const float* __restrict__ lq1, const float* __restrict__ lq2,
                           const float* __restrict__ lk1, const float* __restrict__ lk2) {
    float d1 = 0.f, d2 = 0.f;
    for (int i = 0; i < DH_; i++) { d1 += lq1[i] * lk1[i]; d2 += lq2[i] * lk2[i]; }
    g_lambda = expf(d1) - expf(d2) + LAMBDA_INIT;
    for (int i = 0; i < B_ * H_; i++) { g_sum[i] = 0.0; g_sumsq[i] = 0.0; }
}

// ---------------- conversions ------------------------------------------------
#define N4_X  (B_ * S_ * D_ / 4)
#define N4_WQ (QKDIM * D_ / 4)
#define N4_WV (H_ * DH_ * D_ / 4)
#define N4_TOT (N4_X + 2 * N4_WQ + 2 * N4_WV)

__device__ __forceinline__ void split4h(const float* src, __half* h, __half* l, size_t i) {
    float4 v = ((const float4*)src)[i];
    float vv[4] = {v.x, v.y, v.z, v.w};
    __half hh[4], ll[4];
#pragma unroll
    for (int j = 0; j < 4; j++) {
        hh[j] = __float2half_rn(vv[j]);
        ll[j] = __float2half_rn(vv[j] - __half2float(hh[j]));
    }
    *(uint2*)&h[i * 4] = *(uint2*)hh;
    *(uint2*)&l[i * 4] = *(uint2*)ll;
}
__device__ __forceinline__ void cvt4h(const float* src, __half* h, size_t i) {
    float4 v = ((const float4*)src)[i];
    __half hh[4];
    hh[0] = __float2half_rn(v.x); hh[1] = __float2half_rn(v.y);
    hh[2] = __float2half_rn(v.z); hh[3] = __float2half_rn(v.w);
    *(uint2*)&h[i * 4] = *(uint2*)hh;
}

__global__ void __launch_bounds__(256) cvt_all(
    const float* __restrict__ x,  const float* __restrict__ Wq,
    const float* __restrict__ Wk, const float* __restrict__ Wv,
    const float* __restrict__ Wo) {
    int i = blockIdx.x * 256 + threadIdx.x;
    if (i < N4_X) { split4h(x, g_xh2, g_xl2, i); return; }
    i -= N4_X;
    if (i < N4_WQ) { cvt4h(Wq, g_wq2, i); return; }
    i -= N4_WQ;
    if (i < N4_WQ) { cvt4h(Wk, g_wk2, i); return; }
    i -= N4_WQ;
    if (i < N4_WV) { cvt4h(Wv, g_wv2, i); return; }
    i -= N4_WV;
    if (i < N4_WV) { cvt4h(Wo, g_wo2, i); return; }
}

// ---------------- GEMM loader / chunk (fp16 x2) ------------------------------
#define GSTAGE 32768
#define G_SMEM (3 * GSTAGE)

__device__ __forceinline__ void g_issue_h2(
    const __half* __restrict__ Ah, const __half* __restrict__ Al,
    const __half* __restrict__ B2,
    uint32_t sbuf, int tid, int bm, int bn, int K, int c) {
#pragma unroll
    for (int i = 0; i < 2; i++) {
        int ch = tid + i * 256;
        int p = ch >> 3, c16 = ch & 7;
        int r = (p << 1) + (c16 >> 2);
        int kb = (c16 & 3) * 8;
        int off = p * 128 + c16 * 16;
        uint32_t dst = sbuf + (off ^ ((off >> 3) & 0x70));
        size_t ga = (size_t)(bm + r) * K + c * 32 + kb;
        size_t gb = (size_t)(bn + r) * K + c * 32 + kb;
        CP16(dst,         Ah + ga);
        CP16(dst + 8192,  Al + ga);
        CP16(dst + 16384, B2 + gb);
    }
    CP_COMMIT();
}

__device__ __forceinline__ void g_chunk_h2(uint32_t sbuf, int wm, int wn, int g, int rl,
                                           float acc[2][8][4]) {
#pragma unroll
    for (int ks = 0; ks < 2; ks++) {
        uint32_t ah[2][4], al[2][4];
#pragma unroll
        for (int mb = 0; mb < 2; mb++) {
            int r = wm + mb * 16 + ((g & 1) << 3) + rl;
            int c16 = ((r & 1) << 2) + ks * 2 + (g >> 1);
            int off = (r >> 1) * 128 + c16 * 16;
            uint32_t sw = (uint32_t)(off ^ ((off >> 3) & 0x70));
            ldsm_x4(ah[mb][0], ah[mb][1], ah[mb][2], ah[mb][3], sbuf + sw);
            ldsm_x4(al[mb][0], al[mb][1], al[mb][2], al[mb][3], sbuf + 8192 + sw);
        }
        uint32_t bh[4][4];
#pragma unroll
        for (int np = 0; np < 4; np++) {
            int r = wn + np * 16 + ((g >> 1) << 3) + rl;
            int c16 = ((r & 1) << 2) + ks * 2 + (g & 1);
            int off = (r >> 1) * 128 + c16 * 16;
            uint32_t sw = (uint32_t)(off ^ ((off >> 3) & 0x70));
            ldsm_x4(bh[np][0], bh[np][1], bh[np][2], bh[np][3], sbuf + 16384 + sw);
        }
#pragma unroll
        for (int mb = 0; mb < 2; mb++)
#pragma unroll
            for (int j = 0; j < 8; j++) {
                MMAF16(acc[mb][j], ah[mb], &bh[j >> 1][(j & 1) * 2]);
                MMAF16(acc[mb][j], al[mb], &bh[j >> 1][(j & 1) * 2]);
            }
    }
}

// ---------------- fused QKV projection (fp16 x2; all outputs single fp16) ----
__global__ void __launch_bounds__(256, 2) gemm_qkv() {
    extern __shared__ char smem[];
    const uint32_t sbase = smem_u32(smem);
    const int tid = threadIdx.x, wid = tid >> 5, lane = tid & 31;
    const int nt = blockIdx.x;
    const int bm = blockIdx.y * 128;
    const int wm = (wid & 3) * 32;
    const int wn = (wid >> 2) * 64;
    const int g = lane >> 3, rl = lane & 7;
    const int K = D_;
    const int nch = K >> 5;

    const __half* B2;
    __half* O2;
    int N, bn;
    if (nt < 16)      { B2 = g_wq2; O2 = g_q2; N = QKDIM;    bn = nt * 128; }
    else if (nt < 32) { B2 = g_wk2; O2 = g_k2; N = QKDIM;    bn = (nt - 16) * 128; }
    else              { B2 = g_wv2; O2 = g_v2; N = H_ * DH_; bn = (nt - 32) * 128; }

    float acc[2][8][4];
#pragma unroll
    for (int a = 0; a < 2; a++)
#pragma unroll
        for (int b = 0; b < 8; b++)
#pragma unroll
            for (int d = 0; d < 4; d++) acc[a][b][d] = 0.f;

    g_issue_h2(g_xh2, g_xl2, B2, sbase, tid, bm, bn, K, 0);
    g_issue_h2(g_xh2, g_xl2, B2, sbase + GSTAGE, tid, bm, bn, K, 1);
    for (int c = 0; c < nch; c++) {
        if (c + 1 < nch) { CP_WAIT1(); } else { CP_WAIT0(); }
        __syncthreads();
        if (c + 2 < nch)
            g_issue_h2(g_xh2, g_xl2, B2, sbase + (uint32_t)((c + 2) % 3) * GSTAGE, tid, bm, bn, K, c + 2);
        g_chunk_h2(sbase + (uint32_t)(c % 3) * GSTAGE, wm, wn, g, rl, acc);
    }

#pragma unroll
    for (int mb = 0; mb < 2; mb++) {
        int row0 = bm + wm + mb * 16 + (lane >> 2);
#pragma unroll
        for (int j = 0; j < 8; j++) {
            int col = bn + wn + j * 8 + (lane & 3) * 2;
#pragma unroll
            for (int rr = 0; rr < 2; rr++) {
                __half2 p = __floats2half2_rn(acc[mb][j][rr * 2], acc[mb][j][rr * 2 + 1]);
                *(__half2*)&O2[(size_t)(row0 + rr * 8) * N + col] = p;
            }
        }
    }
}

// ---------------- output projection (fp16 x2, fp32 out) ----------------------
__global__ void __launch_bounds__(256, 2) gemm_o2(float* __restrict__ Cf) {
    extern __shared__ char smem[];
    const uint32_t sbase = smem_u32(smem);
    const int tid = threadIdx.x, wid = tid >> 5, lane = tid & 31;
    const int bm = blockIdx.y * 128, bn = blockIdx.x * 128;
    const int wm = (wid & 3) * 32;
    const int wn = (wid >> 2) * 64;
    const int g = lane >> 3, rl = lane & 7;
    const int K = H_ * DH_, N = D_;
    const int nch = K >> 5;

    float acc[2][8][4];
#pragma unroll
    for (int a = 0; a < 2; a++)
#pragma unroll
        for (int b = 0; b < 8; b++)
#pragma unroll
            for (int d = 0; d < 4; d++) acc[a][b][d] = 0.f;

    g_issue_h2(g_nh2, g_nl2, g_wo2, sbase, tid, bm, bn, K, 0);
    g_issue_h2(g_nh2, g_nl2, g_wo2, sbase + GSTAGE, tid, bm, bn, K, 1);
    for (int c = 0; c < nch; c++) {
        if (c + 1 < nch) { CP_WAIT1(); } else { CP_WAIT0(); }
        __syncthreads();
        if (c + 2 < nch)
            g_issue_h2(g_nh2, g_nl2, g_wo2, sbase + (uint32_t)((c + 2) % 3) * GSTAGE, tid, bm, bn, K, c + 2);
        g_chunk_h2(sbase + (uint32_t)(c % 3) * GSTAGE, wm, wn, g, rl, acc);
    }

#pragma unroll
    for (int mb = 0; mb < 2; mb++) {
        int row0 = bm + wm + mb * 16 + (lane >> 2);
#pragma unroll
        for (int j = 0; j < 8; j++) {
            int col = bn + wn + j * 8 + (lane & 3) * 2;
            *(float2*)&Cf[(size_t)row0 * N + col]       = make_float2(acc[mb][j][0], acc[mb][j][1]);
            *(float2*)&Cf[(size_t)(row0 + 8) * N + col] = make_float2(acc[mb][j][2], acc[mb][j][3]);
        }
    }
}

// ---------------- flash attention --------------------------------------------
// 4 warps, 64-q tiles. QK single x single fp16; PV single x single fp16.
#define FK2  0
#define FV2  8192
#define FAM  16384
#define FSTG_SZ 16640
#define FQ2 (2 * FSTG_SZ)
#define FL_SMEM (3 * FSTG_SZ)   // 49920 (Q 8KB overlays stage 2)

__device__ __forceinline__ void f_issue_stage(uint32_t stg, int tid, int b, int h, int comp,
                                              int kt, const float* __restrict__ amask) {
    const char* Kg = (const char*)(g_k2 + ((size_t)(b * S_) + kt * 64) * QKDIM + h * 128 + comp * 64);
    const char* Vg = (const char*)(g_v2 + ((size_t)(b * S_) + kt * 64) * (H_ * DH_) + h * 64);
#pragma unroll
    for (int i = 0; i < 4; i++) {
        int t = tid + i * 128;
        int row = t >> 3, gr = t & 7;
        int off = row * 128 + gr * 16;
        uint32_t sw = (uint32_t)(off ^ ((off >> 3) & 0x70));
        CP16(stg + FK2 + sw, Kg + (size_t)row * (QKDIM * 2) + gr * 16);
        CP16(stg + FV2 + sw, Vg + (size_t)row * (H_ * DH_ * 2) + gr * 16);
    }
    if (tid < 16)
        CP16(stg + FAM + tid * 16, amask + b * S_ + kt * 64 + tid * 4);
    CP_COMMIT();
}

__global__ void __launch_bounds__(128) flashmma_kernel(const float* __restrict__ amask) {
    extern __shared__ char fsm[];
    const uint32_t sb = smem_u32(fsm);
    const int tid = threadIdx.x, wid = tid >> 5, lane = tid & 31;
    const int g = lane >> 3, rl = lane & 7;
    const int qt = (gridDim.x - 1) - blockIdx.x;
    const int z = blockIdx.y;
    const int comp = z & 1;
    const int bh = z >> 1;
    const int b = bh / H_, h = bh % H_;
    const float slope2 = exp2f(-8.0f * (float)(h + 1) / (float)H_) * LOG2E;
    const float scale2 = 0.125f * LOG2E;
    const int nkt = qt + 1;

    {
        const char* Qg = (const char*)(g_q2 + ((size_t)(b * S_) + qt * 64) * QKDIM + h * 128 + comp * 64);
#pragma unroll
        for (int i = 0; i < 4; i++) {
            int t = tid + i * 128;
            int row = t >> 3, gr = t & 7;
            int off = row * 128 + gr * 16;
            uint32_t sw = (uint32_t)(off ^ ((off >> 3) & 0x70));
            CP16(sb + FQ2 + sw, Qg + (size_t)row * (QKDIM * 2) + gr * 16);
        }
    }
    f_issue_stage(sb, tid, b, h, comp, qt, amask);
    if (nkt > 1) f_issue_stage(sb + FSTG_SZ, tid, b, h, comp, qt - 1, amask);

    float oa[8][4];
#pragma unroll
    for (int j = 0; j < 8; j++)
#pragma unroll
        for (int d = 0; d < 4; d++) oa[j][d] = 0.f;
    float m0 = -1e30f, m1 = -1e30f, l0 = 0.f, l1 = 0.f;
    uint32_t qA[4][4];

    const int qr0 = qt * 64 + wid * 16 + (lane >> 2);
    const float d8 = -8.0f * slope2;

    float cst0[8], cst1[8];
#pragma unroll
    for (int nb = 0; nb < 8; nb++) {
        cst0[nb] = slope2 * (float)(nb * 8 + (lane & 3) * 2);
        cst1[nb] = cst0[nb] + slope2;
    }
    float base0 = -slope2 * (float)(wid * 16 + (lane >> 2));
    const float base_step = 64.0f * slope2;

    for (int it = 0; it < nkt; it++) {
        const int ktile = qt - it;
        if (it + 1 < nkt) { CP_WAIT1(); } else { CP_WAIT0(); }
        __syncthreads();
        if (it == 0) {
#pragma unroll
            for (int kb = 0; kb < 4; kb++) {
                int row = wid * 16 + ((g & 1) << 3) + rl;
                int gr = kb * 2 + (g >> 1);
                int off = row * 128 + gr * 16;
                uint32_t sw = (uint32_t)(off ^ ((off >> 3) & 0x70));
                ldsm_x4(qA[kb][0], qA[kb][1], qA[kb][2], qA[kb][3], sb + FQ2 + sw);
            }
            if (nkt > 2) __syncthreads();
        }
        if (it + 2 < nkt)
            f_issue_stage(sb + (uint32_t)((it + 2) % 3) * FSTG_SZ, tid, b, h, comp, qt - (it + 2), amask);
        uint32_t stg = sb + (uint32_t)(it % 3) * FSTG_SZ;

        // ---- S = Q K^T (single x single) ----
        float sa[8][4];
#pragma unroll
        for (int j = 0; j < 8; j++)
#pragma unroll
            for (int d = 0; d < 4; d++) sa[j][d] = 0.f;
#pragma unroll
        for (int kb = 0; kb < 4; kb++) {
#pragma unroll
            for (int nb2 = 0; nb2 < 4; nb2++) {
                uint32_t kh4[4];
                int row = nb2 * 16 + ((g >> 1) << 3) + rl;
                int gr = kb * 2 + (g & 1);
                int off = row * 128 + gr * 16;
                uint32_t sw = (uint32_t)(off ^ ((off >> 3) & 0x70));
                ldsm_x4(kh4[0], kh4[1], kh4[2], kh4[3], stg + FK2 + sw);
                MMAF16(sa[nb2 * 2], qA[kb], &kh4[0]);
                MMAF16(sa[nb2 * 2 + 1], qA[kb], &kh4[2]);
            }
        }

        // ---- bias + masks (base-2 domain) ----
        const float* ams = (const float*)(fsm + (stg - sb) + FAM);
        float colc[8][2];
#pragma unroll
        for (int nb = 0; nb < 8; nb++) {
            int kc = nb * 8 + (lane & 3) * 2;
            colc[nb][0] = fmaf(1.0f - ams[kc],     NEGV2, base0 + cst0[nb]);
            colc[nb][1] = fmaf(1.0f - ams[kc + 1], NEGV2, base0 + cst1[nb]);
        }
#pragma unroll
        for (int nb = 0; nb < 8; nb++) {
            sa[nb][0] = fmaf(sa[nb][0], scale2, colc[nb][0]);
            sa[nb][1] = fmaf(sa[nb][1], scale2, colc[nb][1]);
            sa[nb][2] = fmaf(sa[nb][2], scale2, colc[nb][0] + d8);
            sa[nb][3] = fmaf(sa[nb][3], scale2, colc[nb][1] + d8);
        }
        if (it == 0) {
            const int kcb = ktile * 64;
#pragma unroll
            for (int nb = 0; nb < 8; nb++) {
                int k0 = kcb + nb * 8 + (lane & 3) * 2;
                if (k0 > qr0)         sa[nb][0] += NEGV2;
                if (k0 + 1 > qr0)     sa[nb][1] += NEGV2;
                if (k0 > qr0 + 8)     sa[nb][2] += NEGV2;
                if (k0 + 1 > qr0 + 8) sa[nb][3] += NEGV2;
            }
        }
        base0 -= base_step;

        // ---- online softmax (base 2; l lane-local) ----
        float mx0 = -1e30f, mx1 = -1e30f;
#pragma unroll
        for (int nb = 0; nb < 8; nb++) {
            mx0 = fmaxf(mx0, fmaxf(sa[nb][0], sa[nb][1]));
            mx1 = fmaxf(mx1, fmaxf(sa[nb][2], sa[nb][3]));
        }
        mx0 = fmaxf(mx0, __shfl_xor_sync(0xffffffffu, mx0, 1));
        mx0 = fmaxf(mx0, __shfl_xor_sync(0xffffffffu, mx0, 2));
        mx1 = fmaxf(mx1, __shfl_xor_sync(0xffffffffu, mx1, 1));
        mx1 = fmaxf(mx1, __shfl_xor_sync(0xffffffffu, mx1, 2));
        float mn0 = fmaxf(m0, mx0), mn1 = fmaxf(m1, mx1);
        float al0 = fast_exp2(m0 - mn0), al1 = fast_exp2(m1 - mn1);
        m0 = mn0; m1 = mn1;
        float ls0 = 0.f, ls1 = 0.f;
#pragma unroll
        for (int nb = 0; nb < 8; nb++) {
            sa[nb][0] = fast_exp2(sa[nb][0] - mn0);
            sa[nb][1] = fast_exp2(sa[nb][1] - mn0);
            sa[nb][2] = fast_exp2(sa[nb][2] - mn1);
            sa[nb][3] = fast_exp2(sa[nb][3] - mn1);
            ls0 += sa[nb][0] + sa[nb][1];
            ls1 += sa[nb][2] + sa[nb][3];
        }
        l0 = l0 * al0 + ls0;
        l1 = l1 * al1 + ls1;

        bool noresc = __all_sync(0xffffffffu, (al0 == 1.0f) && (al1 == 1.0f));
        if (!noresc) {
#pragma unroll
            for (int j = 0; j < 8; j++) {
                oa[j][0] *= al0; oa[j][1] *= al0;
                oa[j][2] *= al1; oa[j][3] *= al1;
            }
        }

        // ---- O += P V (single x single) ----
#pragma unroll
        for (int kb2 = 0; kb2 < 4; kb2++) {
            uint32_t pA[4];
            pA[0] = pack_h2(sa[kb2 * 2][0], sa[kb2 * 2][1]);
            pA[1] = pack_h2(sa[kb2 * 2][2], sa[kb2 * 2][3]);
            pA[2] = pack_h2(sa[kb2 * 2 + 1][0], sa[kb2 * 2 + 1][1]);
            pA[3] = pack_h2(sa[kb2 * 2 + 1][2], sa[kb2 * 2 + 1][3]);
#pragma unroll
            for (int db = 0; db < 4; db++) {
                uint32_t vh4[4];
                int row = kb2 * 16 + ((g & 1) << 3) + rl;
                int gr = db * 2 + (g >> 1);
                int off = row * 128 + gr * 16;
                uint32_t sw = (uint32_t)(off ^ ((off >> 3) & 0x70));
                ldsm_x4t(vh4[0], vh4[1], vh4[2], vh4[3], stg + FV2 + sw);
                MMAF16(oa[db * 2], pA, &vh4[0]);
                MMAF16(oa[db * 2 + 1], pA, &vh4[2]);
            }
        }
    }

    l0 += __shfl_xor_sync(0xffffffffu, l0, 1);
    l0 += __shfl_xor_sync(0xffffffffu, l0, 2);
    l1 += __shfl_xor_sync(0xffffffffu, l1, 1);
    l1 += __shfl_xor_sync(0xffffffffu, l1, 2);
    float inv0 = 1.0f / l0, inv1 = 1.0f / l1;
    float* Og = (comp ? g_o2 : g_o1) + ((size_t)(b * S_) + qr0) * (H_ * DH_) + h * 64;
#pragma unroll
    for (int j = 0; j < 8; j++) {
        int col = j * 8 + (lane & 3) * 2;
        *(float2*)&Og[col] = make_float2(oa[j][0] * inv0, oa[j][1] * inv0);
        *(float2*)&Og[(size_t)8 * (H_ * DH_) + col] = make_float2(oa[j][2] * inv1, oa[j][3] * inv1);
    }
}

// ---------------- combine + groupnorm stats ---------------------------------
__global__ void __launch_bounds__(256) combine_stats_kernel() {
    const int bh = blockIdx.x >> 3;
    const int slice = blockIdx.x & 7;
    const int b = bh / H_, h = bh % H_;
    const float lam = g_lambda;
    double s = 0.0, ss = 0.0;
    const int base_row = b * S_ + slice * 256;
    for (int f = threadIdx.x; f < 256 * (DH_ / 4); f += 256) {
        int row = f >> 4, c = (f & 15) * 4;
        size_t e = (size_t)(base_row + row) * (H_ * DH_) + h * DH_ + c;
        float4 a = *(const float4*)&g_o1[e];
        float4 cc = *(const float4*)&g_o2[e];
        float4 y;
        y.x = a.x - lam * cc.x; y.y = a.y - lam * cc.y;
        y.z = a.z - lam * cc.z; y.w = a.w - lam * cc.w;
        *(float4*)&g_o[e] = y;
        s += (double)y.x + y.y + y.z + y.w;
        ss += (double)y.x * y.x + (double)y.y * y.y + (double)y.z * y.z + (double)y.w * y.w;
    }
    __shared__ double sh_s[256], sh_ss[256];
    sh_s[threadIdx.x] = s; sh_ss[threadIdx.x] = ss;
    __syncthreads();
    for (int st = 128; st > 0; st >>= 1) {
        if (threadIdx.x < st) {
            sh_s[threadIdx.x] += sh_s[threadIdx.x + st];
            sh_ss[threadIdx.x] += sh_ss[threadIdx.x + st];
        }
        __syncthreads();
    }
    if (threadIdx.x == 0) {
        atomicAdd(&g_sum[bh], sh_s[0]);
        atomicAdd(&g_sumsq[bh], sh_ss[0]);
    }
}

// ---------------- normalize + emit fp16 hi/lo --------------------------------
__global__ void __launch_bounds__(256) gn_apply_kernel(const float* __restrict__ gamma,
                                                       const float* __restrict__ beta) {
    int f = blockIdx.x * blockDim.x + threadIdx.x;
    if (f >= (B_ * S_ * H_ * DH_) / 4) return;
    int e = f * 4;
    int c = e % (H_ * DH_);
    int row = e / (H_ * DH_);
    int b = row / S_;
    int h = c / DH_;
    const double n = (double)S_ * DH_;
    double sm = g_sum[b * H_ + h], sq = g_sumsq[b * H_ + h];
    double meand = sm / n;
    float mean = (float)meand;
    float inv = rsqrtf((float)(sq / n - meand * meand) + EPS_);
    float4 x = *(const float4*)&g_o[e];
    float4 gm = *(const float4*)&gamma[c];
    float4 bt = *(const float4*)&beta[c];
    const float post = 1.0f - LAMBDA_INIT;
    float y[4];
    y[0] = ((x.x - mean) * inv * gm.x + bt.x) * post;
    y[1] = ((x.y - mean) * inv * gm.y + bt.y) * post;
    y[2] = ((x.z - mean) * inv * gm.z + bt.z) * post;
    y[3] = ((x.w - mean) * inv * gm.w + bt.w) * post;
    __half hh[4], ll[4];
#pragma unroll
    for (int j = 0; j < 4; j++) {
        hh[j] = __float2half_rn(y[j]);
        ll[j] = __float2half_rn(y[j] - __half2float(hh[j]));
    }
    *(uint2*)&g_nh2[e] = *(uint2*)hh;
    *(uint2*)&g_nl2[e] = *(uint2*)ll;
}

// ---------------- launch ----------------------------------------------------
extern "C" void kernel_launch(void* const* d_in, const int* in_sizes, int n_in,
                              void* d_out, int out_size) {
    const float* x     = (const float*)d_in[0];
    const float* amask = (const float*)d_in[1];
    const float* Wq = (const float*)d_in[3];
    const float* Wk = (const float*)d_in[4];
    const float* Wv = (const float*)d_in[5];
    const float* Wo = (const float*)d_in[6];
    const float* lq1 = (const float*)d_in[7];
    const float* lq2 = (const float*)d_in[8];
    const float* lk1 = (const float*)d_in[9];
    const float* lk2 = (const float*)d_in[10];
    const float* gam = (const float*)d_in[11];
    const float* bet = (const float*)d_in[12];
    float* out = (float*)d_out;

    const int M = B_ * S_;  // 4096

    // 0: lambda + zero stats
    lam_kernel<<<1, 1>>>(lq1, lq2, lk1, lk2);
    // 1: all conversions
    cvt_all<<<(N4_TOT + 255) / 256, 256>>>(x, Wq, Wk, Wv, Wo);
    // 2: fused QKV projection
    cudaFuncSetAttribute(gemm_qkv, cudaFuncAttributeMaxDynamicSharedMemorySize, G_SMEM);
    gemm_qkv<<<dim3(40, M / 128), 256, G_SMEM>>>();
    // 3: flash attention (profiled)
    cudaFuncSetAttribute(flashmma_kernel, cudaFuncAttributeMaxDynamicSharedMemorySize, FL_SMEM);
    flashmma_kernel<<<dim3(S_ / 64, B_ * H_ * 2), 128, FL_SMEM>>>(amask);
    // 4: combine + stats
    combine_stats_kernel<<<B_ * H_ * 8, 256>>>();
    // 5: normalize + fp16 split
    gn_apply_kernel<<<(B_ * S_ * H_ * DH_ / 4 + 255) / 256, 256>>>(gam, bet);
    // 6: output projection
    cudaFuncSetAttribute(gemm_o2, cudaFuncAttributeMaxDynamicSharedMemorySize, G_SMEM);
    gemm_o2<<<dim3(D_ / 128, M / 128), 256, G_SMEM>>>(out);
}

// round 17
// speedup vs baseline: 2.0076x; 1.2178x over previous
#include <cuda_runtime.h>
#include <cuda_fp16.h>
#include <math.h>
#include <cstdint>

#define B_  2
#define S_  2048
#define D_  1024
#define H_  16
#define DH_ 64
#define QKDIM 2048
#define LOG2E 1.44269504f
#define NEGV2 (-1.44269504e9f)
#define LAMBDA_INIT 0.8f
#define EPS_ 1e-5f

// ---------------- scratch (device globals) ---------------------------------
__device__ float g_o1[(size_t)B_ * S_ * H_ * DH_];
__device__ float g_o2[(size_t)B_ * S_ * H_ * DH_];
__device__ float g_o [(size_t)B_ * S_ * H_ * DH_];
__device__ float g_lambda;
__device__ double g_sum[B_ * H_], g_sumsq[B_ * H_];

// fp16 buffers
__device__ __half g_x2[(size_t)B_ * S_ * D_];
__device__ __half g_wq2[QKDIM * D_];
__device__ __half g_wk2[QKDIM * D_];
__device__ __half g_wv2[(H_ * DH_) * D_];
__device__ __half g_wo2[D_ * (H_ * DH_)];
__device__ __half g_q2[(size_t)B_ * S_ * QKDIM];
__device__ __half g_k2[(size_t)B_ * S_ * QKDIM];
__device__ __half g_v2[(size_t)B_ * S_ * H_ * DH_];
__device__ __half g_nh2[(size_t)B_ * S_ * H_ * DH_], g_nl2[(size_t)B_ * S_ * H_ * DH_];

// ---------------- helpers ---------------------------------------------------
__device__ __forceinline__ uint32_t smem_u32(const void* p) {
    uint32_t a;
    asm("{ .reg .u64 t; cvta.to.shared.u64 t, %1; cvt.u32.u64 %0, t; }" : "=r"(a) : "l"(p));
    return a;
}
__device__ __forceinline__ float fast_exp2(float x) {
    float r;
    asm("ex2.approx.ftz.f32 %0, %1;" : "=f"(r) : "f"(x));
    return r;
}
#define CP16(dst, src) \
    asm volatile("cp.async.cg.shared.global [%0], [%1], 16;" :: "r"(dst), "l"(src) : "memory")
#define CP_COMMIT() asm volatile("cp.async.commit_group;" ::: "memory")
#define CP_WAIT1()  asm volatile("cp.async.wait_group 1;" ::: "memory")
#define CP_WAIT0()  asm volatile("cp.async.wait_group 0;" ::: "memory")

__device__ __forceinline__ void ldsm_x4(uint32_t& r0, uint32_t& r1, uint32_t& r2, uint32_t& r3,
                                        uint32_t addr) {
    asm volatile("ldmatrix.sync.aligned.m8n8.x4.shared.b16 {%0,%1,%2,%3}, [%4];"
                 : "=r"(r0), "=r"(r1), "=r"(r2), "=r"(r3) : "r"(addr));
}
__device__ __forceinline__ void ldsm_x4t(uint32_t& r0, uint32_t& r1, uint32_t& r2, uint32_t& r3,
                                         uint32_t addr) {
    asm volatile("ldmatrix.sync.aligned.m8n8.x4.trans.shared.b16 {%0,%1,%2,%3}, [%4];"
                 : "=r"(r0), "=r"(r1), "=r"(r2), "=r"(r3) : "r"(addr));
}
#define MMAF16(d, a, b) \
    asm volatile("mma.sync.aligned.m16n8k16.row.col.f32.f16.f16.f32 " \
                 "{%0,%1,%2,%3}, {%4,%5,%6,%7}, {%8,%9}, {%0,%1,%2,%3};" \
                 : "+f"((d)[0]), "+f"((d)[1]), "+f"((d)[2]), "+f"((d)[3]) \
                 : "r"((a)[0]), "r"((a)[1]), "r"((a)[2]), "r"((a)[3]), \
                   "r"((b)[0]), "r"((b)[1]))

__device__ __forceinline__ uint32_t pack_h2(float lo, float hi) {
    __half2 t = __floats2half2_rn(lo, hi);
    return *(uint32_t*)&t;
}

// ---------------- lambda + zero stats ---------------------------------------
__global__ void lam_kernel(const float* __restrict__ lq1, const float* __restrict__ lq2,
                           const float* __restrict__ lk1, const float* __restrict__ lk2) {
    float d1 = 0.f, d2 = 0.f;
    for (int i = 0; i < DH_; i++) { d1 += lq1[i] * lk1[i]; d2 += lq2[i] * lk2[i]; }
    g_lambda = expf(d1) - expf(d2) + LAMBDA_INIT;
    for (int i = 0; i < B_ * H_; i++) { g_sum[i] = 0.0; g_sumsq[i] = 0.0; }
}

// ---------------- conversions ------------------------------------------------
#define N4_X  (B_ * S_ * D_ / 4)
#define N4_WQ (QKDIM * D_ / 4)
#define N4_WV (H_ * DH_ * D_ / 4)
#define N4_TOT (N4_X + 2 * N4_WQ + 2 * N4_WV)

__device__ __forceinline__ void cvt4h(const float* src, __half* h, size_t i) {
    float4 v = ((const float4*)src)[i];
    __half hh[4];
    hh[0] = __float2half_rn(v.x); hh[1] = __float2half_rn(v.y);
    hh[2] = __float2half_rn(v.z); hh[3] = __float2half_rn(v.w);
    *(uint2*)&h[i * 4] = *(uint2*)hh;
}

__global__ void __launch_bounds__(256) cvt_all(
    const float* __restrict__ x,  const float* __restrict__ Wq,
    const float* __restrict__ Wk, const float* __restrict__ Wv,
    const float* __restrict__ Wo) {
    int i = blockIdx.x * 256 + threadIdx.x;
    if (i < N4_X) { cvt4h(x, g_x2, i); return; }
    i -= N4_X;
    if (i < N4_WQ) { cvt4h(Wq, g_wq2, i); return; }
    i -= N4_WQ;
    if (i < N4_WQ) { cvt4h(Wk, g_wk2, i); return; }
    i -= N4_WQ;
    if (i < N4_WV) { cvt4h(Wv, g_wv2, i); return; }
    i -= N4_WV;
    if (i < N4_WV) { cvt4h(Wo, g_wo2, i); return; }
}

// ---------------- GEMM loaders / chunks --------------------------------------
// single x single (A 8KB + B 8KB per stage)
#define G1STAGE 16384
#define G1_SMEM (3 * G1STAGE)

__device__ __forceinline__ void g_issue_h1(
    const __half* __restrict__ A2, const __half* __restrict__ B2,
    uint32_t sbuf, int tid, int bm, int bn, int K, int c) {
#pragma unroll
    for (int i = 0; i < 2; i++) {
        int ch = tid + i * 256;
        int p = ch >> 3, c16 = ch & 7;
        int r = (p << 1) + (c16 >> 2);
        int kb = (c16 & 3) * 8;
        int off = p * 128 + c16 * 16;
        uint32_t dst = sbuf + (off ^ ((off >> 3) & 0x70));
        size_t ga = (size_t)(bm + r) * K + c * 32 + kb;
        size_t gb = (size_t)(bn + r) * K + c * 32 + kb;
        CP16(dst,        A2 + ga);
        CP16(dst + 8192, B2 + gb);
    }
    CP_COMMIT();
}

__device__ __forceinline__ void g_chunk_h1(uint32_t sbuf, int wm, int wn, int g, int rl,
                                           float acc[2][8][4]) {
#pragma unroll
    for (int ks = 0; ks < 2; ks++) {
        uint32_t ah[2][4];
#pragma unroll
        for (int mb = 0; mb < 2; mb++) {
            int r = wm + mb * 16 + ((g & 1) << 3) + rl;
            int c16 = ((r & 1) << 2) + ks * 2 + (g >> 1);
            int off = (r >> 1) * 128 + c16 * 16;
            uint32_t sw = (uint32_t)(off ^ ((off >> 3) & 0x70));
            ldsm_x4(ah[mb][0], ah[mb][1], ah[mb][2], ah[mb][3], sbuf + sw);
        }
        uint32_t bh[4][4];
#pragma unroll
        for (int np = 0; np < 4; np++) {
            int r = wn + np * 16 + ((g >> 1) << 3) + rl;
            int c16 = ((r & 1) << 2) + ks * 2 + (g & 1);
            int off = (r >> 1) * 128 + c16 * 16;
            uint32_t sw = (uint32_t)(off ^ ((off >> 3) & 0x70));
            ldsm_x4(bh[np][0], bh[np][1], bh[np][2], bh[np][3], sbuf + 8192 + sw);
        }
#pragma unroll
        for (int mb = 0; mb < 2; mb++)
#pragma unroll
            for (int j = 0; j < 8; j++)
                MMAF16(acc[mb][j], ah[mb], &bh[j >> 1][(j & 1) * 2]);
    }
}

// hi/lo x single (A 2x8KB + B 8KB per stage) — output projection only
#define GSTAGE 32768
#define G_SMEM (3 * GSTAGE)

__device__ __forceinline__ void g_issue_h2(
    const __half* __restrict__ Ah, const __half* __restrict__ Al,
    const __half* __restrict__ B2,
    uint32_t sbuf, int tid, int bm, int bn, int K, int c) {
#pragma unroll
    for (int i = 0; i < 2; i++) {
        int ch = tid + i * 256;
        int p = ch >> 3, c16 = ch & 7;
        int r = (p << 1) + (c16 >> 2);
        int kb = (c16 & 3) * 8;
        int off = p * 128 + c16 * 16;
        uint32_t dst = sbuf + (off ^ ((off >> 3) & 0x70));
        size_t ga = (size_t)(bm + r) * K + c * 32 + kb;
        size_t gb = (size_t)(bn + r) * K + c * 32 + kb;
        CP16(dst,         Ah + ga);
        CP16(dst + 8192,  Al + ga);
        CP16(dst + 16384, B2 + gb);
    }
    CP_COMMIT();
}

__device__ __forceinline__ void g_chunk_h2(uint32_t sbuf, int wm, int wn, int g, int rl,
                                           float acc[2][8][4]) {
#pragma unroll
    for (int ks = 0; ks < 2; ks++) {
        uint32_t ah[2][4], al[2][4];
#pragma unroll
        for (int mb = 0; mb < 2; mb++) {
            int r = wm + mb * 16 + ((g & 1) << 3) + rl;
            int c16 = ((r & 1) << 2) + ks * 2 + (g >> 1);
            int off = (r >> 1) * 128 + c16 * 16;
            uint32_t sw = (uint32_t)(off ^ ((off >> 3) & 0x70));
            ldsm_x4(ah[mb][0], ah[mb][1], ah[mb][2], ah[mb][3], sbuf + sw);
            ldsm_x4(al[mb][0], al[mb][1], al[mb][2], al[mb][3], sbuf + 8192 + sw);
        }
        uint32_t bh[4][4];
#pragma unroll
        for (int np = 0; np < 4; np++) {
            int r = wn + np * 16 + ((g >> 1) << 3) + rl;
            int c16 = ((r & 1) << 2) + ks * 2 + (g & 1);
            int off = (r >> 1) * 128 + c16 * 16;
            uint32_t sw = (uint32_t)(off ^ ((off >> 3) & 0x70));
            ldsm_x4(bh[np][0], bh[np][1], bh[np][2], bh[np][3], sbuf + 16384 + sw);
        }
#pragma unroll
        for (int mb = 0; mb < 2; mb++)
#pragma unroll
            for (int j = 0; j < 8; j++) {
                MMAF16(acc[mb][j], ah[mb], &bh[j >> 1][(j & 1) * 2]);
                MMAF16(acc[mb][j], al[mb], &bh[j >> 1][(j & 1) * 2]);
            }
    }
}

// ---------------- fused QKV projection (single x single fp16) ----------------
__global__ void __launch_bounds__(256, 2) gemm_qkv() {
    extern __shared__ char smem[];
    const uint32_t sbase = smem_u32(smem);
    const int tid = threadIdx.x, wid = tid >> 5, lane = tid & 31;
    const int nt = blockIdx.x;
    const int bm = blockIdx.y * 128;
    const int wm = (wid & 3) * 32;
    const int wn = (wid >> 2) * 64;
    const int g = lane >> 3, rl = lane & 7;
    const int K = D_;
    const int nch = K >> 5;

    const __half* B2;
    __half* O2;
    int N, bn;
    if (nt < 16)      { B2 = g_wq2; O2 = g_q2; N = QKDIM;    bn = nt * 128; }
    else if (nt < 32) { B2 = g_wk2; O2 = g_k2; N = QKDIM;    bn = (nt - 16) * 128; }
    else              { B2 = g_wv2; O2 = g_v2; N = H_ * DH_; bn = (nt - 32) * 128; }

    float acc[2][8][4];
#pragma unroll
    for (int a = 0; a < 2; a++)
#pragma unroll
        for (int b = 0; b < 8; b++)
#pragma unroll
            for (int d = 0; d < 4; d++) acc[a][b][d] = 0.f;

    g_issue_h1(g_x2, B2, sbase, tid, bm, bn, K, 0);
    g_issue_h1(g_x2, B2, sbase + G1STAGE, tid, bm, bn, K, 1);
    for (int c = 0; c < nch; c++) {
        if (c + 1 < nch) { CP_WAIT1(); } else { CP_WAIT0(); }
        __syncthreads();
        if (c + 2 < nch)
            g_issue_h1(g_x2, B2, sbase + (uint32_t)((c + 2) % 3) * G1STAGE, tid, bm, bn, K, c + 2);
        g_chunk_h1(sbase + (uint32_t)(c % 3) * G1STAGE, wm, wn, g, rl, acc);
    }

#pragma unroll
    for (int mb = 0; mb < 2; mb++) {
        int row0 = bm + wm + mb * 16 + (lane >> 2);
#pragma unroll
        for (int j = 0; j < 8; j++) {
            int col = bn + wn + j * 8 + (lane & 3) * 2;
#pragma unroll
            for (int rr = 0; rr < 2; rr++) {
                __half2 p = __floats2half2_rn(acc[mb][j][rr * 2], acc[mb][j][rr * 2 + 1]);
                *(__half2*)&O2[(size_t)(row0 + rr * 8) * N + col] = p;
            }
        }
    }
}

// ---------------- output projection (fp16 x2, fp32 out) ----------------------
__global__ void __launch_bounds__(256, 2) gemm_o2(float* __restrict__ Cf) {
    extern __shared__ char smem[];
    const uint32_t sbase = smem_u32(smem);
    const int tid = threadIdx.x, wid = tid >> 5, lane = tid & 31;
    const int bm = blockIdx.y * 128, bn = blockIdx.x * 128;
    const int wm = (wid & 3) * 32;
    const int wn = (wid >> 2) * 64;
    const int g = lane >> 3, rl = lane & 7;
    const int K = H_ * DH_, N = D_;
    const int nch = K >> 5;

    float acc[2][8][4];
#pragma unroll
    for (int a = 0; a < 2; a++)
#pragma unroll
        for (int b = 0; b < 8; b++)
#pragma unroll
            for (int d = 0; d < 4; d++) acc[a][b][d] = 0.f;

    g_issue_h2(g_nh2, g_nl2, g_wo2, sbase, tid, bm, bn, K, 0);
    g_issue_h2(g_nh2, g_nl2, g_wo2, sbase + GSTAGE, tid, bm, bn, K, 1);
    for (int c = 0; c < nch; c++) {
        if (c + 1 < nch) { CP_WAIT1(); } else { CP_WAIT0(); }
        __syncthreads();
        if (c + 2 < nch)
            g_issue_h2(g_nh2, g_nl2, g_wo2, sbase + (uint32_t)((c + 2) % 3) * GSTAGE, tid, bm, bn, K, c + 2);
        g_chunk_h2(sbase + (uint32_t)(c % 3) * GSTAGE, wm, wn, g, rl, acc);
    }

#pragma unroll
    for (int mb = 0; mb < 2; mb++) {
        int row0 = bm + wm + mb * 16 + (lane >> 2);
#pragma unroll
        for (int j = 0; j < 8; j++) {
            int col = bn + wn + j * 8 + (lane & 3) * 2;
            *(float2*)&Cf[(size_t)row0 * N + col]       = make_float2(acc[mb][j][0], acc[mb][j][1]);
            *(float2*)&Cf[(size_t)(row0 + 8) * N + col] = make_float2(acc[mb][j][2], acc[mb][j][3]);
        }
    }
}

// ---------------- flash attention --------------------------------------------
// 4 warps, 64-q tiles. QK single x single fp16; PV single x single fp16.
#define FK2  0
#define FV2  8192
#define FAM  16384
#define FSTG_SZ 16640
#define FQ2 (2 * FSTG_SZ)
#define FL_SMEM (3 * FSTG_SZ)   // 49920 (Q 8KB overlays stage 2)

__device__ __forceinline__ void f_issue_stage(uint32_t stg, int tid, int b, int h, int comp,
                                              int kt, const float* __restrict__ amask) {
    const char* Kg = (const char*)(g_k2 + ((size_t)(b * S_) + kt * 64) * QKDIM + h * 128 + comp * 64);
    const char* Vg = (const char*)(g_v2 + ((size_t)(b * S_) + kt * 64) * (H_ * DH_) + h * 64);
#pragma unroll
    for (int i = 0; i < 4; i++) {
        int t = tid + i * 128;
        int row = t >> 3, gr = t & 7;
        int off = row * 128 + gr * 16;
        uint32_t sw = (uint32_t)(off ^ ((off >> 3) & 0x70));
        CP16(stg + FK2 + sw, Kg + (size_t)row * (QKDIM * 2) + gr * 16);
        CP16(stg + FV2 + sw, Vg + (size_t)row * (H_ * DH_ * 2) + gr * 16);
    }
    if (tid < 16)
        CP16(stg + FAM + tid * 16, amask + b * S_ + kt * 64 + tid * 4);
    CP_COMMIT();
}

__global__ void __launch_bounds__(128) flashmma_kernel(const float* __restrict__ amask) {
    extern __shared__ char fsm[];
    const uint32_t sb = smem_u32(fsm);
    const int tid = threadIdx.x, wid = tid >> 5, lane = tid & 31;
    const int g = lane >> 3, rl = lane & 7;
    const int qt = (gridDim.x - 1) - blockIdx.x;
    const int z = blockIdx.y;
    const int comp = z & 1;
    const int bh = z >> 1;
    const int b = bh / H_, h = bh % H_;
    const float slope2 = exp2f(-8.0f * (float)(h + 1) / (float)H_) * LOG2E;
    const float scale2 = 0.125f * LOG2E;
    const int nkt = qt + 1;

    {
        const char* Qg = (const char*)(g_q2 + ((size_t)(b * S_) + qt * 64) * QKDIM + h * 128 + comp * 64);
#pragma unroll
        for (int i = 0; i < 4; i++) {
            int t = tid + i * 128;
            int row = t >> 3, gr = t & 7;
            int off = row * 128 + gr * 16;
            uint32_t sw = (uint32_t)(off ^ ((off >> 3) & 0x70));
            CP16(sb + FQ2 + sw, Qg + (size_t)row * (QKDIM * 2) + gr * 16);
        }
    }
    f_issue_stage(sb, tid, b, h, comp, qt, amask);
    if (nkt > 1) f_issue_stage(sb + FSTG_SZ, tid, b, h, comp, qt - 1, amask);

    float oa[8][4];
#pragma unroll
    for (int j = 0; j < 8; j++)
#pragma unroll
        for (int d = 0; d < 4; d++) oa[j][d] = 0.f;
    float m0 = -1e30f, m1 = -1e30f, l0 = 0.f, l1 = 0.f;
    uint32_t qA[4][4];

    const int qr0 = qt * 64 + wid * 16 + (lane >> 2);
    const float d8 = -8.0f * slope2;

    float cst0[8], cst1[8];
#pragma unroll
    for (int nb = 0; nb < 8; nb++) {
        cst0[nb] = slope2 * (float)(nb * 8 + (lane & 3) * 2);
        cst1[nb] = cst0[nb] + slope2;
    }
    float base0 = -slope2 * (float)(wid * 16 + (lane >> 2));
    const float base_step = 64.0f * slope2;

    for (int it = 0; it < nkt; it++) {
        const int ktile = qt - it;
        if (it + 1 < nkt) { CP_WAIT1(); } else { CP_WAIT0(); }
        __syncthreads();
        if (it == 0) {
#pragma unroll
            for (int kb = 0; kb < 4; kb++) {
                int row = wid * 16 + ((g & 1) << 3) + rl;
                int gr = kb * 2 + (g >> 1);
                int off = row * 128 + gr * 16;
                uint32_t sw = (uint32_t)(off ^ ((off >> 3) & 0x70));
                ldsm_x4(qA[kb][0], qA[kb][1], qA[kb][2], qA[kb][3], sb + FQ2 + sw);
            }
            if (nkt > 2) __syncthreads();
        }
        if (it + 2 < nkt)
            f_issue_stage(sb + (uint32_t)((it + 2) % 3) * FSTG_SZ, tid, b, h, comp, qt - (it + 2), amask);
        uint32_t stg = sb + (uint32_t)(it % 3) * FSTG_SZ;

        // ---- S = Q K^T (single x single) ----
        float sa[8][4];
#pragma unroll
        for (int j = 0; j < 8; j++)
#pragma unroll
            for (int d = 0; d < 4; d++) sa[j][d] = 0.f;
#pragma unroll
        for (int kb = 0; kb < 4; kb++) {
#pragma unroll
            for (int nb2 = 0; nb2 < 4; nb2++) {
                uint32_t kh4[4];
                int row = nb2 * 16 + ((g >> 1) << 3) + rl;
                int gr = kb * 2 + (g & 1);
                int off = row * 128 + gr * 16;
                uint32_t sw = (uint32_t)(off ^ ((off >> 3) & 0x70));
                ldsm_x4(kh4[0], kh4[1], kh4[2], kh4[3], stg + FK2 + sw);
                MMAF16(sa[nb2 * 2], qA[kb], &kh4[0]);
                MMAF16(sa[nb2 * 2 + 1], qA[kb], &kh4[2]);
            }
        }

        // ---- bias + masks (base-2 domain) ----
        const float* ams = (const float*)(fsm + (stg - sb) + FAM);
        float colc[8][2];
#pragma unroll
        for (int nb = 0; nb < 8; nb++) {
            int kc = nb * 8 + (lane & 3) * 2;
            colc[nb][0] = fmaf(1.0f - ams[kc],     NEGV2, base0 + cst0[nb]);
            colc[nb][1] = fmaf(1.0f - ams[kc + 1], NEGV2, base0 + cst1[nb]);
        }
#pragma unroll
        for (int nb = 0; nb < 8; nb++) {
            sa[nb][0] = fmaf(sa[nb][0], scale2, colc[nb][0]);
            sa[nb][1] = fmaf(sa[nb][1], scale2, colc[nb][1]);
            sa[nb][2] = fmaf(sa[nb][2], scale2, colc[nb][0] + d8);
            sa[nb][3] = fmaf(sa[nb][3], scale2, colc[nb][1] + d8);
        }
        if (it == 0) {
            const int kcb = ktile * 64;
#pragma unroll
            for (int nb = 0; nb < 8; nb++) {
                int k0 = kcb + nb * 8 + (lane & 3) * 2;
                if (k0 > qr0)         sa[nb][0] += NEGV2;
                if (k0 + 1 > qr0)     sa[nb][1] += NEGV2;
                if (k0 > qr0 + 8)     sa[nb][2] += NEGV2;
                if (k0 + 1 > qr0 + 8) sa[nb][3] += NEGV2;
            }
        }
        base0 -= base_step;

        // ---- online softmax (base 2; l lane-local) ----
        float mx0 = -1e30f, mx1 = -1e30f;
#pragma unroll
        for (int nb = 0; nb < 8; nb++) {
            mx0 = fmaxf(mx0, fmaxf(sa[nb][0], sa[nb][1]));
            mx1 = fmaxf(mx1, fmaxf(sa[nb][2], sa[nb][3]));
        }
        mx0 = fmaxf(mx0, __shfl_xor_sync(0xffffffffu, mx0, 1));
        mx0 = fmaxf(mx0, __shfl_xor_sync(0xffffffffu, mx0, 2));
        mx1 = fmaxf(mx1, __shfl_xor_sync(0xffffffffu, mx1, 1));
        mx1 = fmaxf(mx1, __shfl_xor_sync(0xffffffffu, mx1, 2));
        float mn0 = fmaxf(m0, mx0), mn1 = fmaxf(m1, mx1);
        float al0 = fast_exp2(m0 - mn0), al1 = fast_exp2(m1 - mn1);
        m0 = mn0; m1 = mn1;
        float ls0 = 0.f, ls1 = 0.f;
#pragma unroll
        for (int nb = 0; nb < 8; nb++) {
            sa[nb][0] = fast_exp2(sa[nb][0] - mn0);
            sa[nb][1] = fast_exp2(sa[nb][1] - mn0);
            sa[nb][2] = fast_exp2(sa[nb][2] - mn1);
            sa[nb][3] = fast_exp2(sa[nb][3] - mn1);
            ls0 += sa[nb][0] + sa[nb][1];
            ls1 += sa[nb][2] + sa[nb][3];
        }
        l0 = l0 * al0 + ls0;
        l1 = l1 * al1 + ls1;

        bool noresc = __all_sync(0xffffffffu, (al0 == 1.0f) && (al1 == 1.0f));
        if (!noresc) {
#pragma unroll
            for (int j = 0; j < 8; j++) {
                oa[j][0] *= al0; oa[j][1] *= al0;
                oa[j][2] *= al1; oa[j][3] *= al1;
            }
        }

        // ---- O += P V (single x single) ----
#pragma unroll
        for (int kb2 = 0; kb2 < 4; kb2++) {
            uint32_t pA[4];
            pA[0] = pack_h2(sa[kb2 * 2][0], sa[kb2 * 2][1]);
            pA[1] = pack_h2(sa[kb2 * 2][2], sa[kb2 * 2][3]);
            pA[2] = pack_h2(sa[kb2 * 2 + 1][0], sa[kb2 * 2 + 1][1]);
            pA[3] = pack_h2(sa[kb2 * 2 + 1][2], sa[kb2 * 2 + 1][3]);
#pragma unroll
            for (int db = 0; db < 4; db++) {
                uint32_t vh4[4];
                int row = kb2 * 16 + ((g & 1) << 3) + rl;
                int gr = db * 2 + (g >> 1);
                int off = row * 128 + gr * 16;
                uint32_t sw = (uint32_t)(off ^ ((off >> 3) & 0x70));
                ldsm_x4t(vh4[0], vh4[1], vh4[2], vh4[3], stg + FV2 + sw);
                MMAF16(oa[db * 2], pA, &vh4[0]);
                MMAF16(oa[db * 2 + 1], pA, &vh4[2]);
            }
        }
    }

    l0 += __shfl_xor_sync(0xffffffffu, l0, 1);
    l0 += __shfl_xor_sync(0xffffffffu, l0, 2);
    l1 += __shfl_xor_sync(0xffffffffu, l1, 1);
    l1 += __shfl_xor_sync(0xffffffffu, l1, 2);
    float inv0 = 1.0f / l0, inv1 = 1.0f / l1;
    float* Og = (comp ? g_o2 : g_o1) + ((size_t)(b * S_) + qr0) * (H_ * DH_) + h * 64;
#pragma unroll
    for (int j = 0; j < 8; j++) {
        int col = j * 8 + (lane & 3) * 2;
        *(float2*)&Og[col] = make_float2(oa[j][0] * inv0, oa[j][1] * inv0);
        *(float2*)&Og[(size_t)8 * (H_ * DH_) + col] = make_float2(oa[j][2] * inv1, oa[j][3] * inv1);
    }
}

// ---------------- combine + groupnorm stats ---------------------------------
__global__ void __launch_bounds__(256) combine_stats_kernel() {
    const int bh = blockIdx.x >> 3;
    const int slice = blockIdx.x & 7;
    const int b = bh / H_, h = bh % H_;
    const float lam = g_lambda;
    double s = 0.0, ss = 0.0;
    const int base_row = b * S_ + slice * 256;
    for (int f = threadIdx.x; f < 256 * (DH_ / 4); f += 256) {
        int row = f >> 4, c = (f & 15) * 4;
        size_t e = (size_t)(base_row + row) * (H_ * DH_) + h * DH_ + c;
        float4 a = *(const float4*)&g_o1[e];
        float4 cc = *(const float4*)&g_o2[e];
        float4 y;
        y.x = a.x - lam * cc.x; y.y = a.y - lam * cc.y;
        y.z = a.z - lam * cc.z; y.w = a.w - lam * cc.w;
        *(float4*)&g_o[e] = y;
        s += (double)y.x + y.y + y.z + y.w;
        ss += (double)y.x * y.x + (double)y.y * y.y + (double)y.z * y.z + (double)y.w * y.w;
    }
    __shared__ double sh_s[256], sh_ss[256];
    sh_s[threadIdx.x] = s; sh_ss[threadIdx.x] = ss;
    __syncthreads();
    for (int st = 128; st > 0; st >>= 1) {
        if (threadIdx.x < st) {
            sh_s[threadIdx.x] += sh_s[threadIdx.x + st];
            sh_ss[threadIdx.x] += sh_ss[threadIdx.x + st];
        }
        __syncthreads();
    }
    if (threadIdx.x == 0) {
        atomicAdd(&g_sum[bh], sh_s[0]);
        atomicAdd(&g_sumsq[bh], sh_ss[0]);
    }
}

// ---------------- normalize + emit fp16 hi/lo --------------------------------
__global__ void __launch_bounds__(256) gn_apply_kernel(const float* __restrict__ gamma,
                                                       const float* __restrict__ beta) {
    int f = blockIdx.x * blockDim.x + threadIdx.x;
    if (f >= (B_ * S_ * H_ * DH_) / 4) return;
    int e = f * 4;
    int c = e % (H_ * DH_);
    int row = e / (H_ * DH_);
    int b = row / S_;
    int h = c / DH_;
    const double n = (double)S_ * DH_;
    double sm = g_sum[b * H_ + h], sq = g_sumsq[b * H_ + h];
    double meand = sm / n;
    float mean = (float)meand;
    float inv = rsqrtf((float)(sq / n - meand * meand) + EPS_);
    float4 x = *(const float4*)&g_o[e];
    float4 gm = *(const float4*)&gamma[c];
    float4 bt = *(const float4*)&beta[c];
    const float post = 1.0f - LAMBDA_INIT;
    float y[4];
    y[0] = ((x.x - mean) * inv * gm.x + bt.x) * post;
    y[1] = ((x.y - mean) * inv * gm.y + bt.y) * post;
    y[2] = ((x.z - mean) * inv * gm.z + bt.z) * post;
    y[3] = ((x.w - mean) * inv * gm.w + bt.w) * post;
    __half hh[4], ll[4];
#pragma unroll
    for (int j = 0; j < 4; j++) {
        hh[j] = __float2half_rn(y[j]);
        ll[j] = __float2half_rn(y[j] - __half2float(hh[j]));
    }
    *(uint2*)&g_nh2[e] = *(uint2*)hh;
    *(uint2*)&g_nl2[e] = *(uint2*)ll;
}

// ---------------- launch ----------------------------------------------------
extern "C" void kernel_launch(void* const* d_in, const int* in_sizes, int n_in,
                              void* d_out, int out_size) {
    const float* x     = (const float*)d_in[0];
    const float* amask = (const float*)d_in[1];
    const float* Wq = (const float*)d_in[3];
    const float* Wk = (const float*)d_in[4];
    const float* Wv = (const float*)d_in[5];
    const float* Wo = (const float*)d_in[6];
    const float* lq1 = (const float*)d_in[7];
    const float* lq2 = (const float*)d_in[8];
    const float* lk1 = (const float*)d_in[9];
    const float* lk2 = (const float*)d_in[10];
    const float* gam = (const float*)d_in[11];
    const float* bet = (const float*)d_in[12];
    float* out = (float*)d_out;

    const int M = B_ * S_;  // 4096

    // 0: lambda + zero stats
    lam_kernel<<<1, 1>>>(lq1, lq2, lk1, lk2);
    // 1: all conversions (single fp16 x, weights)
    cvt_all<<<(N4_TOT + 255) / 256, 256>>>(x, Wq, Wk, Wv, Wo);
    // 2: fused QKV projection (single x single)
    cudaFuncSetAttribute(gemm_qkv, cudaFuncAttributeMaxDynamicSharedMemorySize, G1_SMEM);
    gemm_qkv<<<dim3(40, M / 128), 256, G1_SMEM>>>();
    // 3: flash attention (profiled)
    cudaFuncSetAttribute(flashmma_kernel, cudaFuncAttributeMaxDynamicSharedMemorySize, FL_SMEM);
    flashmma_kernel<<<dim3(S_ / 64, B_ * H_ * 2), 128, FL_SMEM>>>(amask);
    // 4: combine + stats
    combine_stats_kernel<<<B_ * H_ * 8, 256>>>();
    // 5: normalize + fp16 split
    gn_apply_kernel<<<(B_ * S_ * H_ * DH_ / 4 + 255) / 256, 256>>>(gam, bet);
    // 6: output projection
    cudaFuncSetAttribute(gemm_o2, cudaFuncAttributeMaxDynamicSharedMemorySize, G_SMEM);
    gemm_o2<<<dim3(D_ / 128, M / 128), 256, G_SMEM>>>(out);
}